// round 2
// baseline (speedup 1.0000x reference)
#include <cuda_runtime.h>
#include <math.h>

#define NN 100000
#define EE 1600000
#define DIN 24
#define HH 128
#define DOUT 12
#define HEADS 4
#define DH 32
#define GAT_CAP 512

// ----------------------------------------------------------------------------
// Scratch (device globals; no dynamic allocation allowed)
// ----------------------------------------------------------------------------
__device__ float g_h1[NN * HH];    // h1 = x@W1 ; later h3 = x2@W3
__device__ float g_agg[NN * HH];   // aggregation outputs (a1raw / x2raw / a3raw)
__device__ float g_x1[NN * HH];    // x1
__device__ float g_xin[NN * HH];   // x_in_proj ; later x3
__device__ float g_hg[NN * HH];    // hg ; later x2
__device__ float g_h4[NN * DOUT];
__device__ float g_t[NN * 64];
__device__ float g_as[NN * HEADS];
__device__ float g_ad[NN * HEADS];
__device__ float g_deg[NN];
__device__ float g_dinv[NN];
__device__ int   g_cnt[NN];
__device__ int   g_cur[NN];
__device__ int   g_rowptr[NN + 1];
__device__ int   g_colsrc[EE];
__device__ float g_colw[EE];
__device__ float g_bnsum[6 * 128];   // 3 layers x (sum[128], sumsq[128])
__device__ float g_bnscale[128];
__device__ float g_bnshift[128];

__device__ __forceinline__ float lrelu(float v) { return v > 0.f ? v : 0.2f * v; }

// ----------------------------------------------------------------------------
// Graph preprocessing
// ----------------------------------------------------------------------------
__global__ void __launch_bounds__(256) init_kernel() {
    int i = blockIdx.x * blockDim.x + threadIdx.x;
    if (i < NN) { g_deg[i] = 1.0f; g_cnt[i] = 0; g_cur[i] = 0; }   // self-loop weight 1
    if (i < 6 * 128) g_bnsum[i] = 0.f;
}

__global__ void __launch_bounds__(256) count_kernel(const int* __restrict__ dst,
                                                    const float* __restrict__ w) {
    int e = blockIdx.x * blockDim.x + threadIdx.x;
    if (e < EE) {
        int d = dst[e];
        atomicAdd(&g_deg[d], w[e]);
        atomicAdd(&g_cnt[d], 1);
    }
}

__global__ void __launch_bounds__(256) dinv_kernel() {
    int i = blockIdx.x * blockDim.x + threadIdx.x;
    if (i < NN) g_dinv[i] = rsqrtf(g_deg[i]);   // deg >= 1 always (self loop)
}

// Single-block exclusive scan of g_cnt -> g_rowptr
__global__ void __launch_bounds__(1024) scan_kernel() {
    __shared__ int sp[1024];
    const int tid = threadIdx.x;
    const int CH = (NN + 1023) / 1024;   // 98
    int base = tid * CH;
    int s = 0;
    for (int i = 0; i < CH; i++) { int idx = base + i; if (idx < NN) s += g_cnt[idx]; }
    sp[tid] = s;
    __syncthreads();
    for (int off = 1; off < 1024; off <<= 1) {
        int add = (tid >= off) ? sp[tid - off] : 0;
        __syncthreads();
        sp[tid] += add;
        __syncthreads();
    }
    int run = (tid == 0) ? 0 : sp[tid - 1];
    for (int i = 0; i < CH; i++) {
        int idx = base + i;
        if (idx < NN) { g_rowptr[idx] = run; run += g_cnt[idx]; }
    }
    if (tid == 1023) g_rowptr[NN] = sp[1023];
}

__global__ void __launch_bounds__(256) fill_kernel(const int* __restrict__ src,
                                                   const int* __restrict__ dst,
                                                   const float* __restrict__ w) {
    int e = blockIdx.x * blockDim.x + threadIdx.x;
    if (e < EE) {
        int d = dst[e];
        int pos = g_rowptr[d] + atomicAdd(&g_cur[d], 1);
        g_colsrc[pos] = src[e];
        g_colw[pos] = w[e];
    }
}

// ----------------------------------------------------------------------------
// GEMMs
// ----------------------------------------------------------------------------
// x(N x 24) @ W1 -> h1 ;  x @ Wi + bi -> xin   (fused, 16 rows/block)
__global__ void __launch_bounds__(128) gemm_in_kernel(
        const float* __restrict__ X, const float* __restrict__ W1,
        const float* __restrict__ Wi, const float* __restrict__ bi,
        float* __restrict__ h1, float* __restrict__ xin) {
    const int tid = threadIdx.x;
    const int cg = tid & 31;        // 32 col groups of 4
    const int rg = tid >> 5;        // 4 row groups of 4
    const int n0 = blockIdx.x * 16 + rg * 4;
    float a1[4][4] = {}; float ai[4][4] = {};
    const float4* W1v = (const float4*)W1;
    const float4* Wiv = (const float4*)Wi;
#pragma unroll
    for (int k = 0; k < DIN; k++) {
        float4 w1 = __ldg(&W1v[k * 32 + cg]);
        float4 wi = __ldg(&Wiv[k * 32 + cg]);
#pragma unroll
        for (int r = 0; r < 4; r++) {
            float xv = __ldg(&X[(n0 + r) * DIN + k]);
            a1[r][0] += xv * w1.x; a1[r][1] += xv * w1.y; a1[r][2] += xv * w1.z; a1[r][3] += xv * w1.w;
            ai[r][0] += xv * wi.x; ai[r][1] += xv * wi.y; ai[r][2] += xv * wi.z; ai[r][3] += xv * wi.w;
        }
    }
    const int c0 = cg * 4;
    float4 bv = __ldg(&((const float4*)bi)[cg]);
#pragma unroll
    for (int r = 0; r < 4; r++) {
        float4 v1, vi;
        v1.x = a1[r][0]; v1.y = a1[r][1]; v1.z = a1[r][2]; v1.w = a1[r][3];
        vi.x = ai[r][0] + bv.x; vi.y = ai[r][1] + bv.y; vi.z = ai[r][2] + bv.z; vi.w = ai[r][3] + bv.w;
        *(float4*)&h1[(n0 + r) * HH + c0] = v1;
        *(float4*)&xin[(n0 + r) * HH + c0] = vi;
    }
}

// Generic N x COLS = X(N x 128) @ W(128 x COLS), register-tiled 4x4
template<int COLS, bool RELU, bool BIAS>
__global__ void __launch_bounds__(128) gemm_k128(
        const float* __restrict__ X, const float* __restrict__ W,
        const float* __restrict__ bias, float* __restrict__ out) {
    constexpr int CG = COLS / 4;
    constexpr int RG = 128 / CG;
    const int tid = threadIdx.x;
    const int cg = tid % CG;
    const int rg = tid / CG;
    const int n0 = blockIdx.x * (RG * 4) + rg * 4;
    float acc[4][4] = {};
    const float4* Wv = (const float4*)W;
    const float4* Xv = (const float4*)X;
#pragma unroll 2
    for (int k8 = 0; k8 < 128; k8 += 8) {
        float xr[4][8];
#pragma unroll
        for (int r = 0; r < 4; r++) {
            float4 a = __ldg(&Xv[((n0 + r) * 128 + k8) >> 2]);
            float4 b = __ldg(&Xv[((n0 + r) * 128 + k8 + 4) >> 2]);
            xr[r][0] = a.x; xr[r][1] = a.y; xr[r][2] = a.z; xr[r][3] = a.w;
            xr[r][4] = b.x; xr[r][5] = b.y; xr[r][6] = b.z; xr[r][7] = b.w;
        }
#pragma unroll
        for (int kk = 0; kk < 8; kk++) {
            float4 w = __ldg(&Wv[(k8 + kk) * CG + cg]);
#pragma unroll
            for (int r = 0; r < 4; r++) {
                acc[r][0] += xr[r][kk] * w.x;
                acc[r][1] += xr[r][kk] * w.y;
                acc[r][2] += xr[r][kk] * w.z;
                acc[r][3] += xr[r][kk] * w.w;
            }
        }
    }
    const int c0 = cg * 4;
    float4 bv = make_float4(0.f, 0.f, 0.f, 0.f);
    if (BIAS) bv = __ldg(&((const float4*)bias)[cg]);
#pragma unroll
    for (int r = 0; r < 4; r++) {
        float4 v;
        v.x = acc[r][0] + bv.x; v.y = acc[r][1] + bv.y;
        v.z = acc[r][2] + bv.z; v.w = acc[r][3] + bv.w;
        if (RELU) { v.x = fmaxf(v.x, 0.f); v.y = fmaxf(v.y, 0.f); v.z = fmaxf(v.z, 0.f); v.w = fmaxf(v.w, 0.f); }
        *(float4*)&out[(n0 + r) * COLS + c0] = v;
    }
}

// x3(N x 128) @ W4(128 x 12) -> h4 (no bias; bias applied post-aggregation)
__global__ void __launch_bounds__(128) gemm_w4_kernel(
        const float* __restrict__ X, const float* __restrict__ W,
        float* __restrict__ out) {
    const int tid = threadIdx.x;       // 128
    const int r = tid >> 4;            // 8 rows / block
    const int c = tid & 15;
    const int n = blockIdx.x * 8 + r;
    if (c < DOUT) {
        float acc = 0.f;
#pragma unroll 8
        for (int k = 0; k < 128; k++)
            acc += __ldg(&X[n * 128 + k]) * __ldg(&W[k * DOUT + c]);
        out[n * DOUT + c] = acc;
    }
}

// ----------------------------------------------------------------------------
// BN
// ----------------------------------------------------------------------------
__global__ void __launch_bounds__(128) bn_stats(const float* __restrict__ in,
                                                float* __restrict__ sums) {
    const int c = threadIdx.x;   // 128
    float s = 0.f, s2 = 0.f;
    for (int n = blockIdx.x; n < NN; n += gridDim.x) {
        float v = in[n * HH + c];
        s += v; s2 += v * v;
    }
    atomicAdd(&sums[c], s);
    atomicAdd(&sums[c + 128], s2);
}

__global__ void __launch_bounds__(128) bn_final(const float* __restrict__ sums,
                                                const float* __restrict__ g,
                                                const float* __restrict__ be) {
    const int c = threadIdx.x;
    float mean = sums[c] * (1.0f / NN);
    float var = sums[c + 128] * (1.0f / NN) - mean * mean;
    var = fmaxf(var, 0.f);
    float rstd = rsqrtf(var + 1e-5f);
    float sc = rstd * g[c];
    g_bnscale[c] = sc;
    g_bnshift[c] = be[c] - mean * sc;
}

// out = relu(in*scale + shift) [+ add]
__global__ void __launch_bounds__(256) apply_bn_relu(const float* __restrict__ in,
                                                     const float* __restrict__ add,
                                                     float* __restrict__ out) {
    int idx = blockIdx.x * blockDim.x + threadIdx.x;
    if (idx < NN * HH) {
        int c = idx & 127;
        float v = in[idx] * g_bnscale[c] + g_bnshift[c];
        v = fmaxf(v, 0.f);
        if (add) v += add[idx];
        out[idx] = v;
    }
}

// ----------------------------------------------------------------------------
// GCN aggregation (CSR, one node per 128-thread block)
// ----------------------------------------------------------------------------
__global__ void __launch_bounds__(128) gcn_agg128(const float* __restrict__ in,
                                                  const float* __restrict__ bias,
                                                  float* __restrict__ out) {
    const int n = blockIdx.x;
    const int c = threadIdx.x;
    const float dn = g_dinv[n];
    const int s0 = g_rowptr[n], s1 = g_rowptr[n + 1];
    float acc = in[n * HH + c] * dn * dn;   // self loop (w=1)
    int j = s0;
    for (; j + 4 <= s1; j += 4) {
        int sA = __ldg(&g_colsrc[j + 0]), sB = __ldg(&g_colsrc[j + 1]);
        int sC = __ldg(&g_colsrc[j + 2]), sD = __ldg(&g_colsrc[j + 3]);
        float cA = __ldg(&g_colw[j + 0]) * __ldg(&g_dinv[sA]) * dn;
        float cB = __ldg(&g_colw[j + 1]) * __ldg(&g_dinv[sB]) * dn;
        float cC = __ldg(&g_colw[j + 2]) * __ldg(&g_dinv[sC]) * dn;
        float cD = __ldg(&g_colw[j + 3]) * __ldg(&g_dinv[sD]) * dn;
        float vA = __ldg(&in[sA * HH + c]);
        float vB = __ldg(&in[sB * HH + c]);
        float vC = __ldg(&in[sC * HH + c]);
        float vD = __ldg(&in[sD * HH + c]);
        acc += cA * vA + cB * vB + cC * vC + cD * vD;
    }
    for (; j < s1; j++) {
        int s = __ldg(&g_colsrc[j]);
        acc += __ldg(&g_colw[j]) * __ldg(&g_dinv[s]) * dn * __ldg(&in[s * HH + c]);
    }
    out[n * HH + c] = acc + bias[c];
}

__global__ void __launch_bounds__(128) gcn_agg12(const float* __restrict__ in,
                                                 const float* __restrict__ bias,
                                                 float* __restrict__ out) {
    const int warp = threadIdx.x >> 5;
    const int lane = threadIdx.x & 31;
    const int n = blockIdx.x * 4 + warp;
    const float dn = g_dinv[n];
    const int s0 = g_rowptr[n], s1 = g_rowptr[n + 1];
    float acc = (lane < DOUT) ? in[n * DOUT + lane] * dn * dn : 0.f;
    int j = s0;
    for (; j + 2 <= s1; j += 2) {
        int sA = __ldg(&g_colsrc[j]), sB = __ldg(&g_colsrc[j + 1]);
        float cA = __ldg(&g_colw[j]) * __ldg(&g_dinv[sA]) * dn;
        float cB = __ldg(&g_colw[j + 1]) * __ldg(&g_dinv[sB]) * dn;
        float vA = (lane < DOUT) ? __ldg(&in[sA * DOUT + lane]) : 0.f;
        float vB = (lane < DOUT) ? __ldg(&in[sB * DOUT + lane]) : 0.f;
        acc += cA * vA + cB * vB;
    }
    for (; j < s1; j++) {
        int s = __ldg(&g_colsrc[j]);
        float coef = __ldg(&g_colw[j]) * __ldg(&g_dinv[s]) * dn;
        if (lane < DOUT) acc += coef * __ldg(&in[s * DOUT + lane]);
    }
    if (lane < DOUT) out[n * DOUT + lane] = acc + bias[lane];
}

// ----------------------------------------------------------------------------
// GAT
// ----------------------------------------------------------------------------
__global__ void __launch_bounds__(256) att_reduce(const float* __restrict__ hg,
                                                  const float* __restrict__ att_s,
                                                  const float* __restrict__ att_d) {
    const int tid = threadIdx.x;   // 256 -> 2 nodes/block
    const int n = blockIdx.x * 2 + (tid >> 7);
    const int c = tid & 127;
    float v = hg[n * HH + c];
    float ps = v * __ldg(&att_s[c]);
    float pd = v * __ldg(&att_d[c]);
#pragma unroll
    for (int off = 16; off; off >>= 1) {
        ps += __shfl_xor_sync(0xffffffffu, ps, off);
        pd += __shfl_xor_sync(0xffffffffu, pd, off);
    }
    if ((tid & 31) == 0) {
        int h = c >> 5;
        g_as[n * 4 + h] = ps;
        g_ad[n * 4 + h] = pd;
    }
}

__global__ void __launch_bounds__(128) gat_agg_kernel(const float* __restrict__ hg,
                                                      const float* __restrict__ bg,
                                                      float* __restrict__ out) {
    const int n = blockIdx.x;
    const int tid = threadIdx.x;
    const int lane = tid & 31;
    __shared__ float sh_m[4], sh_inv[4], sh_aself[4], sh_ad4[4];
    __shared__ float sh_ex[GAT_CAP * 4];
    const int s0 = g_rowptr[n];
    const int s1 = g_rowptr[n + 1];
    const int deg = s1 - s0;
    const bool cached = (deg <= GAT_CAP);
    const float4* as4 = (const float4*)g_as;
    const float4* ad4 = (const float4*)g_ad;
    if (tid < 32) {
        float4 adv = __ldg(&ad4[n]);
        float4 asv = __ldg(&as4[n]);
        float es0 = lrelu(asv.x + adv.x), es1 = lrelu(asv.y + adv.y);
        float es2 = lrelu(asv.z + adv.z), es3 = lrelu(asv.w + adv.w);
        float m0 = es0, m1 = es1, m2 = es2, m3 = es3;
        for (int j = lane; j < deg; j += 32) {
            int s = __ldg(&g_colsrc[s0 + j]);
            float4 a = __ldg(&as4[s]);
            float e0 = lrelu(a.x + adv.x), e1 = lrelu(a.y + adv.y);
            float e2 = lrelu(a.z + adv.z), e3 = lrelu(a.w + adv.w);
            if (cached) {
                sh_ex[j * 4 + 0] = e0; sh_ex[j * 4 + 1] = e1;
                sh_ex[j * 4 + 2] = e2; sh_ex[j * 4 + 3] = e3;
            }
            m0 = fmaxf(m0, e0); m1 = fmaxf(m1, e1);
            m2 = fmaxf(m2, e2); m3 = fmaxf(m3, e3);
        }
#pragma unroll
        for (int off = 16; off; off >>= 1) {
            m0 = fmaxf(m0, __shfl_xor_sync(0xffffffffu, m0, off));
            m1 = fmaxf(m1, __shfl_xor_sync(0xffffffffu, m1, off));
            m2 = fmaxf(m2, __shfl_xor_sync(0xffffffffu, m2, off));
            m3 = fmaxf(m3, __shfl_xor_sync(0xffffffffu, m3, off));
        }
        float t0 = 0.f, t1 = 0.f, t2 = 0.f, t3 = 0.f;
        if (cached) {
            for (int j = lane; j < deg; j += 32) {
                float x0 = expf(sh_ex[j * 4 + 0] - m0); sh_ex[j * 4 + 0] = x0; t0 += x0;
                float x1 = expf(sh_ex[j * 4 + 1] - m1); sh_ex[j * 4 + 1] = x1; t1 += x1;
                float x2 = expf(sh_ex[j * 4 + 2] - m2); sh_ex[j * 4 + 2] = x2; t2 += x2;
                float x3 = expf(sh_ex[j * 4 + 3] - m3); sh_ex[j * 4 + 3] = x3; t3 += x3;
            }
        } else {
            for (int j = lane; j < deg; j += 32) {
                int s = __ldg(&g_colsrc[s0 + j]);
                float4 a = __ldg(&as4[s]);
                t0 += expf(lrelu(a.x + adv.x) - m0);
                t1 += expf(lrelu(a.y + adv.y) - m1);
                t2 += expf(lrelu(a.z + adv.z) - m2);
                t3 += expf(lrelu(a.w + adv.w) - m3);
            }
        }
#pragma unroll
        for (int off = 16; off; off >>= 1) {
            t0 += __shfl_xor_sync(0xffffffffu, t0, off);
            t1 += __shfl_xor_sync(0xffffffffu, t1, off);
            t2 += __shfl_xor_sync(0xffffffffu, t2, off);
            t3 += __shfl_xor_sync(0xffffffffu, t3, off);
        }
        if (lane == 0) {
            float x0 = expf(es0 - m0), x1 = expf(es1 - m1);
            float x2 = expf(es2 - m2), x3 = expf(es3 - m3);
            t0 += x0; t1 += x1; t2 += x2; t3 += x3;
            float i0 = 1.f / t0, i1 = 1.f / t1, i2 = 1.f / t2, i3 = 1.f / t3;
            sh_m[0] = m0; sh_m[1] = m1; sh_m[2] = m2; sh_m[3] = m3;
            sh_inv[0] = i0; sh_inv[1] = i1; sh_inv[2] = i2; sh_inv[3] = i3;
            sh_aself[0] = x0 * i0; sh_aself[1] = x1 * i1;
            sh_aself[2] = x2 * i2; sh_aself[3] = x3 * i3;
            sh_ad4[0] = adv.x; sh_ad4[1] = adv.y; sh_ad4[2] = adv.z; sh_ad4[3] = adv.w;
        }
    }
    __syncthreads();
    const int c = tid;
    const int h = c >> 5;
    const float inv = sh_inv[h];
    float acc_edges = 0.f;
    if (cached) {
        int j = 0;
        for (; j + 4 <= deg; j += 4) {
            int sA = __ldg(&g_colsrc[s0 + j + 0]);
            int sB = __ldg(&g_colsrc[s0 + j + 1]);
            int sC = __ldg(&g_colsrc[s0 + j + 2]);
            int sD = __ldg(&g_colsrc[s0 + j + 3]);
            float aA = sh_ex[(j + 0) * 4 + h];
            float aB = sh_ex[(j + 1) * 4 + h];
            float aC = sh_ex[(j + 2) * 4 + h];
            float aD = sh_ex[(j + 3) * 4 + h];
            float vA = __ldg(&hg[sA * HH + c]);
            float vB = __ldg(&hg[sB * HH + c]);
            float vC = __ldg(&hg[sC * HH + c]);
            float vD = __ldg(&hg[sD * HH + c]);
            acc_edges += aA * vA + aB * vB + aC * vC + aD * vD;
        }
        for (; j < deg; j++) {
            int s = __ldg(&g_colsrc[s0 + j]);
            acc_edges += sh_ex[j * 4 + h] * __ldg(&hg[s * HH + c]);
        }
    } else {
        const float m = sh_m[h];
        const float ad = sh_ad4[h];
        for (int j = 0; j < deg; j++) {
            int s = __ldg(&g_colsrc[s0 + j]);
            float e = lrelu(__ldg(&g_as[s * 4 + h]) + ad);
            acc_edges += expf(e - m) * __ldg(&hg[s * HH + c]);
        }
    }
    out[n * HH + c] = sh_aself[h] * __ldg(&hg[n * HH + c]) + inv * acc_edges + bg[c];
}

// ----------------------------------------------------------------------------
// Gate + final epilogue: out += 2.5 * flag * sigmoid(t@Gw2+Gb2) * sig
// ----------------------------------------------------------------------------
__global__ void __launch_bounds__(128) final_kernel(
        const float* __restrict__ t, const float* __restrict__ x,
        const float* __restrict__ Gw2, const float* __restrict__ Gb2,
        const float* __restrict__ Ws, const float* __restrict__ bs,
        float* __restrict__ out) {
    __shared__ float sG[64 * DOUT];
    __shared__ float sGb[DOUT], sWs[DOUT], sbs[DOUT];
    const int tid = threadIdx.x;   // 128
    for (int i = tid; i < 64 * DOUT; i += 128) sG[i] = Gw2[i];
    if (tid < DOUT) { sGb[tid] = Gb2[tid]; sWs[tid] = Ws[tid]; sbs[tid] = bs[tid]; }
    __syncthreads();
    if (tid < 120) {
        const int ni = tid / DOUT, c = tid % DOUT;
        const int n = blockIdx.x * 10 + ni;
        float z = sGb[c];
#pragma unroll 8
        for (int k = 0; k < 64; k++)
            z += __ldg(&t[n * 64 + k]) * sG[k * DOUT + c];
        float gate = 1.f / (1.f + expf(-z));
        float status = __ldg(&x[n * DIN + 12]);
        float flag = status < 0.5f ? 1.f : 0.f;
        float sig = (1.f - status) * sWs[c] + sbs[c];
        out[n * DOUT + c] += 2.5f * flag * gate * sig;
    }
}

// ----------------------------------------------------------------------------
// Launch
// ----------------------------------------------------------------------------
extern "C" void kernel_launch(void* const* d_in, const int* in_sizes, int n_in,
                              void* d_out, int out_size) {
    const float* x   = (const float*)d_in[0];
    const int*   ei  = (const int*)d_in[1];
    const float* ew  = (const float*)d_in[2];
    const float* W1  = (const float*)d_in[3];
    const float* b1  = (const float*)d_in[4];
    const float* g1  = (const float*)d_in[5];
    const float* be1 = (const float*)d_in[6];
    const float* Wg  = (const float*)d_in[7];
    const float* atts= (const float*)d_in[8];
    const float* attd= (const float*)d_in[9];
    const float* bg  = (const float*)d_in[10];
    const float* g2  = (const float*)d_in[11];
    const float* be2 = (const float*)d_in[12];
    const float* W3  = (const float*)d_in[13];
    const float* b3  = (const float*)d_in[14];
    const float* g3  = (const float*)d_in[15];
    const float* be3 = (const float*)d_in[16];
    const float* W4  = (const float*)d_in[17];
    const float* b4  = (const float*)d_in[18];
    const float* Wi  = (const float*)d_in[19];
    const float* bi  = (const float*)d_in[20];
    const float* Gw1 = (const float*)d_in[21];
    const float* Gb1 = (const float*)d_in[22];
    const float* Gw2 = (const float*)d_in[23];
    const float* Gb2 = (const float*)d_in[24];
    const float* Ws  = (const float*)d_in[25];
    const float* bs  = (const float*)d_in[26];
    float* out = (float*)d_out;
    const int* src = ei;
    const int* dst = ei + EE;

    float *p_h1, *p_agg, *p_x1, *p_xin, *p_hg, *p_h4, *p_t, *p_bnsum;
    cudaGetSymbolAddress((void**)&p_h1, g_h1);
    cudaGetSymbolAddress((void**)&p_agg, g_agg);
    cudaGetSymbolAddress((void**)&p_x1, g_x1);
    cudaGetSymbolAddress((void**)&p_xin, g_xin);
    cudaGetSymbolAddress((void**)&p_hg, g_hg);
    cudaGetSymbolAddress((void**)&p_h4, g_h4);
    cudaGetSymbolAddress((void**)&p_t, g_t);
    cudaGetSymbolAddress((void**)&p_bnsum, g_bnsum);

    // graph preprocessing
    init_kernel<<<(NN + 255) / 256, 256>>>();
    count_kernel<<<(EE + 255) / 256, 256>>>(dst, ew);
    dinv_kernel<<<(NN + 255) / 256, 256>>>();
    scan_kernel<<<1, 1024>>>();
    fill_kernel<<<(EE + 255) / 256, 256>>>(src, dst, ew);

    // layer 1: gcn + bn + relu
    gemm_in_kernel<<<NN / 16, 128>>>(x, W1, Wi, bi, p_h1, p_xin);
    gcn_agg128<<<NN, 128>>>(p_h1, b1, p_agg);
    bn_stats<<<1024, 128>>>(p_agg, p_bnsum + 0 * 256);
    bn_final<<<1, 128>>>(p_bnsum + 0 * 256, g1, be1);
    apply_bn_relu<<<(NN * HH + 255) / 256, 256>>>(p_agg, nullptr, p_x1);

    // GAT
    gemm_k128<128, false, false><<<NN / 16, 128>>>(p_x1, Wg, nullptr, p_hg);
    att_reduce<<<NN / 2, 256>>>(p_hg, atts, attd);
    gat_agg_kernel<<<NN, 128>>>(p_hg, bg, p_agg);
    bn_stats<<<1024, 128>>>(p_agg, p_bnsum + 1 * 256);
    bn_final<<<1, 128>>>(p_bnsum + 1 * 256, g2, be2);
    apply_bn_relu<<<(NN * HH + 255) / 256, 256>>>(p_agg, p_xin, p_hg);   // x2 -> g_hg

    // layer 3: gcn + bn + relu + x1
    gemm_k128<128, false, false><<<NN / 16, 128>>>(p_hg, W3, nullptr, p_h1);   // h3
    gcn_agg128<<<NN, 128>>>(p_h1, b3, p_agg);
    bn_stats<<<1024, 128>>>(p_agg, p_bnsum + 2 * 256);
    bn_final<<<1, 128>>>(p_bnsum + 2 * 256, g3, be3);
    apply_bn_relu<<<(NN * HH + 255) / 256, 256>>>(p_agg, p_x1, p_xin);   // x3 -> g_xin

    // output gcn + gate
    gemm_w4_kernel<<<NN / 8, 128>>>(p_xin, W4, p_h4);
    gemm_k128<64, true, true><<<NN / 32, 128>>>(p_xin, Gw1, Gb1, p_t);
    gcn_agg12<<<NN / 4, 128>>>(p_h4, b4, out);
    final_kernel<<<NN / 10, 128>>>(p_t, x, Gw2, Gb2, Ws, bs, out);
}

// round 3
// speedup vs baseline: 1.3241x; 1.3241x over previous
#include <cuda_runtime.h>
#include <math.h>

#define NN 100000
#define EE 1600000
#define DIN 24
#define HH 128
#define DOUT 12
#define HEADS 4
#define DH 32
#define GAT_CAP 512
#define NB 391   // ceil(NN/256)

// ----------------------------------------------------------------------------
// Scratch (device globals; no dynamic allocation allowed)
// ----------------------------------------------------------------------------
__device__ float g_h1[NN * HH];    // h1 = x@W1 ; later h3 = x2@W3
__device__ float g_agg[NN * HH];   // aggregation outputs
__device__ float g_x1[NN * HH];    // x1
__device__ float g_xin[NN * HH];   // x_in_proj ; later x3
__device__ float g_hg[NN * HH];    // hg ; later x2
__device__ float g_h4[NN * DOUT];
__device__ float g_t[NN * 64];
__device__ float g_as[NN * HEADS];
__device__ float g_ad[NN * HEADS];
__device__ float g_deg[NN];
__device__ float g_dinv[NN];
__device__ int   g_cnt[NN];
__device__ int   g_cur[NN];
__device__ int   g_rowptr[NN + 1];
__device__ int2  g_epack[EE];      // (src, coef bits)
__device__ int   g_part[512];
__device__ int   g_poff[512];
__device__ float g_bnsum[6 * 128];
__device__ float g_bnscale[128];
__device__ float g_bnshift[128];

__device__ __forceinline__ float lrelu(float v) { return v > 0.f ? v : 0.2f * v; }

// ----------------------------------------------------------------------------
// Graph preprocessing
// ----------------------------------------------------------------------------
__global__ void __launch_bounds__(256) init_kernel() {
    int i = blockIdx.x * blockDim.x + threadIdx.x;
    if (i < NN) { g_deg[i] = 1.0f; g_cnt[i] = 0; g_cur[i] = 0; }
    if (i < 6 * 128) g_bnsum[i] = 0.f;
}

__global__ void __launch_bounds__(256) count_kernel(const int* __restrict__ dst,
                                                    const float* __restrict__ w) {
    int e = blockIdx.x * blockDim.x + threadIdx.x;
    if (e < EE) {
        int d = dst[e];
        atomicAdd(&g_deg[d], w[e]);
        atomicAdd(&g_cnt[d], 1);
    }
}

__global__ void __launch_bounds__(256) dinv_kernel() {
    int i = blockIdx.x * blockDim.x + threadIdx.x;
    if (i < NN) g_dinv[i] = rsqrtf(g_deg[i]);
}

// Multi-block scan of g_cnt -> g_rowptr
__global__ void __launch_bounds__(256) part_kernel() {
    __shared__ int sw[8];
    int i = blockIdx.x * 256 + threadIdx.x;
    int v = (i < NN) ? g_cnt[i] : 0;
#pragma unroll
    for (int off = 16; off; off >>= 1) v += __shfl_down_sync(0xffffffffu, v, off);
    if ((threadIdx.x & 31) == 0) sw[threadIdx.x >> 5] = v;
    __syncthreads();
    if (threadIdx.x == 0) {
        int s = 0;
#pragma unroll
        for (int k = 0; k < 8; k++) s += sw[k];
        g_part[blockIdx.x] = s;
    }
}

__global__ void __launch_bounds__(512) scanpart_kernel() {
    __shared__ int sp[512];
    int t = threadIdx.x;
    sp[t] = (t < NB) ? g_part[t] : 0;
    __syncthreads();
    for (int off = 1; off < 512; off <<= 1) {
        int a = (t >= off) ? sp[t - off] : 0;
        __syncthreads();
        sp[t] += a;
        __syncthreads();
    }
    if (t < NB) g_poff[t] = (t == 0) ? 0 : sp[t - 1];
}

__global__ void __launch_bounds__(256) writerow_kernel() {
    __shared__ int sp[256];
    int t = threadIdx.x;
    int i = blockIdx.x * 256 + t;
    int v = (i < NN) ? g_cnt[i] : 0;
    sp[t] = v;
    __syncthreads();
    for (int off = 1; off < 256; off <<= 1) {
        int a = (t >= off) ? sp[t - off] : 0;
        __syncthreads();
        sp[t] += a;
        __syncthreads();
    }
    if (i < NN) g_rowptr[i] = sp[t] - v + g_poff[blockIdx.x];
    if (i == 0) g_rowptr[NN] = EE;
}

// Fill CSR with precomputed coef = w * dinv[src] * dinv[dst]
__global__ void __launch_bounds__(256) fill_kernel(const int* __restrict__ src,
                                                   const int* __restrict__ dst,
                                                   const float* __restrict__ w) {
    int e = blockIdx.x * blockDim.x + threadIdx.x;
    if (e < EE) {
        int d = dst[e];
        int s = src[e];
        int pos = g_rowptr[d] + atomicAdd(&g_cur[d], 1);
        float coef = w[e] * __ldg(&g_dinv[s]) * __ldg(&g_dinv[d]);
        g_epack[pos] = make_int2(s, __float_as_int(coef));
    }
}

// ----------------------------------------------------------------------------
// GEMMs
// ----------------------------------------------------------------------------
__global__ void __launch_bounds__(128) gemm_in_kernel(
        const float* __restrict__ X, const float* __restrict__ W1,
        const float* __restrict__ Wi, const float* __restrict__ bi,
        float* __restrict__ h1, float* __restrict__ xin) {
    const int tid = threadIdx.x;
    const int cg = tid & 31;
    const int rg = tid >> 5;
    const int n0 = blockIdx.x * 16 + rg * 4;
    float a1[4][4] = {}; float ai[4][4] = {};
    const float4* W1v = (const float4*)W1;
    const float4* Wiv = (const float4*)Wi;
#pragma unroll
    for (int k = 0; k < DIN; k++) {
        float4 w1 = __ldg(&W1v[k * 32 + cg]);
        float4 wi = __ldg(&Wiv[k * 32 + cg]);
#pragma unroll
        for (int r = 0; r < 4; r++) {
            float xv = __ldg(&X[(n0 + r) * DIN + k]);
            a1[r][0] += xv * w1.x; a1[r][1] += xv * w1.y; a1[r][2] += xv * w1.z; a1[r][3] += xv * w1.w;
            ai[r][0] += xv * wi.x; ai[r][1] += xv * wi.y; ai[r][2] += xv * wi.z; ai[r][3] += xv * wi.w;
        }
    }
    const int c0 = cg * 4;
    float4 bv = __ldg(&((const float4*)bi)[cg]);
#pragma unroll
    for (int r = 0; r < 4; r++) {
        float4 v1, vi;
        v1.x = a1[r][0]; v1.y = a1[r][1]; v1.z = a1[r][2]; v1.w = a1[r][3];
        vi.x = ai[r][0] + bv.x; vi.y = ai[r][1] + bv.y; vi.z = ai[r][2] + bv.z; vi.w = ai[r][3] + bv.w;
        *(float4*)&h1[(n0 + r) * HH + c0] = v1;
        *(float4*)&xin[(n0 + r) * HH + c0] = vi;
    }
}

template<int COLS, bool RELU, bool BIAS>
__global__ void __launch_bounds__(128) gemm_k128(
        const float* __restrict__ X, const float* __restrict__ W,
        const float* __restrict__ bias, float* __restrict__ out) {
    constexpr int CG = COLS / 4;
    constexpr int RG = 128 / CG;
    const int tid = threadIdx.x;
    const int cg = tid % CG;
    const int rg = tid / CG;
    const int n0 = blockIdx.x * (RG * 4) + rg * 4;
    float acc[4][4] = {};
    const float4* Wv = (const float4*)W;
    const float4* Xv = (const float4*)X;
#pragma unroll 2
    for (int k8 = 0; k8 < 128; k8 += 8) {
        float xr[4][8];
#pragma unroll
        for (int r = 0; r < 4; r++) {
            float4 a = __ldg(&Xv[((n0 + r) * 128 + k8) >> 2]);
            float4 b = __ldg(&Xv[((n0 + r) * 128 + k8 + 4) >> 2]);
            xr[r][0] = a.x; xr[r][1] = a.y; xr[r][2] = a.z; xr[r][3] = a.w;
            xr[r][4] = b.x; xr[r][5] = b.y; xr[r][6] = b.z; xr[r][7] = b.w;
        }
#pragma unroll
        for (int kk = 0; kk < 8; kk++) {
            float4 w = __ldg(&Wv[(k8 + kk) * CG + cg]);
#pragma unroll
            for (int r = 0; r < 4; r++) {
                acc[r][0] += xr[r][kk] * w.x;
                acc[r][1] += xr[r][kk] * w.y;
                acc[r][2] += xr[r][kk] * w.z;
                acc[r][3] += xr[r][kk] * w.w;
            }
        }
    }
    const int c0 = cg * 4;
    float4 bv = make_float4(0.f, 0.f, 0.f, 0.f);
    if (BIAS) bv = __ldg(&((const float4*)bias)[cg]);
#pragma unroll
    for (int r = 0; r < 4; r++) {
        float4 v;
        v.x = acc[r][0] + bv.x; v.y = acc[r][1] + bv.y;
        v.z = acc[r][2] + bv.z; v.w = acc[r][3] + bv.w;
        if (RELU) { v.x = fmaxf(v.x, 0.f); v.y = fmaxf(v.y, 0.f); v.z = fmaxf(v.z, 0.f); v.w = fmaxf(v.w, 0.f); }
        *(float4*)&out[(n0 + r) * COLS + c0] = v;
    }
}

__global__ void __launch_bounds__(128) gemm_w4_kernel(
        const float* __restrict__ X, const float* __restrict__ W,
        float* __restrict__ out) {
    const int tid = threadIdx.x;
    const int r = tid >> 4;
    const int c = tid & 15;
    const int n = blockIdx.x * 8 + r;
    if (c < DOUT) {
        float acc = 0.f;
#pragma unroll 8
        for (int k = 0; k < 128; k++)
            acc += __ldg(&X[n * 128 + k]) * __ldg(&W[k * DOUT + c]);
        out[n * DOUT + c] = acc;
    }
}

// ----------------------------------------------------------------------------
// BN
// ----------------------------------------------------------------------------
__global__ void __launch_bounds__(128) bn_stats(const float* __restrict__ in,
                                                float* __restrict__ sums) {
    const int c = threadIdx.x;
    float s = 0.f, s2 = 0.f;
    for (int n = blockIdx.x; n < NN; n += gridDim.x) {
        float v = in[n * HH + c];
        s += v; s2 += v * v;
    }
    atomicAdd(&sums[c], s);
    atomicAdd(&sums[c + 128], s2);
}

__global__ void __launch_bounds__(128) bn_final(const float* __restrict__ sums,
                                                const float* __restrict__ g,
                                                const float* __restrict__ be) {
    const int c = threadIdx.x;
    float mean = sums[c] * (1.0f / NN);
    float var = sums[c + 128] * (1.0f / NN) - mean * mean;
    var = fmaxf(var, 0.f);
    float rstd = rsqrtf(var + 1e-5f);
    float sc = rstd * g[c];
    g_bnscale[c] = sc;
    g_bnshift[c] = be[c] - mean * sc;
}

// out = relu(in*scale + shift) [+ add], float4-vectorized
__global__ void __launch_bounds__(256) apply_bn_relu(const float4* __restrict__ in,
                                                     const float4* __restrict__ add,
                                                     float4* __restrict__ out) {
    int idx = blockIdx.x * blockDim.x + threadIdx.x;
    if (idx < NN * 32) {
        int c4 = idx & 31;
        float4 sc = ((const float4*)g_bnscale)[c4];
        float4 sh = ((const float4*)g_bnshift)[c4];
        float4 v = in[idx];
        v.x = fmaxf(v.x * sc.x + sh.x, 0.f);
        v.y = fmaxf(v.y * sc.y + sh.y, 0.f);
        v.z = fmaxf(v.z * sc.z + sh.z, 0.f);
        v.w = fmaxf(v.w * sc.w + sh.w, 0.f);
        if (add) {
            float4 a = add[idx];
            v.x += a.x; v.y += a.y; v.z += a.z; v.w += a.w;
        }
        out[idx] = v;
    }
}

// ----------------------------------------------------------------------------
// GCN aggregation: warp per node, float4 channels
// ----------------------------------------------------------------------------
__global__ void __launch_bounds__(128) gcn_agg128(const float* __restrict__ in,
                                                  const float* __restrict__ bias,
                                                  float* __restrict__ out) {
    const int warp = threadIdx.x >> 5;
    const int lane = threadIdx.x & 31;
    const int n = blockIdx.x * 4 + warp;
    const float dn = g_dinv[n];
    const int s0 = g_rowptr[n], s1 = g_rowptr[n + 1];
    const float4* in4 = (const float4*)in;
    float4 acc = __ldg(&in4[n * 32 + lane]);
    float dn2 = dn * dn;
    acc.x *= dn2; acc.y *= dn2; acc.z *= dn2; acc.w *= dn2;
    int j = s0;
    for (; j + 2 <= s1; j += 2) {
        int2 eA = __ldg(&g_epack[j]);
        int2 eB = __ldg(&g_epack[j + 1]);
        float4 vA = __ldg(&in4[eA.x * 32 + lane]);
        float4 vB = __ldg(&in4[eB.x * 32 + lane]);
        float cA = __int_as_float(eA.y);
        float cB = __int_as_float(eB.y);
        acc.x += cA * vA.x + cB * vB.x;
        acc.y += cA * vA.y + cB * vB.y;
        acc.z += cA * vA.z + cB * vB.z;
        acc.w += cA * vA.w + cB * vB.w;
    }
    if (j < s1) {
        int2 e = __ldg(&g_epack[j]);
        float4 v = __ldg(&in4[e.x * 32 + lane]);
        float c = __int_as_float(e.y);
        acc.x += c * v.x; acc.y += c * v.y; acc.z += c * v.z; acc.w += c * v.w;
    }
    float4 bv = __ldg(&((const float4*)bias)[lane]);
    acc.x += bv.x; acc.y += bv.y; acc.z += bv.z; acc.w += bv.w;
    ((float4*)out)[n * 32 + lane] = acc;
}

__global__ void __launch_bounds__(128) gcn_agg12(const float* __restrict__ in,
                                                 const float* __restrict__ bias,
                                                 float* __restrict__ out) {
    const int warp = threadIdx.x >> 5;
    const int lane = threadIdx.x & 31;
    const int n = blockIdx.x * 4 + warp;
    const float dn = g_dinv[n];
    const int s0 = g_rowptr[n], s1 = g_rowptr[n + 1];
    float acc = (lane < DOUT) ? in[n * DOUT + lane] * dn * dn : 0.f;
    int j = s0;
    for (; j + 2 <= s1; j += 2) {
        int2 eA = __ldg(&g_epack[j]);
        int2 eB = __ldg(&g_epack[j + 1]);
        float vA = (lane < DOUT) ? __ldg(&in[eA.x * DOUT + lane]) : 0.f;
        float vB = (lane < DOUT) ? __ldg(&in[eB.x * DOUT + lane]) : 0.f;
        acc += __int_as_float(eA.y) * vA + __int_as_float(eB.y) * vB;
    }
    if (j < s1) {
        int2 e = __ldg(&g_epack[j]);
        if (lane < DOUT) acc += __int_as_float(e.y) * __ldg(&in[e.x * DOUT + lane]);
    }
    if (lane < DOUT) out[n * DOUT + lane] = acc + bias[lane];
}

// ----------------------------------------------------------------------------
// GAT
// ----------------------------------------------------------------------------
__global__ void __launch_bounds__(256) att_reduce(const float* __restrict__ hg,
                                                  const float* __restrict__ att_s,
                                                  const float* __restrict__ att_d) {
    const int tid = threadIdx.x;
    const int n = blockIdx.x * 2 + (tid >> 7);
    const int c = tid & 127;
    float v = hg[n * HH + c];
    float ps = v * __ldg(&att_s[c]);
    float pd = v * __ldg(&att_d[c]);
#pragma unroll
    for (int off = 16; off; off >>= 1) {
        ps += __shfl_xor_sync(0xffffffffu, ps, off);
        pd += __shfl_xor_sync(0xffffffffu, pd, off);
    }
    if ((tid & 31) == 0) {
        int h = c >> 5;
        g_as[n * 4 + h] = ps;
        g_ad[n * 4 + h] = pd;
    }
}

__global__ void __launch_bounds__(128) gat_agg_kernel(const float* __restrict__ hg,
                                                      const float* __restrict__ bg,
                                                      float* __restrict__ out) {
    const int n = blockIdx.x;
    const int tid = threadIdx.x;
    const int lane = tid & 31;
    __shared__ float sh_m[4], sh_inv[4], sh_aself[4], sh_ad4[4];
    __shared__ float sh_ex[GAT_CAP * 4];
    __shared__ float4 sh_acc[128];
    const int s0 = g_rowptr[n];
    const int s1 = g_rowptr[n + 1];
    const int deg = s1 - s0;
    const bool cached = (deg <= GAT_CAP);
    const float4* as4 = (const float4*)g_as;
    const float4* ad4 = (const float4*)g_ad;
    if (tid < 32) {
        float4 adv = __ldg(&ad4[n]);
        float4 asv = __ldg(&as4[n]);
        float es0 = lrelu(asv.x + adv.x), es1 = lrelu(asv.y + adv.y);
        float es2 = lrelu(asv.z + adv.z), es3 = lrelu(asv.w + adv.w);
        float m0 = es0, m1 = es1, m2 = es2, m3 = es3;
        for (int j = lane; j < deg; j += 32) {
            int s = __ldg(&g_epack[s0 + j]).x;
            float4 a = __ldg(&as4[s]);
            float e0 = lrelu(a.x + adv.x), e1 = lrelu(a.y + adv.y);
            float e2 = lrelu(a.z + adv.z), e3 = lrelu(a.w + adv.w);
            if (cached) {
                sh_ex[j * 4 + 0] = e0; sh_ex[j * 4 + 1] = e1;
                sh_ex[j * 4 + 2] = e2; sh_ex[j * 4 + 3] = e3;
            }
            m0 = fmaxf(m0, e0); m1 = fmaxf(m1, e1);
            m2 = fmaxf(m2, e2); m3 = fmaxf(m3, e3);
        }
#pragma unroll
        for (int off = 16; off; off >>= 1) {
            m0 = fmaxf(m0, __shfl_xor_sync(0xffffffffu, m0, off));
            m1 = fmaxf(m1, __shfl_xor_sync(0xffffffffu, m1, off));
            m2 = fmaxf(m2, __shfl_xor_sync(0xffffffffu, m2, off));
            m3 = fmaxf(m3, __shfl_xor_sync(0xffffffffu, m3, off));
        }
        float t0 = 0.f, t1 = 0.f, t2 = 0.f, t3 = 0.f;
        if (cached) {
            for (int j = lane; j < deg; j += 32) {
                float x0 = expf(sh_ex[j * 4 + 0] - m0); sh_ex[j * 4 + 0] = x0; t0 += x0;
                float x1 = expf(sh_ex[j * 4 + 1] - m1); sh_ex[j * 4 + 1] = x1; t1 += x1;
                float x2 = expf(sh_ex[j * 4 + 2] - m2); sh_ex[j * 4 + 2] = x2; t2 += x2;
                float x3 = expf(sh_ex[j * 4 + 3] - m3); sh_ex[j * 4 + 3] = x3; t3 += x3;
            }
        } else {
            for (int j = lane; j < deg; j += 32) {
                int s = __ldg(&g_epack[s0 + j]).x;
                float4 a = __ldg(&as4[s]);
                t0 += expf(lrelu(a.x + adv.x) - m0);
                t1 += expf(lrelu(a.y + adv.y) - m1);
                t2 += expf(lrelu(a.z + adv.z) - m2);
                t3 += expf(lrelu(a.w + adv.w) - m3);
            }
        }
#pragma unroll
        for (int off = 16; off; off >>= 1) {
            t0 += __shfl_xor_sync(0xffffffffu, t0, off);
            t1 += __shfl_xor_sync(0xffffffffu, t1, off);
            t2 += __shfl_xor_sync(0xffffffffu, t2, off);
            t3 += __shfl_xor_sync(0xffffffffu, t3, off);
        }
        if (lane == 0) {
            float x0 = expf(es0 - m0), x1 = expf(es1 - m1);
            float x2 = expf(es2 - m2), x3 = expf(es3 - m3);
            t0 += x0; t1 += x1; t2 += x2; t3 += x3;
            float i0 = 1.f / t0, i1 = 1.f / t1, i2 = 1.f / t2, i3 = 1.f / t3;
            sh_m[0] = m0; sh_m[1] = m1; sh_m[2] = m2; sh_m[3] = m3;
            sh_inv[0] = i0; sh_inv[1] = i1; sh_inv[2] = i2; sh_inv[3] = i3;
            sh_aself[0] = x0 * i0; sh_aself[1] = x1 * i1;
            sh_aself[2] = x2 * i2; sh_aself[3] = x3 * i3;
            sh_ad4[0] = adv.x; sh_ad4[1] = adv.y; sh_ad4[2] = adv.z; sh_ad4[3] = adv.w;
        }
    }
    __syncthreads();
    // Gather phase: warp `eslot` handles edges j = eslot, eslot+4, ...
    // Within a warp, lane -> float4 channel group; h = lane>>3 is the head.
    const int eslot = tid >> 5;
    const int h = lane >> 3;
    const float4* hg4 = (const float4*)hg;
    float4 acc = make_float4(0.f, 0.f, 0.f, 0.f);
    if (cached) {
        for (int j = eslot; j < deg; j += 4) {
            int s = __ldg(&g_epack[s0 + j]).x;
            float a = sh_ex[j * 4 + h];
            float4 v = __ldg(&hg4[s * 32 + lane]);
            acc.x += a * v.x; acc.y += a * v.y; acc.z += a * v.z; acc.w += a * v.w;
        }
    } else {
        const float m = sh_m[h];
        const float ad = sh_ad4[h];
        for (int j = eslot; j < deg; j += 4) {
            int s = __ldg(&g_epack[s0 + j]).x;
            float e = lrelu(__ldg(&g_as[s * 4 + h]) + ad);
            float a = expf(e - m);
            float4 v = __ldg(&hg4[s * 32 + lane]);
            acc.x += a * v.x; acc.y += a * v.y; acc.z += a * v.z; acc.w += a * v.w;
        }
    }
    sh_acc[tid] = acc;
    __syncthreads();
    if (tid < 32) {
        float4 a0 = sh_acc[tid], a1 = sh_acc[tid + 32], a2 = sh_acc[tid + 64], a3 = sh_acc[tid + 96];
        float4 tot;
        tot.x = a0.x + a1.x + a2.x + a3.x;
        tot.y = a0.y + a1.y + a2.y + a3.y;
        tot.z = a0.z + a1.z + a2.z + a3.z;
        tot.w = a0.w + a1.w + a2.w + a3.w;
        float4 self = __ldg(&hg4[n * 32 + lane]);
        float asf = sh_aself[h], inv = sh_inv[h];
        float4 bv = __ldg(&((const float4*)bg)[lane]);
        float4 o;
        o.x = asf * self.x + inv * tot.x + bv.x;
        o.y = asf * self.y + inv * tot.y + bv.y;
        o.z = asf * self.z + inv * tot.z + bv.z;
        o.w = asf * self.w + inv * tot.w + bv.w;
        ((float4*)out)[n * 32 + lane] = o;
    }
}

// ----------------------------------------------------------------------------
// Gate + final epilogue
// ----------------------------------------------------------------------------
__global__ void __launch_bounds__(128) final_kernel(
        const float* __restrict__ t, const float* __restrict__ x,
        const float* __restrict__ Gw2, const float* __restrict__ Gb2,
        const float* __restrict__ Ws, const float* __restrict__ bs,
        float* __restrict__ out) {
    __shared__ float sG[64 * DOUT];
    __shared__ float sGb[DOUT], sWs[DOUT], sbs[DOUT];
    const int tid = threadIdx.x;
    for (int i = tid; i < 64 * DOUT; i += 128) sG[i] = Gw2[i];
    if (tid < DOUT) { sGb[tid] = Gb2[tid]; sWs[tid] = Ws[tid]; sbs[tid] = bs[tid]; }
    __syncthreads();
    if (tid < 120) {
        const int ni = tid / DOUT, c = tid % DOUT;
        const int n = blockIdx.x * 10 + ni;
        float z = sGb[c];
#pragma unroll 8
        for (int k = 0; k < 64; k++)
            z += __ldg(&t[n * 64 + k]) * sG[k * DOUT + c];
        float gate = 1.f / (1.f + expf(-z));
        float status = __ldg(&x[n * DIN + 12]);
        float flag = status < 0.5f ? 1.f : 0.f;
        float sig = (1.f - status) * sWs[c] + sbs[c];
        out[n * DOUT + c] += 2.5f * flag * gate * sig;
    }
}

// ----------------------------------------------------------------------------
// Launch
// ----------------------------------------------------------------------------
extern "C" void kernel_launch(void* const* d_in, const int* in_sizes, int n_in,
                              void* d_out, int out_size) {
    const float* x   = (const float*)d_in[0];
    const int*   ei  = (const int*)d_in[1];
    const float* ew  = (const float*)d_in[2];
    const float* W1  = (const float*)d_in[3];
    const float* b1  = (const float*)d_in[4];
    const float* g1  = (const float*)d_in[5];
    const float* be1 = (const float*)d_in[6];
    const float* Wg  = (const float*)d_in[7];
    const float* atts= (const float*)d_in[8];
    const float* attd= (const float*)d_in[9];
    const float* bg  = (const float*)d_in[10];
    const float* g2  = (const float*)d_in[11];
    const float* be2 = (const float*)d_in[12];
    const float* W3  = (const float*)d_in[13];
    const float* b3  = (const float*)d_in[14];
    const float* g3  = (const float*)d_in[15];
    const float* be3 = (const float*)d_in[16];
    const float* W4  = (const float*)d_in[17];
    const float* b4  = (const float*)d_in[18];
    const float* Wi  = (const float*)d_in[19];
    const float* bi  = (const float*)d_in[20];
    const float* Gw1 = (const float*)d_in[21];
    const float* Gb1 = (const float*)d_in[22];
    const float* Gw2 = (const float*)d_in[23];
    const float* Gb2 = (const float*)d_in[24];
    const float* Ws  = (const float*)d_in[25];
    const float* bs  = (const float*)d_in[26];
    float* out = (float*)d_out;
    const int* src = ei;
    const int* dst = ei + EE;

    float *p_h1, *p_agg, *p_x1, *p_xin, *p_hg, *p_h4, *p_t, *p_bnsum;
    cudaGetSymbolAddress((void**)&p_h1, g_h1);
    cudaGetSymbolAddress((void**)&p_agg, g_agg);
    cudaGetSymbolAddress((void**)&p_x1, g_x1);
    cudaGetSymbolAddress((void**)&p_xin, g_xin);
    cudaGetSymbolAddress((void**)&p_hg, g_hg);
    cudaGetSymbolAddress((void**)&p_h4, g_h4);
    cudaGetSymbolAddress((void**)&p_t, g_t);
    cudaGetSymbolAddress((void**)&p_bnsum, g_bnsum);

    // graph preprocessing
    init_kernel<<<(NN + 255) / 256, 256>>>();
    count_kernel<<<(EE + 255) / 256, 256>>>(dst, ew);
    dinv_kernel<<<(NN + 255) / 256, 256>>>();
    part_kernel<<<NB, 256>>>();
    scanpart_kernel<<<1, 512>>>();
    writerow_kernel<<<NB, 256>>>();
    fill_kernel<<<(EE + 255) / 256, 256>>>(src, dst, ew);

    // layer 1: gcn + bn + relu
    gemm_in_kernel<<<NN / 16, 128>>>(x, W1, Wi, bi, p_h1, p_xin);
    gcn_agg128<<<NN / 4, 128>>>(p_h1, b1, p_agg);
    bn_stats<<<1024, 128>>>(p_agg, p_bnsum + 0 * 256);
    bn_final<<<1, 128>>>(p_bnsum + 0 * 256, g1, be1);
    apply_bn_relu<<<(NN * 32 + 255) / 256, 256>>>((const float4*)p_agg, nullptr, (float4*)p_x1);

    // GAT
    gemm_k128<128, false, false><<<NN / 16, 128>>>(p_x1, Wg, nullptr, p_hg);
    att_reduce<<<NN / 2, 256>>>(p_hg, atts, attd);
    gat_agg_kernel<<<NN, 128>>>(p_hg, bg, p_agg);
    bn_stats<<<1024, 128>>>(p_agg, p_bnsum + 1 * 256);
    bn_final<<<1, 128>>>(p_bnsum + 1 * 256, g2, be2);
    apply_bn_relu<<<(NN * 32 + 255) / 256, 256>>>((const float4*)p_agg, (const float4*)p_xin, (float4*)p_hg);

    // layer 3: gcn + bn + relu + x1
    gemm_k128<128, false, false><<<NN / 16, 128>>>(p_hg, W3, nullptr, p_h1);
    gcn_agg128<<<NN / 4, 128>>>(p_h1, b3, p_agg);
    bn_stats<<<1024, 128>>>(p_agg, p_bnsum + 2 * 256);
    bn_final<<<1, 128>>>(p_bnsum + 2 * 256, g3, be3);
    apply_bn_relu<<<(NN * 32 + 255) / 256, 256>>>((const float4*)p_agg, (const float4*)p_x1, (float4*)p_xin);

    // output gcn + gate
    gemm_w4_kernel<<<NN / 8, 128>>>(p_xin, W4, p_h4);
    gemm_k128<64, true, true><<<NN / 32, 128>>>(p_xin, Gw1, Gb1, p_t);
    gcn_agg12<<<NN / 4, 128>>>(p_h4, b4, out);
    final_kernel<<<NN / 10, 128>>>(p_t, x, Gw2, Gb2, Ws, bs, out);
}

// round 5
// speedup vs baseline: 1.4935x; 1.1280x over previous
#include <cuda_runtime.h>
#include <math.h>
#include <stdint.h>

#define NN 100000
#define EE 1600000
#define DIN 24
#define HH 128
#define DOUT 12
#define HEADS 4
#define DH 32
#define GAT_CAP 512
#define NB 391   // ceil(NN/256)

// ----------------------------------------------------------------------------
// Scratch (device globals; no dynamic allocation allowed)
// ----------------------------------------------------------------------------
__device__ float g_h1[NN * HH];
__device__ float g_agg[NN * HH];
__device__ float g_x1[NN * HH];
__device__ float g_xin[NN * HH];
__device__ float g_hg[NN * HH];
__device__ float g_h4[NN * DOUT];
__device__ float g_t[NN * 64];
__device__ float g_as[NN * HEADS];
__device__ float g_ad[NN * HEADS];
__device__ float g_deg[NN];
__device__ float g_dinv[NN];
__device__ int   g_cnt[NN];
__device__ int   g_cur[NN];
__device__ int   g_rowptr[NN + 1];
__device__ int2  g_epack[EE];
__device__ int   g_part[512];
__device__ int   g_poff[512];
__device__ float g_bnsum[6 * 128];
__device__ float g_bnscale[128];
__device__ float g_bnshift[128];
__device__ float g_wtg[HH * HH];    // Wg^T  [128,128] K-major
__device__ float g_wt3[HH * HH];    // W3^T
__device__ float g_wtg1[64 * HH];   // Gw1^T [64,128]

__device__ __forceinline__ float lrelu(float v) { return v > 0.f ? v : 0.2f * v; }
__device__ __forceinline__ uint32_t to_tf32(float f) {
    uint32_t t;
    asm("cvt.rna.tf32.f32 %0, %1;" : "=r"(t) : "f"(f));
    return t;
}

// ----------------------------------------------------------------------------
// Graph preprocessing
// ----------------------------------------------------------------------------
__global__ void __launch_bounds__(256) init_kernel() {
    int i = blockIdx.x * blockDim.x + threadIdx.x;
    if (i < NN) { g_deg[i] = 1.0f; g_cnt[i] = 0; g_cur[i] = 0; }
    if (i < 6 * 128) g_bnsum[i] = 0.f;
}

__global__ void __launch_bounds__(256) count_kernel(const int* __restrict__ dst,
                                                    const float* __restrict__ w) {
    int e = blockIdx.x * blockDim.x + threadIdx.x;
    if (e < EE) {
        int d = dst[e];
        atomicAdd(&g_deg[d], w[e]);
        atomicAdd(&g_cnt[d], 1);
    }
}

__global__ void __launch_bounds__(256) dinv_kernel() {
    int i = blockIdx.x * blockDim.x + threadIdx.x;
    if (i < NN) g_dinv[i] = rsqrtf(g_deg[i]);
}

__global__ void __launch_bounds__(256) part_kernel() {
    __shared__ int sw[8];
    int i = blockIdx.x * 256 + threadIdx.x;
    int v = (i < NN) ? g_cnt[i] : 0;
#pragma unroll
    for (int off = 16; off; off >>= 1) v += __shfl_down_sync(0xffffffffu, v, off);
    if ((threadIdx.x & 31) == 0) sw[threadIdx.x >> 5] = v;
    __syncthreads();
    if (threadIdx.x == 0) {
        int s = 0;
#pragma unroll
        for (int k = 0; k < 8; k++) s += sw[k];
        g_part[blockIdx.x] = s;
    }
}

__global__ void __launch_bounds__(512) scanpart_kernel() {
    __shared__ int sp[512];
    int t = threadIdx.x;
    sp[t] = (t < NB) ? g_part[t] : 0;
    __syncthreads();
    for (int off = 1; off < 512; off <<= 1) {
        int a = (t >= off) ? sp[t - off] : 0;
        __syncthreads();
        sp[t] += a;
        __syncthreads();
    }
    if (t < NB) g_poff[t] = (t == 0) ? 0 : sp[t - 1];
}

__global__ void __launch_bounds__(256) writerow_kernel() {
    __shared__ int sp[256];
    int t = threadIdx.x;
    int i = blockIdx.x * 256 + t;
    int v = (i < NN) ? g_cnt[i] : 0;
    sp[t] = v;
    __syncthreads();
    for (int off = 1; off < 256; off <<= 1) {
        int a = (t >= off) ? sp[t - off] : 0;
        __syncthreads();
        sp[t] += a;
        __syncthreads();
    }
    if (i < NN) g_rowptr[i] = sp[t] - v + g_poff[blockIdx.x];
    if (i == 0) g_rowptr[NN] = EE;
}

__global__ void __launch_bounds__(256) fill_kernel(const int* __restrict__ src,
                                                   const int* __restrict__ dst,
                                                   const float* __restrict__ w) {
    int e = blockIdx.x * blockDim.x + threadIdx.x;
    if (e < EE) {
        int d = dst[e];
        int s = src[e];
        int pos = g_rowptr[d] + atomicAdd(&g_cur[d], 1);
        float coef = w[e] * __ldg(&g_dinv[s]) * __ldg(&g_dinv[d]);
        g_epack[pos] = make_int2(s, __float_as_int(coef));
    }
}

// W[k*C+c] -> Wt[c*K+k]
__global__ void __launch_bounds__(256) transpose_kernel(const float* __restrict__ W,
                                                        float* __restrict__ Wt,
                                                        int K, int C) {
    int idx = blockIdx.x * 256 + threadIdx.x;
    if (idx < K * C) {
        int k = idx / C, c = idx % C;
        Wt[c * K + k] = W[idx];
    }
}

// ----------------------------------------------------------------------------
// TF32 mma.sync GEMM: out[M, NC] = X[M,128] @ Bt^T  (Bt is [NC,128] K-major)
// 256 threads = 8 warps; warp w owns rows [blk*128 + w*16, +16)
// ----------------------------------------------------------------------------
template<int NC, bool RELU, bool BIAS>
__global__ void __launch_bounds__(256) mma_gemm(const float* __restrict__ X,
                                                const float* __restrict__ Bt,
                                                const float* __restrict__ bias,
                                                float* __restrict__ out) {
    extern __shared__ uint32_t sW[];   // [NC][132] tf32 bits, padded stride
    const int tid = threadIdx.x, wid = tid >> 5, lane = tid & 31;
    const int n0 = blockIdx.x * 128;

    for (int i = tid; i < NC * 128; i += 256) {
        int c = i >> 7, k = i & 127;
        sW[c * 132 + k] = to_tf32(__ldg(&Bt[i]));
    }
    __syncthreads();

    constexpr int NCH = NC / 8;
    float acc[NCH][4];
#pragma unroll
    for (int i = 0; i < NCH; i++) {
        acc[i][0] = 0.f; acc[i][1] = 0.f; acc[i][2] = 0.f; acc[i][3] = 0.f;
    }

    const int r0 = n0 + wid * 16 + (lane >> 2);
    const int r1 = r0 + 8;
    const bool v0 = r0 < NN, v1 = r1 < NN;
    const int kq = lane & 3;
    const int nq = lane >> 2;

#pragma unroll 4
    for (int k8 = 0; k8 < 128; k8 += 8) {
        float f0 = v0 ? __ldg(&X[(size_t)r0 * 128 + k8 + kq]) : 0.f;
        float f1 = v1 ? __ldg(&X[(size_t)r1 * 128 + k8 + kq]) : 0.f;
        float f2 = v0 ? __ldg(&X[(size_t)r0 * 128 + k8 + kq + 4]) : 0.f;
        float f3 = v1 ? __ldg(&X[(size_t)r1 * 128 + k8 + kq + 4]) : 0.f;
        uint32_t a0 = to_tf32(f0), a1 = to_tf32(f1), a2 = to_tf32(f2), a3 = to_tf32(f3);
#pragma unroll
        for (int nc = 0; nc < NCH; nc++) {
            uint32_t b0 = sW[(nc * 8 + nq) * 132 + k8 + kq];
            uint32_t b1 = sW[(nc * 8 + nq) * 132 + k8 + kq + 4];
            asm volatile(
                "mma.sync.aligned.m16n8k8.row.col.f32.tf32.tf32.f32 "
                "{%0,%1,%2,%3}, {%4,%5,%6,%7}, {%8,%9}, {%0,%1,%2,%3};"
                : "+f"(acc[nc][0]), "+f"(acc[nc][1]), "+f"(acc[nc][2]), "+f"(acc[nc][3])
                : "r"(a0), "r"(a1), "r"(a2), "r"(a3), "r"(b0), "r"(b1));
        }
    }

    const int colb = 2 * kq;
#pragma unroll
    for (int nc = 0; nc < NCH; nc++) {
        int col = nc * 8 + colb;
        float2 vlo = make_float2(acc[nc][0], acc[nc][1]);
        float2 vhi = make_float2(acc[nc][2], acc[nc][3]);
        if (BIAS) {
            float bx = __ldg(&bias[col]), by = __ldg(&bias[col + 1]);
            vlo.x += bx; vlo.y += by; vhi.x += bx; vhi.y += by;
        }
        if (RELU) {
            vlo.x = fmaxf(vlo.x, 0.f); vlo.y = fmaxf(vlo.y, 0.f);
            vhi.x = fmaxf(vhi.x, 0.f); vhi.y = fmaxf(vhi.y, 0.f);
        }
        if (v0) *(float2*)&out[(size_t)r0 * NC + col] = vlo;
        if (v1) *(float2*)&out[(size_t)r1 * NC + col] = vhi;
    }
}

// ----------------------------------------------------------------------------
// Small GEMMs (SIMT)
// ----------------------------------------------------------------------------
__global__ void __launch_bounds__(128) gemm_in_kernel(
        const float* __restrict__ X, const float* __restrict__ W1,
        const float* __restrict__ Wi, const float* __restrict__ bi,
        float* __restrict__ h1, float* __restrict__ xin) {
    const int tid = threadIdx.x;
    const int cg = tid & 31;
    const int rg = tid >> 5;
    const int n0 = blockIdx.x * 16 + rg * 4;
    float a1[4][4] = {}; float ai[4][4] = {};
    const float4* W1v = (const float4*)W1;
    const float4* Wiv = (const float4*)Wi;
#pragma unroll
    for (int k = 0; k < DIN; k++) {
        float4 w1 = __ldg(&W1v[k * 32 + cg]);
        float4 wi = __ldg(&Wiv[k * 32 + cg]);
#pragma unroll
        for (int r = 0; r < 4; r++) {
            float xv = __ldg(&X[(n0 + r) * DIN + k]);
            a1[r][0] += xv * w1.x; a1[r][1] += xv * w1.y; a1[r][2] += xv * w1.z; a1[r][3] += xv * w1.w;
            ai[r][0] += xv * wi.x; ai[r][1] += xv * wi.y; ai[r][2] += xv * wi.z; ai[r][3] += xv * wi.w;
        }
    }
    const int c0 = cg * 4;
    float4 bv = __ldg(&((const float4*)bi)[cg]);
#pragma unroll
    for (int r = 0; r < 4; r++) {
        float4 v1, vi;
        v1.x = a1[r][0]; v1.y = a1[r][1]; v1.z = a1[r][2]; v1.w = a1[r][3];
        vi.x = ai[r][0] + bv.x; vi.y = ai[r][1] + bv.y; vi.z = ai[r][2] + bv.z; vi.w = ai[r][3] + bv.w;
        *(float4*)&h1[(n0 + r) * HH + c0] = v1;
        *(float4*)&xin[(n0 + r) * HH + c0] = vi;
    }
}

__global__ void __launch_bounds__(128) gemm_w4_kernel(
        const float* __restrict__ X, const float* __restrict__ W,
        float* __restrict__ out) {
    const int tid = threadIdx.x;
    const int r = tid >> 4;
    const int c = tid & 15;
    const int n = blockIdx.x * 8 + r;
    if (c < DOUT) {
        float acc = 0.f;
#pragma unroll 8
        for (int k = 0; k < 128; k++)
            acc += __ldg(&X[n * 128 + k]) * __ldg(&W[k * DOUT + c]);
        out[n * DOUT + c] = acc;
    }
}

// ----------------------------------------------------------------------------
// BN
// ----------------------------------------------------------------------------
__global__ void __launch_bounds__(128) bn_stats(const float* __restrict__ in,
                                                float* __restrict__ sums) {
    const int c = threadIdx.x;
    float s = 0.f, s2 = 0.f;
    for (int n = blockIdx.x; n < NN; n += gridDim.x) {
        float v = in[n * HH + c];
        s += v; s2 += v * v;
    }
    atomicAdd(&sums[c], s);
    atomicAdd(&sums[c + 128], s2);
}

__global__ void __launch_bounds__(128) bn_final(const float* __restrict__ sums,
                                                const float* __restrict__ g,
                                                const float* __restrict__ be) {
    const int c = threadIdx.x;
    float mean = sums[c] * (1.0f / NN);
    float var = sums[c + 128] * (1.0f / NN) - mean * mean;
    var = fmaxf(var, 0.f);
    float rstd = rsqrtf(var + 1e-5f);
    float sc = rstd * g[c];
    g_bnscale[c] = sc;
    g_bnshift[c] = be[c] - mean * sc;
}

__global__ void __launch_bounds__(256) apply_bn_relu(const float4* __restrict__ in,
                                                     const float4* __restrict__ add,
                                                     float4* __restrict__ out) {
    int idx = blockIdx.x * blockDim.x + threadIdx.x;
    if (idx < NN * 32) {
        int c4 = idx & 31;
        float4 sc = ((const float4*)g_bnscale)[c4];
        float4 sh = ((const float4*)g_bnshift)[c4];
        float4 v = in[idx];
        v.x = fmaxf(v.x * sc.x + sh.x, 0.f);
        v.y = fmaxf(v.y * sc.y + sh.y, 0.f);
        v.z = fmaxf(v.z * sc.z + sh.z, 0.f);
        v.w = fmaxf(v.w * sc.w + sh.w, 0.f);
        if (add) {
            float4 a = add[idx];
            v.x += a.x; v.y += a.y; v.z += a.z; v.w += a.w;
        }
        out[idx] = v;
    }
}

// ----------------------------------------------------------------------------
// GCN aggregation
// ----------------------------------------------------------------------------
__global__ void __launch_bounds__(128) gcn_agg128(const float* __restrict__ in,
                                                  const float* __restrict__ bias,
                                                  float* __restrict__ out) {
    const int warp = threadIdx.x >> 5;
    const int lane = threadIdx.x & 31;
    const int n = blockIdx.x * 4 + warp;
    const float dn = g_dinv[n];
    const int s0 = g_rowptr[n], s1 = g_rowptr[n + 1];
    const float4* in4 = (const float4*)in;
    float4 acc = __ldg(&in4[n * 32 + lane]);
    float dn2 = dn * dn;
    acc.x *= dn2; acc.y *= dn2; acc.z *= dn2; acc.w *= dn2;
    int j = s0;
    for (; j + 2 <= s1; j += 2) {
        int2 eA = __ldg(&g_epack[j]);
        int2 eB = __ldg(&g_epack[j + 1]);
        float4 vA = __ldg(&in4[eA.x * 32 + lane]);
        float4 vB = __ldg(&in4[eB.x * 32 + lane]);
        float cA = __int_as_float(eA.y);
        float cB = __int_as_float(eB.y);
        acc.x += cA * vA.x + cB * vB.x;
        acc.y += cA * vA.y + cB * vB.y;
        acc.z += cA * vA.z + cB * vB.z;
        acc.w += cA * vA.w + cB * vB.w;
    }
    if (j < s1) {
        int2 e = __ldg(&g_epack[j]);
        float4 v = __ldg(&in4[e.x * 32 + lane]);
        float c = __int_as_float(e.y);
        acc.x += c * v.x; acc.y += c * v.y; acc.z += c * v.z; acc.w += c * v.w;
    }
    float4 bv = __ldg(&((const float4*)bias)[lane]);
    acc.x += bv.x; acc.y += bv.y; acc.z += bv.z; acc.w += bv.w;
    ((float4*)out)[n * 32 + lane] = acc;
}

__global__ void __launch_bounds__(128) gcn_agg12(const float* __restrict__ in,
                                                 const float* __restrict__ bias,
                                                 float* __restrict__ out) {
    const int warp = threadIdx.x >> 5;
    const int lane = threadIdx.x & 31;
    const int n = blockIdx.x * 4 + warp;
    const float dn = g_dinv[n];
    const int s0 = g_rowptr[n], s1 = g_rowptr[n + 1];
    float acc = (lane < DOUT) ? in[n * DOUT + lane] * dn * dn : 0.f;
    int j = s0;
    for (; j + 2 <= s1; j += 2) {
        int2 eA = __ldg(&g_epack[j]);
        int2 eB = __ldg(&g_epack[j + 1]);
        float vA = (lane < DOUT) ? __ldg(&in[eA.x * DOUT + lane]) : 0.f;
        float vB = (lane < DOUT) ? __ldg(&in[eB.x * DOUT + lane]) : 0.f;
        acc += __int_as_float(eA.y) * vA + __int_as_float(eB.y) * vB;
    }
    if (j < s1) {
        int2 e = __ldg(&g_epack[j]);
        if (lane < DOUT) acc += __int_as_float(e.y) * __ldg(&in[e.x * DOUT + lane]);
    }
    if (lane < DOUT) out[n * DOUT + lane] = acc + bias[lane];
}

// ----------------------------------------------------------------------------
// GAT
// ----------------------------------------------------------------------------
__global__ void __launch_bounds__(256) att_reduce(const float* __restrict__ hg,
                                                  const float* __restrict__ att_s,
                                                  const float* __restrict__ att_d) {
    const int tid = threadIdx.x;
    const int n = blockIdx.x * 2 + (tid >> 7);
    const int c = tid & 127;
    float v = hg[n * HH + c];
    float ps = v * __ldg(&att_s[c]);
    float pd = v * __ldg(&att_d[c]);
#pragma unroll
    for (int off = 16; off; off >>= 1) {
        ps += __shfl_xor_sync(0xffffffffu, ps, off);
        pd += __shfl_xor_sync(0xffffffffu, pd, off);
    }
    if ((tid & 31) == 0) {
        int h = c >> 5;
        g_as[n * 4 + h] = ps;
        g_ad[n * 4 + h] = pd;
    }
}

__global__ void __launch_bounds__(128) gat_agg_kernel(const float* __restrict__ hg,
                                                      const float* __restrict__ bg,
                                                      float* __restrict__ out) {
    const int n = blockIdx.x;
    const int tid = threadIdx.x;
    const int lane = tid & 31;
    __shared__ float sh_m[4], sh_inv[4], sh_aself[4], sh_ad4[4];
    __shared__ float sh_ex[GAT_CAP * 4];
    __shared__ float4 sh_acc[128];
    const int s0 = g_rowptr[n];
    const int s1 = g_rowptr[n + 1];
    const int deg = s1 - s0;
    const bool cached = (deg <= GAT_CAP);
    const float4* as4 = (const float4*)g_as;
    const float4* ad4 = (const float4*)g_ad;
    if (tid < 32) {
        float4 adv = __ldg(&ad4[n]);
        float4 asv = __ldg(&as4[n]);
        float es0 = lrelu(asv.x + adv.x), es1 = lrelu(asv.y + adv.y);
        float es2 = lrelu(asv.z + adv.z), es3 = lrelu(asv.w + adv.w);
        float m0 = es0, m1 = es1, m2 = es2, m3 = es3;
        for (int j = lane; j < deg; j += 32) {
            int s = __ldg(&g_epack[s0 + j]).x;
            float4 a = __ldg(&as4[s]);
            float e0 = lrelu(a.x + adv.x), e1 = lrelu(a.y + adv.y);
            float e2 = lrelu(a.z + adv.z), e3 = lrelu(a.w + adv.w);
            if (cached) {
                sh_ex[j * 4 + 0] = e0; sh_ex[j * 4 + 1] = e1;
                sh_ex[j * 4 + 2] = e2; sh_ex[j * 4 + 3] = e3;
            }
            m0 = fmaxf(m0, e0); m1 = fmaxf(m1, e1);
            m2 = fmaxf(m2, e2); m3 = fmaxf(m3, e3);
        }
#pragma unroll
        for (int off = 16; off; off >>= 1) {
            m0 = fmaxf(m0, __shfl_xor_sync(0xffffffffu, m0, off));
            m1 = fmaxf(m1, __shfl_xor_sync(0xffffffffu, m1, off));
            m2 = fmaxf(m2, __shfl_xor_sync(0xffffffffu, m2, off));
            m3 = fmaxf(m3, __shfl_xor_sync(0xffffffffu, m3, off));
        }
        float t0 = 0.f, t1 = 0.f, t2 = 0.f, t3 = 0.f;
        if (cached) {
            for (int j = lane; j < deg; j += 32) {
                float x0 = expf(sh_ex[j * 4 + 0] - m0); sh_ex[j * 4 + 0] = x0; t0 += x0;
                float x1 = expf(sh_ex[j * 4 + 1] - m1); sh_ex[j * 4 + 1] = x1; t1 += x1;
                float x2 = expf(sh_ex[j * 4 + 2] - m2); sh_ex[j * 4 + 2] = x2; t2 += x2;
                float x3 = expf(sh_ex[j * 4 + 3] - m3); sh_ex[j * 4 + 3] = x3; t3 += x3;
            }
        } else {
            for (int j = lane; j < deg; j += 32) {
                int s = __ldg(&g_epack[s0 + j]).x;
                float4 a = __ldg(&as4[s]);
                t0 += expf(lrelu(a.x + adv.x) - m0);
                t1 += expf(lrelu(a.y + adv.y) - m1);
                t2 += expf(lrelu(a.z + adv.z) - m2);
                t3 += expf(lrelu(a.w + adv.w) - m3);
            }
        }
#pragma unroll
        for (int off = 16; off; off >>= 1) {
            t0 += __shfl_xor_sync(0xffffffffu, t0, off);
            t1 += __shfl_xor_sync(0xffffffffu, t1, off);
            t2 += __shfl_xor_sync(0xffffffffu, t2, off);
            t3 += __shfl_xor_sync(0xffffffffu, t3, off);
        }
        if (lane == 0) {
            float x0 = expf(es0 - m0), x1 = expf(es1 - m1);
            float x2 = expf(es2 - m2), x3 = expf(es3 - m3);
            t0 += x0; t1 += x1; t2 += x2; t3 += x3;
            float i0 = 1.f / t0, i1 = 1.f / t1, i2 = 1.f / t2, i3 = 1.f / t3;
            sh_m[0] = m0; sh_m[1] = m1; sh_m[2] = m2; sh_m[3] = m3;
            sh_inv[0] = i0; sh_inv[1] = i1; sh_inv[2] = i2; sh_inv[3] = i3;
            sh_aself[0] = x0 * i0; sh_aself[1] = x1 * i1;
            sh_aself[2] = x2 * i2; sh_aself[3] = x3 * i3;
            sh_ad4[0] = adv.x; sh_ad4[1] = adv.y; sh_ad4[2] = adv.z; sh_ad4[3] = adv.w;
        }
    }
    __syncthreads();
    const int eslot = tid >> 5;
    const int h = lane >> 3;
    const float4* hg4 = (const float4*)hg;
    float4 acc = make_float4(0.f, 0.f, 0.f, 0.f);
    if (cached) {
        for (int j = eslot; j < deg; j += 4) {
            int s = __ldg(&g_epack[s0 + j]).x;
            float a = sh_ex[j * 4 + h];
            float4 v = __ldg(&hg4[s * 32 + lane]);
            acc.x += a * v.x; acc.y += a * v.y; acc.z += a * v.z; acc.w += a * v.w;
        }
    } else {
        const float m = sh_m[h];
        const float ad = sh_ad4[h];
        for (int j = eslot; j < deg; j += 4) {
            int s = __ldg(&g_epack[s0 + j]).x;
            float e = lrelu(__ldg(&g_as[s * 4 + h]) + ad);
            float a = expf(e - m);
            float4 v = __ldg(&hg4[s * 32 + lane]);
            acc.x += a * v.x; acc.y += a * v.y; acc.z += a * v.z; acc.w += a * v.w;
        }
    }
    sh_acc[tid] = acc;
    __syncthreads();
    if (tid < 32) {
        float4 a0 = sh_acc[tid], a1 = sh_acc[tid + 32], a2 = sh_acc[tid + 64], a3 = sh_acc[tid + 96];
        float4 tot;
        tot.x = a0.x + a1.x + a2.x + a3.x;
        tot.y = a0.y + a1.y + a2.y + a3.y;
        tot.z = a0.z + a1.z + a2.z + a3.z;
        tot.w = a0.w + a1.w + a2.w + a3.w;
        float4 self = __ldg(&hg4[n * 32 + lane]);
        float asf = sh_aself[h], inv = sh_inv[h];
        float4 bv = __ldg(&((const float4*)bg)[lane]);
        float4 o;
        o.x = asf * self.x + inv * tot.x + bv.x;
        o.y = asf * self.y + inv * tot.y + bv.y;
        o.z = asf * self.z + inv * tot.z + bv.z;
        o.w = asf * self.w + inv * tot.w + bv.w;
        ((float4*)out)[n * 32 + lane] = o;
    }
}

// ----------------------------------------------------------------------------
// Gate + final epilogue
// ----------------------------------------------------------------------------
__global__ void __launch_bounds__(128) final_kernel(
        const float* __restrict__ t, const float* __restrict__ x,
        const float* __restrict__ Gw2, const float* __restrict__ Gb2,
        const float* __restrict__ Ws, const float* __restrict__ bs,
        float* __restrict__ out) {
    __shared__ float sG[64 * DOUT];
    __shared__ float sGb[DOUT], sWs[DOUT], sbs[DOUT];
    const int tid = threadIdx.x;
    for (int i = tid; i < 64 * DOUT; i += 128) sG[i] = Gw2[i];
    if (tid < DOUT) { sGb[tid] = Gb2[tid]; sWs[tid] = Ws[tid]; sbs[tid] = bs[tid]; }
    __syncthreads();
    if (tid < 120) {
        const int ni = tid / DOUT, c = tid % DOUT;
        const int n = blockIdx.x * 10 + ni;
        float z = sGb[c];
#pragma unroll 8
        for (int k = 0; k < 64; k++)
            z += __ldg(&t[n * 64 + k]) * sG[k * DOUT + c];
        float gate = 1.f / (1.f + expf(-z));
        float status = __ldg(&x[n * DIN + 12]);
        float flag = status < 0.5f ? 1.f : 0.f;
        float sig = (1.f - status) * sWs[c] + sbs[c];
        out[n * DOUT + c] += 2.5f * flag * gate * sig;
    }
}

// ----------------------------------------------------------------------------
// Launch
// ----------------------------------------------------------------------------
extern "C" void kernel_launch(void* const* d_in, const int* in_sizes, int n_in,
                              void* d_out, int out_size) {
    const float* x   = (const float*)d_in[0];
    const int*   ei  = (const int*)d_in[1];
    const float* ew  = (const float*)d_in[2];
    const float* W1  = (const float*)d_in[3];
    const float* b1  = (const float*)d_in[4];
    const float* g1  = (const float*)d_in[5];
    const float* be1 = (const float*)d_in[6];
    const float* Wg  = (const float*)d_in[7];
    const float* atts= (const float*)d_in[8];
    const float* attd= (const float*)d_in[9];
    const float* bg  = (const float*)d_in[10];
    const float* g2  = (const float*)d_in[11];
    const float* be2 = (const float*)d_in[12];
    const float* W3  = (const float*)d_in[13];
    const float* b3  = (const float*)d_in[14];
    const float* g3  = (const float*)d_in[15];
    const float* be3 = (const float*)d_in[16];
    const float* W4  = (const float*)d_in[17];
    const float* b4  = (const float*)d_in[18];
    const float* Wi  = (const float*)d_in[19];
    const float* bi  = (const float*)d_in[20];
    const float* Gw1 = (const float*)d_in[21];
    const float* Gb1 = (const float*)d_in[22];
    const float* Gw2 = (const float*)d_in[23];
    const float* Gb2 = (const float*)d_in[24];
    const float* Ws  = (const float*)d_in[25];
    const float* bs  = (const float*)d_in[26];
    float* out = (float*)d_out;
    const int* src = ei;
    const int* dst = ei + EE;

    float *p_h1, *p_agg, *p_x1, *p_xin, *p_hg, *p_h4, *p_t, *p_bnsum;
    float *p_wtg, *p_wt3, *p_wtg1;
    cudaGetSymbolAddress((void**)&p_h1, g_h1);
    cudaGetSymbolAddress((void**)&p_agg, g_agg);
    cudaGetSymbolAddress((void**)&p_x1, g_x1);
    cudaGetSymbolAddress((void**)&p_xin, g_xin);
    cudaGetSymbolAddress((void**)&p_hg, g_hg);
    cudaGetSymbolAddress((void**)&p_h4, g_h4);
    cudaGetSymbolAddress((void**)&p_t, g_t);
    cudaGetSymbolAddress((void**)&p_bnsum, g_bnsum);
    cudaGetSymbolAddress((void**)&p_wtg, g_wtg);
    cudaGetSymbolAddress((void**)&p_wt3, g_wt3);
    cudaGetSymbolAddress((void**)&p_wtg1, g_wtg1);

    const int SMEM128 = 128 * 132 * 4;   // 67584
    const int SMEM64  = 64 * 132 * 4;    // 33792
    cudaFuncSetAttribute(mma_gemm<128, false, false>,
                         cudaFuncAttributeMaxDynamicSharedMemorySize, SMEM128);
    cudaFuncSetAttribute(mma_gemm<64, true, true>,
                         cudaFuncAttributeMaxDynamicSharedMemorySize, SMEM64);
    const int MGRID = (NN + 127) / 128;   // 782

    // graph preprocessing + weight transposes
    init_kernel<<<(NN + 255) / 256, 256>>>();
    count_kernel<<<(EE + 255) / 256, 256>>>(dst, ew);
    dinv_kernel<<<(NN + 255) / 256, 256>>>();
    part_kernel<<<NB, 256>>>();
    scanpart_kernel<<<1, 512>>>();
    writerow_kernel<<<NB, 256>>>();
    fill_kernel<<<(EE + 255) / 256, 256>>>(src, dst, ew);
    transpose_kernel<<<64, 256>>>(Wg, p_wtg, 128, 128);
    transpose_kernel<<<64, 256>>>(W3, p_wt3, 128, 128);
    transpose_kernel<<<32, 256>>>(Gw1, p_wtg1, 128, 64);

    // layer 1: gcn + bn + relu
    gemm_in_kernel<<<NN / 16, 128>>>(x, W1, Wi, bi, p_h1, p_xin);
    gcn_agg128<<<NN / 4, 128>>>(p_h1, b1, p_agg);
    bn_stats<<<1024, 128>>>(p_agg, p_bnsum + 0 * 256);
    bn_final<<<1, 128>>>(p_bnsum + 0 * 256, g1, be1);
    apply_bn_relu<<<(NN * 32 + 255) / 256, 256>>>((const float4*)p_agg, nullptr, (float4*)p_x1);

    // GAT
    mma_gemm<128, false, false><<<MGRID, 256, SMEM128>>>(p_x1, p_wtg, nullptr, p_hg);
    att_reduce<<<NN / 2, 256>>>(p_hg, atts, attd);
    gat_agg_kernel<<<NN, 128>>>(p_hg, bg, p_agg);
    bn_stats<<<1024, 128>>>(p_agg, p_bnsum + 1 * 256);
    bn_final<<<1, 128>>>(p_bnsum + 1 * 256, g2, be2);
    apply_bn_relu<<<(NN * 32 + 255) / 256, 256>>>((const float4*)p_agg, (const float4*)p_xin, (float4*)p_hg);

    // layer 3: gcn + bn + relu + x1
    mma_gemm<128, false, false><<<MGRID, 256, SMEM128>>>(p_hg, p_wt3, nullptr, p_h1);
    gcn_agg128<<<NN / 4, 128>>>(p_h1, b3, p_agg);
    bn_stats<<<1024, 128>>>(p_agg, p_bnsum + 2 * 256);
    bn_final<<<1, 128>>>(p_bnsum + 2 * 256, g3, be3);
    apply_bn_relu<<<(NN * 32 + 255) / 256, 256>>>((const float4*)p_agg, (const float4*)p_x1, (float4*)p_xin);

    // output gcn + gate
    gemm_w4_kernel<<<NN / 8, 128>>>(p_xin, W4, p_h4);
    mma_gemm<64, true, true><<<MGRID, 256, SMEM64>>>(p_xin, p_wtg1, Gb1, p_t);
    gcn_agg12<<<NN / 4, 128>>>(p_h4, b4, out);
    final_kernel<<<NN / 10, 128>>>(p_t, x, Gw2, Gb2, Ws, bs, out);
}

// round 6
// speedup vs baseline: 1.5813x; 1.0588x over previous
#include <cuda_runtime.h>
#include <math.h>
#include <stdint.h>

#define NN 100000
#define EE 1600000
#define DIN 24
#define HH 128
#define DOUT 12
#define HEADS 4
#define DH 32
#define GAT_CAP 512
#define NB 391   // ceil(NN/256)

// ----------------------------------------------------------------------------
// Scratch (device globals; no dynamic allocation allowed)
// ----------------------------------------------------------------------------
__device__ float g_h1[NN * HH];
__device__ float g_agg[NN * HH];
__device__ float g_x1[NN * HH];
__device__ float g_xin[NN * HH];
__device__ float g_hg[NN * HH];
__device__ float g_xa[NN * DIN];    // 24-dim aggregated x
__device__ float g_h4[NN * DOUT];
__device__ float g_t[NN * 64];
__device__ float g_as[NN * HEADS];
__device__ float g_ad[NN * HEADS];
__device__ float g_deg[NN];
__device__ float g_dinv[NN];
__device__ int   g_cnt[NN];
__device__ int   g_cur[NN];
__device__ int   g_rowptr[NN + 1];
__device__ int2  g_epack[EE];
__device__ int   g_part[512];
__device__ int   g_poff[512];
__device__ float g_bnsum[6 * 128];
__device__ float g_bnscale[128];
__device__ float g_bnshift[128];
__device__ float g_wtg[HH * HH];    // Wg^T  [128,128] K-major
__device__ float g_wt3[HH * HH];    // W3^T
__device__ float g_wtg1[64 * HH];   // Gw1^T [64,128]

__device__ __forceinline__ float lrelu(float v) { return v > 0.f ? v : 0.2f * v; }
__device__ __forceinline__ uint32_t to_tf32(float f) {
    uint32_t t;
    asm("cvt.rna.tf32.f32 %0, %1;" : "=r"(t) : "f"(f));
    return t;
}

// ----------------------------------------------------------------------------
// Graph preprocessing
// ----------------------------------------------------------------------------
__global__ void __launch_bounds__(256) init_kernel() {
    int i = blockIdx.x * blockDim.x + threadIdx.x;
    if (i < NN) { g_deg[i] = 1.0f; g_cnt[i] = 0; g_cur[i] = 0; }
    if (i < 6 * 128) g_bnsum[i] = 0.f;
}

__global__ void __launch_bounds__(256) count_kernel(const int* __restrict__ dst,
                                                    const float* __restrict__ w) {
    int e = blockIdx.x * blockDim.x + threadIdx.x;
    if (e < EE) {
        int d = dst[e];
        atomicAdd(&g_deg[d], w[e]);
        atomicAdd(&g_cnt[d], 1);
    }
}

__global__ void __launch_bounds__(256) dinv_kernel() {
    int i = blockIdx.x * blockDim.x + threadIdx.x;
    if (i < NN) g_dinv[i] = rsqrtf(g_deg[i]);
}

__global__ void __launch_bounds__(256) part_kernel() {
    __shared__ int sw[8];
    int i = blockIdx.x * 256 + threadIdx.x;
    int v = (i < NN) ? g_cnt[i] : 0;
#pragma unroll
    for (int off = 16; off; off >>= 1) v += __shfl_down_sync(0xffffffffu, v, off);
    if ((threadIdx.x & 31) == 0) sw[threadIdx.x >> 5] = v;
    __syncthreads();
    if (threadIdx.x == 0) {
        int s = 0;
#pragma unroll
        for (int k = 0; k < 8; k++) s += sw[k];
        g_part[blockIdx.x] = s;
    }
}

__global__ void __launch_bounds__(512) scanpart_kernel() {
    __shared__ int sp[512];
    int t = threadIdx.x;
    sp[t] = (t < NB) ? g_part[t] : 0;
    __syncthreads();
    for (int off = 1; off < 512; off <<= 1) {
        int a = (t >= off) ? sp[t - off] : 0;
        __syncthreads();
        sp[t] += a;
        __syncthreads();
    }
    if (t < NB) g_poff[t] = (t == 0) ? 0 : sp[t - 1];
}

__global__ void __launch_bounds__(256) writerow_kernel() {
    __shared__ int sp[256];
    int t = threadIdx.x;
    int i = blockIdx.x * 256 + t;
    int v = (i < NN) ? g_cnt[i] : 0;
    sp[t] = v;
    __syncthreads();
    for (int off = 1; off < 256; off <<= 1) {
        int a = (t >= off) ? sp[t - off] : 0;
        __syncthreads();
        sp[t] += a;
        __syncthreads();
    }
    if (i < NN) g_rowptr[i] = sp[t] - v + g_poff[blockIdx.x];
    if (i == 0) g_rowptr[NN] = EE;
}

__global__ void __launch_bounds__(256) fill_kernel(const int* __restrict__ src,
                                                   const int* __restrict__ dst,
                                                   const float* __restrict__ w) {
    int e = blockIdx.x * blockDim.x + threadIdx.x;
    if (e < EE) {
        int d = dst[e];
        int s = src[e];
        int pos = g_rowptr[d] + atomicAdd(&g_cur[d], 1);
        float coef = w[e] * __ldg(&g_dinv[s]) * __ldg(&g_dinv[d]);
        g_epack[pos] = make_int2(s, __float_as_int(coef));
    }
}

// W[k*C+c] -> Wt[c*K+k]
__global__ void __launch_bounds__(256) transpose_kernel(const float* __restrict__ W,
                                                        float* __restrict__ Wt,
                                                        int K, int C) {
    int idx = blockIdx.x * 256 + threadIdx.x;
    if (idx < K * C) {
        int k = idx / C, c = idx % C;
        Wt[c * K + k] = W[idx];
    }
}

// ----------------------------------------------------------------------------
// 24-channel GCN aggregation of raw x (layer-1 reassociation)
// warp per node; lanes 0..23 = channels
// ----------------------------------------------------------------------------
__global__ void __launch_bounds__(128) agg24_kernel(const float* __restrict__ x,
                                                    float* __restrict__ xa) {
    const int warp = threadIdx.x >> 5;
    const int lane = threadIdx.x & 31;
    const int n = blockIdx.x * 4 + warp;
    const float dn = g_dinv[n];
    const int s0 = g_rowptr[n], s1 = g_rowptr[n + 1];
    float acc = (lane < DIN) ? x[n * DIN + lane] * dn * dn : 0.f;
    int j = s0;
    for (; j + 2 <= s1; j += 2) {
        int2 eA = __ldg(&g_epack[j]);
        int2 eB = __ldg(&g_epack[j + 1]);
        float vA = (lane < DIN) ? __ldg(&x[eA.x * DIN + lane]) : 0.f;
        float vB = (lane < DIN) ? __ldg(&x[eB.x * DIN + lane]) : 0.f;
        acc += __int_as_float(eA.y) * vA + __int_as_float(eB.y) * vB;
    }
    if (j < s1) {
        int2 e = __ldg(&g_epack[j]);
        if (lane < DIN) acc += __int_as_float(e.y) * __ldg(&x[e.x * DIN + lane]);
    }
    if (lane < DIN) xa[n * DIN + lane] = acc;
}

// ----------------------------------------------------------------------------
// TF32 mma.sync GEMM: out[M, NC] = X[M,128] @ Bt^T  (Bt is [NC,128] K-major)
// 256 threads = 8 warps; warp w owns rows [blk*128 + w*16, +16)
// ATT: also emit g_as/g_ad head reductions (NC must be 128)
// ----------------------------------------------------------------------------
template<int NC, bool RELU, bool BIAS, bool ATT>
__global__ void __launch_bounds__(256) mma_gemm(const float* __restrict__ X,
                                                const float* __restrict__ Bt,
                                                const float* __restrict__ bias,
                                                float* __restrict__ out,
                                                const float* __restrict__ att_s,
                                                const float* __restrict__ att_d) {
    extern __shared__ uint32_t sW[];   // [NC][132] tf32 bits, padded stride
    const int tid = threadIdx.x, wid = tid >> 5, lane = tid & 31;
    const int n0 = blockIdx.x * 128;

    for (int i = tid; i < NC * 128; i += 256) {
        int c = i >> 7, k = i & 127;
        sW[c * 132 + k] = to_tf32(__ldg(&Bt[i]));
    }
    __syncthreads();

    constexpr int NCH = NC / 8;
    float acc[NCH][4];
#pragma unroll
    for (int i = 0; i < NCH; i++) {
        acc[i][0] = 0.f; acc[i][1] = 0.f; acc[i][2] = 0.f; acc[i][3] = 0.f;
    }

    const int r0 = n0 + wid * 16 + (lane >> 2);
    const int r1 = r0 + 8;
    const bool v0 = r0 < NN, v1 = r1 < NN;
    const int kq = lane & 3;
    const int nq = lane >> 2;

#pragma unroll 4
    for (int k8 = 0; k8 < 128; k8 += 8) {
        float f0 = v0 ? __ldg(&X[(size_t)r0 * 128 + k8 + kq]) : 0.f;
        float f1 = v1 ? __ldg(&X[(size_t)r1 * 128 + k8 + kq]) : 0.f;
        float f2 = v0 ? __ldg(&X[(size_t)r0 * 128 + k8 + kq + 4]) : 0.f;
        float f3 = v1 ? __ldg(&X[(size_t)r1 * 128 + k8 + kq + 4]) : 0.f;
        uint32_t a0 = to_tf32(f0), a1 = to_tf32(f1), a2 = to_tf32(f2), a3 = to_tf32(f3);
#pragma unroll
        for (int nc = 0; nc < NCH; nc++) {
            uint32_t b0 = sW[(nc * 8 + nq) * 132 + k8 + kq];
            uint32_t b1 = sW[(nc * 8 + nq) * 132 + k8 + kq + 4];
            asm volatile(
                "mma.sync.aligned.m16n8k8.row.col.f32.tf32.tf32.f32 "
                "{%0,%1,%2,%3}, {%4,%5,%6,%7}, {%8,%9}, {%0,%1,%2,%3};"
                : "+f"(acc[nc][0]), "+f"(acc[nc][1]), "+f"(acc[nc][2]), "+f"(acc[nc][3])
                : "r"(a0), "r"(a1), "r"(a2), "r"(a3), "r"(b0), "r"(b1));
        }
    }

    const int colb = 2 * kq;
#pragma unroll
    for (int nc = 0; nc < NCH; nc++) {
        int col = nc * 8 + colb;
        float2 vlo = make_float2(acc[nc][0], acc[nc][1]);
        float2 vhi = make_float2(acc[nc][2], acc[nc][3]);
        if (BIAS) {
            float bx = __ldg(&bias[col]), by = __ldg(&bias[col + 1]);
            vlo.x += bx; vlo.y += by; vhi.x += bx; vhi.y += by;
        }
        if (RELU) {
            vlo.x = fmaxf(vlo.x, 0.f); vlo.y = fmaxf(vlo.y, 0.f);
            vhi.x = fmaxf(vhi.x, 0.f); vhi.y = fmaxf(vhi.y, 0.f);
        }
        if (v0) *(float2*)&out[(size_t)r0 * NC + col] = vlo;
        if (v1) *(float2*)&out[(size_t)r1 * NC + col] = vhi;
    }

    if (ATT) {
        float as0[4] = {}, ad0[4] = {}, as1[4] = {}, ad1[4] = {};
#pragma unroll
        for (int nc = 0; nc < NCH; nc++) {
            int col = nc * 8 + colb;
            float sx = __ldg(&att_s[col]), sy = __ldg(&att_s[col + 1]);
            float dx = __ldg(&att_d[col]), dy = __ldg(&att_d[col + 1]);
            int h = nc >> 2;
            as0[h] += acc[nc][0] * sx + acc[nc][1] * sy;
            ad0[h] += acc[nc][0] * dx + acc[nc][1] * dy;
            as1[h] += acc[nc][2] * sx + acc[nc][3] * sy;
            ad1[h] += acc[nc][2] * dx + acc[nc][3] * dy;
        }
#pragma unroll
        for (int h = 0; h < 4; h++) {
#pragma unroll
            for (int off = 1; off <= 2; off <<= 1) {
                as0[h] += __shfl_xor_sync(0xffffffffu, as0[h], off);
                ad0[h] += __shfl_xor_sync(0xffffffffu, ad0[h], off);
                as1[h] += __shfl_xor_sync(0xffffffffu, as1[h], off);
                ad1[h] += __shfl_xor_sync(0xffffffffu, ad1[h], off);
            }
        }
        if (kq == 0) {
#pragma unroll
            for (int h = 0; h < 4; h++) {
                if (v0) { g_as[r0 * 4 + h] = as0[h]; g_ad[r0 * 4 + h] = ad0[h]; }
                if (v1) { g_as[r1 * 4 + h] = as1[h]; g_ad[r1 * 4 + h] = ad1[h]; }
            }
        }
    }
}

// ----------------------------------------------------------------------------
// Fused input GEMM: h1 = xa@W1 + b1 (the layer-1 GCN output), xin = x@Wi + bi
// ----------------------------------------------------------------------------
__global__ void __launch_bounds__(128) gemm_in_kernel(
        const float* __restrict__ XA, const float* __restrict__ X,
        const float* __restrict__ W1, const float* __restrict__ b1,
        const float* __restrict__ Wi, const float* __restrict__ bi,
        float* __restrict__ h1, float* __restrict__ xin) {
    const int tid = threadIdx.x;
    const int cg = tid & 31;
    const int rg = tid >> 5;
    const int n0 = blockIdx.x * 16 + rg * 4;
    float a1[4][4] = {}; float ai[4][4] = {};
    const float4* W1v = (const float4*)W1;
    const float4* Wiv = (const float4*)Wi;
#pragma unroll
    for (int k = 0; k < DIN; k++) {
        float4 w1 = __ldg(&W1v[k * 32 + cg]);
        float4 wi = __ldg(&Wiv[k * 32 + cg]);
#pragma unroll
        for (int r = 0; r < 4; r++) {
            float xav = __ldg(&XA[(n0 + r) * DIN + k]);
            float xv  = __ldg(&X[(n0 + r) * DIN + k]);
            a1[r][0] += xav * w1.x; a1[r][1] += xav * w1.y; a1[r][2] += xav * w1.z; a1[r][3] += xav * w1.w;
            ai[r][0] += xv * wi.x;  ai[r][1] += xv * wi.y;  ai[r][2] += xv * wi.z;  ai[r][3] += xv * wi.w;
        }
    }
    const int c0 = cg * 4;
    float4 b1v = __ldg(&((const float4*)b1)[cg]);
    float4 biv = __ldg(&((const float4*)bi)[cg]);
#pragma unroll
    for (int r = 0; r < 4; r++) {
        float4 v1, vi;
        v1.x = a1[r][0] + b1v.x; v1.y = a1[r][1] + b1v.y;
        v1.z = a1[r][2] + b1v.z; v1.w = a1[r][3] + b1v.w;
        vi.x = ai[r][0] + biv.x; vi.y = ai[r][1] + biv.y;
        vi.z = ai[r][2] + biv.z; vi.w = ai[r][3] + biv.w;
        *(float4*)&h1[(n0 + r) * HH + c0] = v1;
        *(float4*)&xin[(n0 + r) * HH + c0] = vi;
    }
}

__global__ void __launch_bounds__(128) gemm_w4_kernel(
        const float* __restrict__ X, const float* __restrict__ W,
        float* __restrict__ out) {
    const int tid = threadIdx.x;
    const int r = tid >> 4;
    const int c = tid & 15;
    const int n = blockIdx.x * 8 + r;
    if (c < DOUT) {
        float acc = 0.f;
#pragma unroll 8
        for (int k = 0; k < 128; k++)
            acc += __ldg(&X[n * 128 + k]) * __ldg(&W[k * DOUT + c]);
        out[n * DOUT + c] = acc;
    }
}

// ----------------------------------------------------------------------------
// BN
// ----------------------------------------------------------------------------
__global__ void __launch_bounds__(128) bn_stats(const float* __restrict__ in,
                                                float* __restrict__ sums) {
    const int c = threadIdx.x;
    float s = 0.f, s2 = 0.f;
    for (int n = blockIdx.x; n < NN; n += gridDim.x) {
        float v = in[n * HH + c];
        s += v; s2 += v * v;
    }
    atomicAdd(&sums[c], s);
    atomicAdd(&sums[c + 128], s2);
}

__global__ void __launch_bounds__(128) bn_final(const float* __restrict__ sums,
                                                const float* __restrict__ g,
                                                const float* __restrict__ be) {
    const int c = threadIdx.x;
    float mean = sums[c] * (1.0f / NN);
    float var = sums[c + 128] * (1.0f / NN) - mean * mean;
    var = fmaxf(var, 0.f);
    float rstd = rsqrtf(var + 1e-5f);
    float sc = rstd * g[c];
    g_bnscale[c] = sc;
    g_bnshift[c] = be[c] - mean * sc;
}

__global__ void __launch_bounds__(256) apply_bn_relu(const float4* __restrict__ in,
                                                     const float4* __restrict__ add,
                                                     float4* __restrict__ out) {
    int idx = blockIdx.x * blockDim.x + threadIdx.x;
    if (idx < NN * 32) {
        int c4 = idx & 31;
        float4 sc = ((const float4*)g_bnscale)[c4];
        float4 sh = ((const float4*)g_bnshift)[c4];
        float4 v = in[idx];
        v.x = fmaxf(v.x * sc.x + sh.x, 0.f);
        v.y = fmaxf(v.y * sc.y + sh.y, 0.f);
        v.z = fmaxf(v.z * sc.z + sh.z, 0.f);
        v.w = fmaxf(v.w * sc.w + sh.w, 0.f);
        if (add) {
            float4 a = add[idx];
            v.x += a.x; v.y += a.y; v.z += a.z; v.w += a.w;
        }
        out[idx] = v;
    }
}

// ----------------------------------------------------------------------------
// GCN aggregation (128 channels, warp per node, 4-wide unroll)
// ----------------------------------------------------------------------------
__global__ void __launch_bounds__(128) gcn_agg128(const float* __restrict__ in,
                                                  const float* __restrict__ bias,
                                                  float* __restrict__ out) {
    const int warp = threadIdx.x >> 5;
    const int lane = threadIdx.x & 31;
    const int n = blockIdx.x * 4 + warp;
    const float dn = g_dinv[n];
    const int s0 = g_rowptr[n], s1 = g_rowptr[n + 1];
    const float4* in4 = (const float4*)in;
    float4 acc = __ldg(&in4[n * 32 + lane]);
    float dn2 = dn * dn;
    acc.x *= dn2; acc.y *= dn2; acc.z *= dn2; acc.w *= dn2;
    int j = s0;
    for (; j + 4 <= s1; j += 4) {
        int2 eA = __ldg(&g_epack[j]);
        int2 eB = __ldg(&g_epack[j + 1]);
        int2 eC = __ldg(&g_epack[j + 2]);
        int2 eD = __ldg(&g_epack[j + 3]);
        float4 vA = __ldg(&in4[eA.x * 32 + lane]);
        float4 vB = __ldg(&in4[eB.x * 32 + lane]);
        float4 vC = __ldg(&in4[eC.x * 32 + lane]);
        float4 vD = __ldg(&in4[eD.x * 32 + lane]);
        float cA = __int_as_float(eA.y), cB = __int_as_float(eB.y);
        float cC = __int_as_float(eC.y), cD = __int_as_float(eD.y);
        acc.x += cA * vA.x + cB * vB.x + cC * vC.x + cD * vD.x;
        acc.y += cA * vA.y + cB * vB.y + cC * vC.y + cD * vD.y;
        acc.z += cA * vA.z + cB * vB.z + cC * vC.z + cD * vD.z;
        acc.w += cA * vA.w + cB * vB.w + cC * vC.w + cD * vD.w;
    }
    for (; j < s1; j++) {
        int2 e = __ldg(&g_epack[j]);
        float4 v = __ldg(&in4[e.x * 32 + lane]);
        float c = __int_as_float(e.y);
        acc.x += c * v.x; acc.y += c * v.y; acc.z += c * v.z; acc.w += c * v.w;
    }
    float4 bv = __ldg(&((const float4*)bias)[lane]);
    acc.x += bv.x; acc.y += bv.y; acc.z += bv.z; acc.w += bv.w;
    ((float4*)out)[n * 32 + lane] = acc;
}

__global__ void __launch_bounds__(128) gcn_agg12(const float* __restrict__ in,
                                                 const float* __restrict__ bias,
                                                 float* __restrict__ out) {
    const int warp = threadIdx.x >> 5;
    const int lane = threadIdx.x & 31;
    const int n = blockIdx.x * 4 + warp;
    const float dn = g_dinv[n];
    const int s0 = g_rowptr[n], s1 = g_rowptr[n + 1];
    float acc = (lane < DOUT) ? in[n * DOUT + lane] * dn * dn : 0.f;
    int j = s0;
    for (; j + 2 <= s1; j += 2) {
        int2 eA = __ldg(&g_epack[j]);
        int2 eB = __ldg(&g_epack[j + 1]);
        float vA = (lane < DOUT) ? __ldg(&in[eA.x * DOUT + lane]) : 0.f;
        float vB = (lane < DOUT) ? __ldg(&in[eB.x * DOUT + lane]) : 0.f;
        acc += __int_as_float(eA.y) * vA + __int_as_float(eB.y) * vB;
    }
    if (j < s1) {
        int2 e = __ldg(&g_epack[j]);
        if (lane < DOUT) acc += __int_as_float(e.y) * __ldg(&in[e.x * DOUT + lane]);
    }
    if (lane < DOUT) out[n * DOUT + lane] = acc + bias[lane];
}

// ----------------------------------------------------------------------------
// GAT aggregation
// ----------------------------------------------------------------------------
__global__ void __launch_bounds__(128) gat_agg_kernel(const float* __restrict__ hg,
                                                      const float* __restrict__ bg,
                                                      float* __restrict__ out) {
    const int n = blockIdx.x;
    const int tid = threadIdx.x;
    const int lane = tid & 31;
    __shared__ float sh_m[4], sh_inv[4], sh_aself[4], sh_ad4[4];
    __shared__ float sh_ex[GAT_CAP * 4];
    __shared__ float4 sh_acc[128];
    const int s0 = g_rowptr[n];
    const int s1 = g_rowptr[n + 1];
    const int deg = s1 - s0;
    const bool cached = (deg <= GAT_CAP);
    const float4* as4 = (const float4*)g_as;
    const float4* ad4 = (const float4*)g_ad;
    if (tid < 32) {
        float4 adv = __ldg(&ad4[n]);
        float4 asv = __ldg(&as4[n]);
        float es0 = lrelu(asv.x + adv.x), es1 = lrelu(asv.y + adv.y);
        float es2 = lrelu(asv.z + adv.z), es3 = lrelu(asv.w + adv.w);
        float m0 = es0, m1 = es1, m2 = es2, m3 = es3;
        for (int j = lane; j < deg; j += 32) {
            int s = __ldg(&g_epack[s0 + j]).x;
            float4 a = __ldg(&as4[s]);
            float e0 = lrelu(a.x + adv.x), e1 = lrelu(a.y + adv.y);
            float e2 = lrelu(a.z + adv.z), e3 = lrelu(a.w + adv.w);
            if (cached) {
                sh_ex[j * 4 + 0] = e0; sh_ex[j * 4 + 1] = e1;
                sh_ex[j * 4 + 2] = e2; sh_ex[j * 4 + 3] = e3;
            }
            m0 = fmaxf(m0, e0); m1 = fmaxf(m1, e1);
            m2 = fmaxf(m2, e2); m3 = fmaxf(m3, e3);
        }
#pragma unroll
        for (int off = 16; off; off >>= 1) {
            m0 = fmaxf(m0, __shfl_xor_sync(0xffffffffu, m0, off));
            m1 = fmaxf(m1, __shfl_xor_sync(0xffffffffu, m1, off));
            m2 = fmaxf(m2, __shfl_xor_sync(0xffffffffu, m2, off));
            m3 = fmaxf(m3, __shfl_xor_sync(0xffffffffu, m3, off));
        }
        float t0 = 0.f, t1 = 0.f, t2 = 0.f, t3 = 0.f;
        if (cached) {
            for (int j = lane; j < deg; j += 32) {
                float x0 = expf(sh_ex[j * 4 + 0] - m0); sh_ex[j * 4 + 0] = x0; t0 += x0;
                float x1 = expf(sh_ex[j * 4 + 1] - m1); sh_ex[j * 4 + 1] = x1; t1 += x1;
                float x2 = expf(sh_ex[j * 4 + 2] - m2); sh_ex[j * 4 + 2] = x2; t2 += x2;
                float x3 = expf(sh_ex[j * 4 + 3] - m3); sh_ex[j * 4 + 3] = x3; t3 += x3;
            }
        } else {
            for (int j = lane; j < deg; j += 32) {
                int s = __ldg(&g_epack[s0 + j]).x;
                float4 a = __ldg(&as4[s]);
                t0 += expf(lrelu(a.x + adv.x) - m0);
                t1 += expf(lrelu(a.y + adv.y) - m1);
                t2 += expf(lrelu(a.z + adv.z) - m2);
                t3 += expf(lrelu(a.w + adv.w) - m3);
            }
        }
#pragma unroll
        for (int off = 16; off; off >>= 1) {
            t0 += __shfl_xor_sync(0xffffffffu, t0, off);
            t1 += __shfl_xor_sync(0xffffffffu, t1, off);
            t2 += __shfl_xor_sync(0xffffffffu, t2, off);
            t3 += __shfl_xor_sync(0xffffffffu, t3, off);
        }
        if (lane == 0) {
            float x0 = expf(es0 - m0), x1 = expf(es1 - m1);
            float x2 = expf(es2 - m2), x3 = expf(es3 - m3);
            t0 += x0; t1 += x1; t2 += x2; t3 += x3;
            float i0 = 1.f / t0, i1 = 1.f / t1, i2 = 1.f / t2, i3 = 1.f / t3;
            sh_m[0] = m0; sh_m[1] = m1; sh_m[2] = m2; sh_m[3] = m3;
            sh_inv[0] = i0; sh_inv[1] = i1; sh_inv[2] = i2; sh_inv[3] = i3;
            sh_aself[0] = x0 * i0; sh_aself[1] = x1 * i1;
            sh_aself[2] = x2 * i2; sh_aself[3] = x3 * i3;
            sh_ad4[0] = adv.x; sh_ad4[1] = adv.y; sh_ad4[2] = adv.z; sh_ad4[3] = adv.w;
        }
    }
    __syncthreads();
    const int eslot = tid >> 5;
    const int h = lane >> 3;
    const float4* hg4 = (const float4*)hg;
    float4 acc = make_float4(0.f, 0.f, 0.f, 0.f);
    if (cached) {
        for (int j = eslot; j < deg; j += 4) {
            int s = __ldg(&g_epack[s0 + j]).x;
            float a = sh_ex[j * 4 + h];
            float4 v = __ldg(&hg4[s * 32 + lane]);
            acc.x += a * v.x; acc.y += a * v.y; acc.z += a * v.z; acc.w += a * v.w;
        }
    } else {
        const float m = sh_m[h];
        const float ad = sh_ad4[h];
        for (int j = eslot; j < deg; j += 4) {
            int s = __ldg(&g_epack[s0 + j]).x;
            float e = lrelu(__ldg(&g_as[s * 4 + h]) + ad);
            float a = expf(e - m);
            float4 v = __ldg(&hg4[s * 32 + lane]);
            acc.x += a * v.x; acc.y += a * v.y; acc.z += a * v.z; acc.w += a * v.w;
        }
    }
    sh_acc[tid] = acc;
    __syncthreads();
    if (tid < 32) {
        float4 a0 = sh_acc[tid], a1 = sh_acc[tid + 32], a2 = sh_acc[tid + 64], a3 = sh_acc[tid + 96];
        float4 tot;
        tot.x = a0.x + a1.x + a2.x + a3.x;
        tot.y = a0.y + a1.y + a2.y + a3.y;
        tot.z = a0.z + a1.z + a2.z + a3.z;
        tot.w = a0.w + a1.w + a2.w + a3.w;
        float4 self = __ldg(&hg4[n * 32 + lane]);
        float asf = sh_aself[h], inv = sh_inv[h];
        float4 bv = __ldg(&((const float4*)bg)[lane]);
        float4 o;
        o.x = asf * self.x + inv * tot.x + bv.x;
        o.y = asf * self.y + inv * tot.y + bv.y;
        o.z = asf * self.z + inv * tot.z + bv.z;
        o.w = asf * self.w + inv * tot.w + bv.w;
        ((float4*)out)[n * 32 + lane] = o;
    }
}

// ----------------------------------------------------------------------------
// Gate + final epilogue
// ----------------------------------------------------------------------------
__global__ void __launch_bounds__(128) final_kernel(
        const float* __restrict__ t, const float* __restrict__ x,
        const float* __restrict__ Gw2, const float* __restrict__ Gb2,
        const float* __restrict__ Ws, const float* __restrict__ bs,
        float* __restrict__ out) {
    __shared__ float sG[64 * DOUT];
    __shared__ float sGb[DOUT], sWs[DOUT], sbs[DOUT];
    const int tid = threadIdx.x;
    for (int i = tid; i < 64 * DOUT; i += 128) sG[i] = Gw2[i];
    if (tid < DOUT) { sGb[tid] = Gb2[tid]; sWs[tid] = Ws[tid]; sbs[tid] = bs[tid]; }
    __syncthreads();
    if (tid < 120) {
        const int ni = tid / DOUT, c = tid % DOUT;
        const int n = blockIdx.x * 10 + ni;
        float z = sGb[c];
#pragma unroll 8
        for (int k = 0; k < 64; k++)
            z += __ldg(&t[n * 64 + k]) * sG[k * DOUT + c];
        float gate = 1.f / (1.f + expf(-z));
        float status = __ldg(&x[n * DIN + 12]);
        float flag = status < 0.5f ? 1.f : 0.f;
        float sig = (1.f - status) * sWs[c] + sbs[c];
        out[n * DOUT + c] += 2.5f * flag * gate * sig;
    }
}

// ----------------------------------------------------------------------------
// Launch
// ----------------------------------------------------------------------------
extern "C" void kernel_launch(void* const* d_in, const int* in_sizes, int n_in,
                              void* d_out, int out_size) {
    const float* x   = (const float*)d_in[0];
    const int*   ei  = (const int*)d_in[1];
    const float* ew  = (const float*)d_in[2];
    const float* W1  = (const float*)d_in[3];
    const float* b1  = (const float*)d_in[4];
    const float* g1  = (const float*)d_in[5];
    const float* be1 = (const float*)d_in[6];
    const float* Wg  = (const float*)d_in[7];
    const float* atts= (const float*)d_in[8];
    const float* attd= (const float*)d_in[9];
    const float* bg  = (const float*)d_in[10];
    const float* g2  = (const float*)d_in[11];
    const float* be2 = (const float*)d_in[12];
    const float* W3  = (const float*)d_in[13];
    const float* b3  = (const float*)d_in[14];
    const float* g3  = (const float*)d_in[15];
    const float* be3 = (const float*)d_in[16];
    const float* W4  = (const float*)d_in[17];
    const float* b4  = (const float*)d_in[18];
    const float* Wi  = (const float*)d_in[19];
    const float* bi  = (const float*)d_in[20];
    const float* Gw1 = (const float*)d_in[21];
    const float* Gb1 = (const float*)d_in[22];
    const float* Gw2 = (const float*)d_in[23];
    const float* Gb2 = (const float*)d_in[24];
    const float* Ws  = (const float*)d_in[25];
    const float* bs  = (const float*)d_in[26];
    float* out = (float*)d_out;
    const int* src = ei;
    const int* dst = ei + EE;

    float *p_h1, *p_agg, *p_x1, *p_xin, *p_hg, *p_xa, *p_h4, *p_t, *p_bnsum;
    float *p_wtg, *p_wt3, *p_wtg1;
    cudaGetSymbolAddress((void**)&p_h1, g_h1);
    cudaGetSymbolAddress((void**)&p_agg, g_agg);
    cudaGetSymbolAddress((void**)&p_x1, g_x1);
    cudaGetSymbolAddress((void**)&p_xin, g_xin);
    cudaGetSymbolAddress((void**)&p_hg, g_hg);
    cudaGetSymbolAddress((void**)&p_xa, g_xa);
    cudaGetSymbolAddress((void**)&p_h4, g_h4);
    cudaGetSymbolAddress((void**)&p_t, g_t);
    cudaGetSymbolAddress((void**)&p_bnsum, g_bnsum);
    cudaGetSymbolAddress((void**)&p_wtg, g_wtg);
    cudaGetSymbolAddress((void**)&p_wt3, g_wt3);
    cudaGetSymbolAddress((void**)&p_wtg1, g_wtg1);

    const int SMEM128 = 128 * 132 * 4;   // 67584
    const int SMEM64  = 64 * 132 * 4;    // 33792
    cudaFuncSetAttribute(mma_gemm<128, false, false, true>,
                         cudaFuncAttributeMaxDynamicSharedMemorySize, SMEM128);
    cudaFuncSetAttribute(mma_gemm<128, false, false, false>,
                         cudaFuncAttributeMaxDynamicSharedMemorySize, SMEM128);
    cudaFuncSetAttribute(mma_gemm<64, true, true, false>,
                         cudaFuncAttributeMaxDynamicSharedMemorySize, SMEM64);
    const int MGRID = (NN + 127) / 128;   // 782

    // graph preprocessing + weight transposes
    init_kernel<<<(NN + 255) / 256, 256>>>();
    count_kernel<<<(EE + 255) / 256, 256>>>(dst, ew);
    dinv_kernel<<<(NN + 255) / 256, 256>>>();
    part_kernel<<<NB, 256>>>();
    scanpart_kernel<<<1, 512>>>();
    writerow_kernel<<<NB, 256>>>();
    fill_kernel<<<(EE + 255) / 256, 256>>>(src, dst, ew);
    transpose_kernel<<<64, 256>>>(Wg, p_wtg, 128, 128);
    transpose_kernel<<<64, 256>>>(W3, p_wt3, 128, 128);
    transpose_kernel<<<32, 256>>>(Gw1, p_wtg1, 128, 64);

    // layer 1: aggregate x in 24-dim, then fused GEMM (reassociated GCN)
    agg24_kernel<<<NN / 4, 128>>>(x, p_xa);
    gemm_in_kernel<<<NN / 16, 128>>>(p_xa, x, W1, b1, Wi, bi, p_agg, p_xin);
    bn_stats<<<1024, 128>>>(p_agg, p_bnsum + 0 * 256);
    bn_final<<<1, 128>>>(p_bnsum + 0 * 256, g1, be1);
    apply_bn_relu<<<(NN * 32 + 255) / 256, 256>>>((const float4*)p_agg, nullptr, (float4*)p_x1);

    // GAT (att reductions fused into GEMM epilogue)
    mma_gemm<128, false, false, true><<<MGRID, 256, SMEM128>>>(p_x1, p_wtg, nullptr, p_hg, atts, attd);
    gat_agg_kernel<<<NN, 128>>>(p_hg, bg, p_agg);
    bn_stats<<<1024, 128>>>(p_agg, p_bnsum + 1 * 256);
    bn_final<<<1, 128>>>(p_bnsum + 1 * 256, g2, be2);
    apply_bn_relu<<<(NN * 32 + 255) / 256, 256>>>((const float4*)p_agg, (const float4*)p_xin, (float4*)p_hg);

    // layer 3: gcn + bn + relu + x1
    mma_gemm<128, false, false, false><<<MGRID, 256, SMEM128>>>(p_hg, p_wt3, nullptr, p_h1, nullptr, nullptr);
    gcn_agg128<<<NN / 4, 128>>>(p_h1, b3, p_agg);
    bn_stats<<<1024, 128>>>(p_agg, p_bnsum + 2 * 256);
    bn_final<<<1, 128>>>(p_bnsum + 2 * 256, g3, be3);
    apply_bn_relu<<<(NN * 32 + 255) / 256, 256>>>((const float4*)p_agg, (const float4*)p_x1, (float4*)p_xin);

    // output gcn + gate
    gemm_w4_kernel<<<NN / 8, 128>>>(p_xin, W4, p_h4);
    mma_gemm<64, true, true, false><<<MGRID, 256, SMEM64>>>(p_xin, p_wtg1, Gb1, p_t, nullptr, nullptr);
    gcn_agg12<<<NN / 4, 128>>>(p_h4, b4, out);
    final_kernel<<<NN / 10, 128>>>(p_t, x, Gw2, Gb2, Ws, bs, out);
}

// round 7
// speedup vs baseline: 1.9369x; 1.2249x over previous
#include <cuda_runtime.h>
#include <math.h>
#include <stdint.h>

#define NN 100000
#define EE 1600000
#define DIN 24
#define HH 128
#define DOUT 12
#define HEADS 4
#define GAT_CAP 128
#define NB 391   // ceil(NN/256)

// ----------------------------------------------------------------------------
// Scratch (device globals; no dynamic allocation allowed)
// ----------------------------------------------------------------------------
__device__ float g_h1[NN * HH];      // h3 = x2@W3
__device__ float g_agg[NN * HH];     // raw pre-BN activations per layer
__device__ float g_x1[NN * HH];      // x1 (side-written by Wg GEMM)
__device__ float g_xin[NN * HH];     // x_in_proj
__device__ float g_hg[NN * HH];      // hg
__device__ float g_xa[NN * DIN];     // 24-dim aggregated x
__device__ float g_h4[NN * DOUT];
__device__ float g_t[NN * 64];
__device__ float g_as[NN * HEADS];
__device__ float g_ad[NN * HEADS];
__device__ float g_deg[NN];
__device__ float g_dinv[NN];
__device__ int   g_cnt[NN];
__device__ int   g_cur[NN];
__device__ int   g_rowptr[NN + 1];
__device__ int2  g_epack[EE];
__device__ int   g_part[512];
__device__ int   g_poff[512];
__device__ float g_bnsum[6 * 128];
__device__ float g_bnscale[128];
__device__ float g_bnshift[128];
__device__ float g_wtg[HH * HH];     // Wg^T  [128,128] K-major
__device__ float g_wt3[HH * HH];     // W3^T
__device__ float g_wtcomb[80 * HH];  // [Gw1^T ; W4^T ; pad]

__device__ __forceinline__ float lrelu(float v) { return v > 0.f ? v : 0.2f * v; }
__device__ __forceinline__ uint32_t to_tf32(float f) {
    uint32_t t;
    asm("cvt.rna.tf32.f32 %0, %1;" : "=r"(t) : "f"(f));
    return t;
}

// ----------------------------------------------------------------------------
// Graph preprocessing
// ----------------------------------------------------------------------------
__global__ void __launch_bounds__(256) init_kernel() {
    int i = blockIdx.x * blockDim.x + threadIdx.x;
    if (i < NN) { g_deg[i] = 1.0f; g_cnt[i] = 0; g_cur[i] = 0; }
    if (i < 6 * 128) g_bnsum[i] = 0.f;
}

__global__ void __launch_bounds__(256) count_kernel(const int* __restrict__ dst,
                                                    const float* __restrict__ w) {
    int e = blockIdx.x * blockDim.x + threadIdx.x;
    if (e < EE) {
        int d = dst[e];
        atomicAdd(&g_deg[d], w[e]);
        atomicAdd(&g_cnt[d], 1);
    }
}

__global__ void __launch_bounds__(256) dinv_kernel() {
    int i = blockIdx.x * blockDim.x + threadIdx.x;
    if (i < NN) g_dinv[i] = rsqrtf(g_deg[i]);
}

__global__ void __launch_bounds__(256) part_kernel() {
    __shared__ int sw[8];
    int i = blockIdx.x * 256 + threadIdx.x;
    int v = (i < NN) ? g_cnt[i] : 0;
#pragma unroll
    for (int off = 16; off; off >>= 1) v += __shfl_down_sync(0xffffffffu, v, off);
    if ((threadIdx.x & 31) == 0) sw[threadIdx.x >> 5] = v;
    __syncthreads();
    if (threadIdx.x == 0) {
        int s = 0;
#pragma unroll
        for (int k = 0; k < 8; k++) s += sw[k];
        g_part[blockIdx.x] = s;
    }
}

__global__ void __launch_bounds__(512) scanpart_kernel() {
    __shared__ int sp[512];
    int t = threadIdx.x;
    sp[t] = (t < NB) ? g_part[t] : 0;
    __syncthreads();
    for (int off = 1; off < 512; off <<= 1) {
        int a = (t >= off) ? sp[t - off] : 0;
        __syncthreads();
        sp[t] += a;
        __syncthreads();
    }
    if (t < NB) g_poff[t] = (t == 0) ? 0 : sp[t - 1];
}

__global__ void __launch_bounds__(256) writerow_kernel() {
    __shared__ int sp[256];
    int t = threadIdx.x;
    int i = blockIdx.x * 256 + t;
    int v = (i < NN) ? g_cnt[i] : 0;
    sp[t] = v;
    __syncthreads();
    for (int off = 1; off < 256; off <<= 1) {
        int a = (t >= off) ? sp[t - off] : 0;
        __syncthreads();
        sp[t] += a;
        __syncthreads();
    }
    if (i < NN) g_rowptr[i] = sp[t] - v + g_poff[blockIdx.x];
    if (i == 0) g_rowptr[NN] = EE;
}

__global__ void __launch_bounds__(256) fill_kernel(const int* __restrict__ src,
                                                   const int* __restrict__ dst,
                                                   const float* __restrict__ w) {
    int e = blockIdx.x * blockDim.x + threadIdx.x;
    if (e < EE) {
        int d = dst[e];
        int s = src[e];
        int pos = g_rowptr[d] + atomicAdd(&g_cur[d], 1);
        float coef = w[e] * __ldg(&g_dinv[s]) * __ldg(&g_dinv[d]);
        g_epack[pos] = make_int2(s, __float_as_int(coef));
    }
}

// W[k*C+c] -> Wt[c*K+k]
__global__ void __launch_bounds__(256) transpose_kernel(const float* __restrict__ W,
                                                        float* __restrict__ Wt,
                                                        int K, int C) {
    int idx = blockIdx.x * 256 + threadIdx.x;
    if (idx < K * C) {
        int k = idx / C, c = idx % C;
        Wt[c * K + k] = W[idx];
    }
}

// Combined output B: rows 0..63 = Gw1^T, 64..75 = W4^T, 76..79 = 0
__global__ void __launch_bounds__(256) comb_transpose_kernel(const float* __restrict__ Gw1,
                                                             const float* __restrict__ W4) {
    int idx = blockIdx.x * 256 + threadIdx.x;
    if (idx < 80 * 128) {
        int r = idx >> 7, k = idx & 127;
        float v = 0.f;
        if (r < 64) v = __ldg(&Gw1[k * 64 + r]);
        else if (r < 76) v = __ldg(&W4[k * DOUT + (r - 64)]);
        g_wtcomb[idx] = v;
    }
}

// ----------------------------------------------------------------------------
// 24-channel GCN aggregation of raw x (layer-1 reassociation)
// ----------------------------------------------------------------------------
__global__ void __launch_bounds__(128) agg24_kernel(const float* __restrict__ x,
                                                    float* __restrict__ xa) {
    const int warp = threadIdx.x >> 5;
    const int lane = threadIdx.x & 31;
    const int n = blockIdx.x * 4 + warp;
    const float dn = g_dinv[n];
    const int s0 = g_rowptr[n], s1 = g_rowptr[n + 1];
    float acc = (lane < DIN) ? x[n * DIN + lane] * dn * dn : 0.f;
    int j = s0;
    for (; j + 2 <= s1; j += 2) {
        int2 eA = __ldg(&g_epack[j]);
        int2 eB = __ldg(&g_epack[j + 1]);
        float vA = (lane < DIN) ? __ldg(&x[eA.x * DIN + lane]) : 0.f;
        float vB = (lane < DIN) ? __ldg(&x[eB.x * DIN + lane]) : 0.f;
        acc += __int_as_float(eA.y) * vA + __int_as_float(eB.y) * vB;
    }
    if (j < s1) {
        int2 e = __ldg(&g_epack[j]);
        if (lane < DIN) acc += __int_as_float(e.y) * __ldg(&x[e.x * DIN + lane]);
    }
    if (lane < DIN) xa[n * DIN + lane] = acc;
}

// ----------------------------------------------------------------------------
// TF32 mma.sync GEMM with fused BN+ReLU on A (always), optional residual add,
// optional side-write of the activated A, optional att-reduction epilogue,
// optional combined (t + h4) epilogue.
//   A_eff[r,k] = relu(Araw[r,k]*bnscale[k]+bnshift[k]) [+ addp[r,k]]
// ----------------------------------------------------------------------------
template<int NC, bool ADD, bool WRITEX, bool ATT, bool COMBO>
__global__ void __launch_bounds__(256) mma_gemm(const float* __restrict__ Araw,
                                                const float* __restrict__ addp,
                                                float* __restrict__ xout,
                                                const float* __restrict__ Bt,
                                                const float* __restrict__ bias,
                                                float* __restrict__ out,
                                                float* __restrict__ out2,
                                                const float* __restrict__ att_s,
                                                const float* __restrict__ att_d) {
    extern __shared__ float smf[];
    float* sSC = smf;               // [128]
    float* sSH = smf + 128;         // [128]
    uint32_t* sW = (uint32_t*)(smf + 256);   // [NC][132] tf32 bits
    const int tid = threadIdx.x, wid = tid >> 5, lane = tid & 31;
    const int n0 = blockIdx.x * 128;

    for (int i = tid; i < 128; i += 256) { sSC[i] = g_bnscale[i]; sSH[i] = g_bnshift[i]; }
    for (int i = tid; i < NC * 128; i += 256) {
        int c = i >> 7, k = i & 127;
        sW[c * 132 + k] = to_tf32(__ldg(&Bt[i]));
    }
    __syncthreads();

    constexpr int NCH = NC / 8;
    float acc[NCH][4];
#pragma unroll
    for (int i = 0; i < NCH; i++) {
        acc[i][0] = 0.f; acc[i][1] = 0.f; acc[i][2] = 0.f; acc[i][3] = 0.f;
    }

    const int r0 = n0 + wid * 16 + (lane >> 2);
    const int r1 = r0 + 8;
    const bool v0 = r0 < NN, v1 = r1 < NN;
    const int kq = lane & 3;
    const int nq = lane >> 2;

#pragma unroll 4
    for (int k8 = 0; k8 < 128; k8 += 8) {
        int ka = k8 + kq, kb = k8 + kq + 4;
        float f0 = 0.f, f1 = 0.f, f2 = 0.f, f3 = 0.f;
        if (v0) {
            f0 = fmaxf(__ldg(&Araw[(size_t)r0 * 128 + ka]) * sSC[ka] + sSH[ka], 0.f);
            f2 = fmaxf(__ldg(&Araw[(size_t)r0 * 128 + kb]) * sSC[kb] + sSH[kb], 0.f);
            if (ADD) {
                f0 += __ldg(&addp[(size_t)r0 * 128 + ka]);
                f2 += __ldg(&addp[(size_t)r0 * 128 + kb]);
            }
            if (WRITEX) {
                xout[(size_t)r0 * 128 + ka] = f0;
                xout[(size_t)r0 * 128 + kb] = f2;
            }
        }
        if (v1) {
            f1 = fmaxf(__ldg(&Araw[(size_t)r1 * 128 + ka]) * sSC[ka] + sSH[ka], 0.f);
            f3 = fmaxf(__ldg(&Araw[(size_t)r1 * 128 + kb]) * sSC[kb] + sSH[kb], 0.f);
            if (ADD) {
                f1 += __ldg(&addp[(size_t)r1 * 128 + ka]);
                f3 += __ldg(&addp[(size_t)r1 * 128 + kb]);
            }
            if (WRITEX) {
                xout[(size_t)r1 * 128 + ka] = f1;
                xout[(size_t)r1 * 128 + kb] = f3;
            }
        }
        uint32_t a0 = to_tf32(f0), a1 = to_tf32(f1), a2 = to_tf32(f2), a3 = to_tf32(f3);
#pragma unroll
        for (int nc = 0; nc < NCH; nc++) {
            uint32_t b0 = sW[(nc * 8 + nq) * 132 + ka];
            uint32_t b1 = sW[(nc * 8 + nq) * 132 + kb];
            asm volatile(
                "mma.sync.aligned.m16n8k8.row.col.f32.tf32.tf32.f32 "
                "{%0,%1,%2,%3}, {%4,%5,%6,%7}, {%8,%9}, {%0,%1,%2,%3};"
                : "+f"(acc[nc][0]), "+f"(acc[nc][1]), "+f"(acc[nc][2]), "+f"(acc[nc][3])
                : "r"(a0), "r"(a1), "r"(a2), "r"(a3), "r"(b0), "r"(b1));
        }
    }

    const int colb = 2 * kq;
#pragma unroll
    for (int nc = 0; nc < NCH; nc++) {
        int col = nc * 8 + colb;
        float2 vlo = make_float2(acc[nc][0], acc[nc][1]);
        float2 vhi = make_float2(acc[nc][2], acc[nc][3]);
        if (COMBO) {
            if (col < 64) {
                float bx = __ldg(&bias[col]), by = __ldg(&bias[col + 1]);
                vlo.x = fmaxf(vlo.x + bx, 0.f); vlo.y = fmaxf(vlo.y + by, 0.f);
                vhi.x = fmaxf(vhi.x + bx, 0.f); vhi.y = fmaxf(vhi.y + by, 0.f);
                if (v0) *(float2*)&out[(size_t)r0 * 64 + col] = vlo;
                if (v1) *(float2*)&out[(size_t)r1 * 64 + col] = vhi;
            } else if (col < 76) {
                int c2 = col - 64;
                if (v0) *(float2*)&out2[(size_t)r0 * DOUT + c2] = vlo;
                if (v1) *(float2*)&out2[(size_t)r1 * DOUT + c2] = vhi;
            }
        } else {
            if (v0) *(float2*)&out[(size_t)r0 * NC + col] = vlo;
            if (v1) *(float2*)&out[(size_t)r1 * NC + col] = vhi;
        }
    }

    if (ATT) {
        float as0[4] = {}, ad0[4] = {}, as1[4] = {}, ad1[4] = {};
#pragma unroll
        for (int nc = 0; nc < NCH; nc++) {
            int col = nc * 8 + colb;
            float sx = __ldg(&att_s[col]), sy = __ldg(&att_s[col + 1]);
            float dx = __ldg(&att_d[col]), dy = __ldg(&att_d[col + 1]);
            int h = nc >> 2;
            as0[h] += acc[nc][0] * sx + acc[nc][1] * sy;
            ad0[h] += acc[nc][0] * dx + acc[nc][1] * dy;
            as1[h] += acc[nc][2] * sx + acc[nc][3] * sy;
            ad1[h] += acc[nc][2] * dx + acc[nc][3] * dy;
        }
#pragma unroll
        for (int h = 0; h < 4; h++) {
#pragma unroll
            for (int off = 1; off <= 2; off <<= 1) {
                as0[h] += __shfl_xor_sync(0xffffffffu, as0[h], off);
                ad0[h] += __shfl_xor_sync(0xffffffffu, ad0[h], off);
                as1[h] += __shfl_xor_sync(0xffffffffu, as1[h], off);
                ad1[h] += __shfl_xor_sync(0xffffffffu, ad1[h], off);
            }
        }
        if (kq == 0) {
#pragma unroll
            for (int h = 0; h < 4; h++) {
                if (v0) { g_as[r0 * 4 + h] = as0[h]; g_ad[r0 * 4 + h] = ad0[h]; }
                if (v1) { g_as[r1 * 4 + h] = as1[h]; g_ad[r1 * 4 + h] = ad1[h]; }
            }
        }
    }
}

// ----------------------------------------------------------------------------
// Fused input GEMM: agg1 = xa@W1 + b1, xin = x@Wi + bi
// ----------------------------------------------------------------------------
__global__ void __launch_bounds__(128) gemm_in_kernel(
        const float* __restrict__ XA, const float* __restrict__ X,
        const float* __restrict__ W1, const float* __restrict__ b1,
        const float* __restrict__ Wi, const float* __restrict__ bi,
        float* __restrict__ h1, float* __restrict__ xin) {
    const int tid = threadIdx.x;
    const int cg = tid & 31;
    const int rg = tid >> 5;
    const int n0 = blockIdx.x * 16 + rg * 4;
    float a1[4][4] = {}; float ai[4][4] = {};
    const float4* W1v = (const float4*)W1;
    const float4* Wiv = (const float4*)Wi;
#pragma unroll
    for (int k = 0; k < DIN; k++) {
        float4 w1 = __ldg(&W1v[k * 32 + cg]);
        float4 wi = __ldg(&Wiv[k * 32 + cg]);
#pragma unroll
        for (int r = 0; r < 4; r++) {
            float xav = __ldg(&XA[(n0 + r) * DIN + k]);
            float xv  = __ldg(&X[(n0 + r) * DIN + k]);
            a1[r][0] += xav * w1.x; a1[r][1] += xav * w1.y; a1[r][2] += xav * w1.z; a1[r][3] += xav * w1.w;
            ai[r][0] += xv * wi.x;  ai[r][1] += xv * wi.y;  ai[r][2] += xv * wi.z;  ai[r][3] += xv * wi.w;
        }
    }
    const int c0 = cg * 4;
    float4 b1v = __ldg(&((const float4*)b1)[cg]);
    float4 biv = __ldg(&((const float4*)bi)[cg]);
#pragma unroll
    for (int r = 0; r < 4; r++) {
        float4 v1, vi;
        v1.x = a1[r][0] + b1v.x; v1.y = a1[r][1] + b1v.y;
        v1.z = a1[r][2] + b1v.z; v1.w = a1[r][3] + b1v.w;
        vi.x = ai[r][0] + biv.x; vi.y = ai[r][1] + biv.y;
        vi.z = ai[r][2] + biv.z; vi.w = ai[r][3] + biv.w;
        *(float4*)&h1[(n0 + r) * HH + c0] = v1;
        *(float4*)&xin[(n0 + r) * HH + c0] = vi;
    }
}

// ----------------------------------------------------------------------------
// BN stats
// ----------------------------------------------------------------------------
__global__ void __launch_bounds__(128) bn_stats(const float* __restrict__ in,
                                                float* __restrict__ sums) {
    const int c = threadIdx.x;
    float s = 0.f, s2 = 0.f;
    for (int n = blockIdx.x; n < NN; n += gridDim.x) {
        float v = in[n * HH + c];
        s += v; s2 += v * v;
    }
    atomicAdd(&sums[c], s);
    atomicAdd(&sums[c + 128], s2);
}

__global__ void __launch_bounds__(128) bn_final(const float* __restrict__ sums,
                                                const float* __restrict__ g,
                                                const float* __restrict__ be) {
    const int c = threadIdx.x;
    float mean = sums[c] * (1.0f / NN);
    float var = sums[c + 128] * (1.0f / NN) - mean * mean;
    var = fmaxf(var, 0.f);
    float rstd = rsqrtf(var + 1e-5f);
    float sc = rstd * g[c];
    g_bnscale[c] = sc;
    g_bnshift[c] = be[c] - mean * sc;
}

// ----------------------------------------------------------------------------
// GCN aggregation (128 channels, warp per node)
// ----------------------------------------------------------------------------
__global__ void __launch_bounds__(128) gcn_agg128(const float* __restrict__ in,
                                                  const float* __restrict__ bias,
                                                  float* __restrict__ out) {
    const int warp = threadIdx.x >> 5;
    const int lane = threadIdx.x & 31;
    const int n = blockIdx.x * 4 + warp;
    const float dn = g_dinv[n];
    const int s0 = g_rowptr[n], s1 = g_rowptr[n + 1];
    const float4* in4 = (const float4*)in;
    float4 acc = __ldg(&in4[n * 32 + lane]);
    float dn2 = dn * dn;
    acc.x *= dn2; acc.y *= dn2; acc.z *= dn2; acc.w *= dn2;
    int j = s0;
    for (; j + 4 <= s1; j += 4) {
        int2 eA = __ldg(&g_epack[j]);
        int2 eB = __ldg(&g_epack[j + 1]);
        int2 eC = __ldg(&g_epack[j + 2]);
        int2 eD = __ldg(&g_epack[j + 3]);
        float4 vA = __ldg(&in4[eA.x * 32 + lane]);
        float4 vB = __ldg(&in4[eB.x * 32 + lane]);
        float4 vC = __ldg(&in4[eC.x * 32 + lane]);
        float4 vD = __ldg(&in4[eD.x * 32 + lane]);
        float cA = __int_as_float(eA.y), cB = __int_as_float(eB.y);
        float cC = __int_as_float(eC.y), cD = __int_as_float(eD.y);
        acc.x += cA * vA.x + cB * vB.x + cC * vC.x + cD * vD.x;
        acc.y += cA * vA.y + cB * vB.y + cC * vC.y + cD * vD.y;
        acc.z += cA * vA.z + cB * vB.z + cC * vC.z + cD * vD.z;
        acc.w += cA * vA.w + cB * vB.w + cC * vC.w + cD * vD.w;
    }
    for (; j < s1; j++) {
        int2 e = __ldg(&g_epack[j]);
        float4 v = __ldg(&in4[e.x * 32 + lane]);
        float c = __int_as_float(e.y);
        acc.x += c * v.x; acc.y += c * v.y; acc.z += c * v.z; acc.w += c * v.w;
    }
    float4 bv = __ldg(&((const float4*)bias)[lane]);
    acc.x += bv.x; acc.y += bv.y; acc.z += bv.z; acc.w += bv.w;
    ((float4*)out)[n * 32 + lane] = acc;
}

__global__ void __launch_bounds__(128) gcn_agg12(const float* __restrict__ in,
                                                 const float* __restrict__ bias,
                                                 float* __restrict__ out) {
    const int warp = threadIdx.x >> 5;
    const int lane = threadIdx.x & 31;
    const int n = blockIdx.x * 4 + warp;
    const float dn = g_dinv[n];
    const int s0 = g_rowptr[n], s1 = g_rowptr[n + 1];
    float acc = (lane < DOUT) ? in[n * DOUT + lane] * dn * dn : 0.f;
    int j = s0;
    for (; j + 2 <= s1; j += 2) {
        int2 eA = __ldg(&g_epack[j]);
        int2 eB = __ldg(&g_epack[j + 1]);
        float vA = (lane < DOUT) ? __ldg(&in[eA.x * DOUT + lane]) : 0.f;
        float vB = (lane < DOUT) ? __ldg(&in[eB.x * DOUT + lane]) : 0.f;
        acc += __int_as_float(eA.y) * vA + __int_as_float(eB.y) * vB;
    }
    if (j < s1) {
        int2 e = __ldg(&g_epack[j]);
        if (lane < DOUT) acc += __int_as_float(e.y) * __ldg(&in[e.x * DOUT + lane]);
    }
    if (lane < DOUT) out[n * DOUT + lane] = acc + bias[lane];
}

// ----------------------------------------------------------------------------
// GAT aggregation: warp per node (8 nodes per 256-thread block)
// ----------------------------------------------------------------------------
__global__ void __launch_bounds__(256) gat_agg_kernel(const float* __restrict__ hg,
                                                      const float* __restrict__ bg,
                                                      float* __restrict__ out) {
    __shared__ float sh_ex[8][GAT_CAP * 4];
    const int w = threadIdx.x >> 5;
    const int lane = threadIdx.x & 31;
    const int n = blockIdx.x * 8 + w;
    const int s0 = g_rowptr[n], s1 = g_rowptr[n + 1];
    const int deg = s1 - s0;
    const bool cached = (deg <= GAT_CAP);
    const float4* as4 = (const float4*)g_as;
    const float4* ad4 = (const float4*)g_ad;

    float4 adv = __ldg(&ad4[n]);
    float4 asv = __ldg(&as4[n]);
    float es0 = lrelu(asv.x + adv.x), es1 = lrelu(asv.y + adv.y);
    float es2 = lrelu(asv.z + adv.z), es3 = lrelu(asv.w + adv.w);
    float m0 = es0, m1 = es1, m2 = es2, m3 = es3;

    for (int j = lane; j < deg; j += 32) {
        int s = __ldg(&g_epack[s0 + j]).x;
        float4 a = __ldg(&as4[s]);
        float e0 = lrelu(a.x + adv.x), e1 = lrelu(a.y + adv.y);
        float e2 = lrelu(a.z + adv.z), e3 = lrelu(a.w + adv.w);
        if (cached) {
            sh_ex[w][j * 4 + 0] = e0; sh_ex[w][j * 4 + 1] = e1;
            sh_ex[w][j * 4 + 2] = e2; sh_ex[w][j * 4 + 3] = e3;
        }
        m0 = fmaxf(m0, e0); m1 = fmaxf(m1, e1);
        m2 = fmaxf(m2, e2); m3 = fmaxf(m3, e3);
    }
#pragma unroll
    for (int off = 16; off; off >>= 1) {
        m0 = fmaxf(m0, __shfl_xor_sync(0xffffffffu, m0, off));
        m1 = fmaxf(m1, __shfl_xor_sync(0xffffffffu, m1, off));
        m2 = fmaxf(m2, __shfl_xor_sync(0xffffffffu, m2, off));
        m3 = fmaxf(m3, __shfl_xor_sync(0xffffffffu, m3, off));
    }
    __syncwarp();

    float t0 = 0.f, t1 = 0.f, t2 = 0.f, t3 = 0.f;
    if (cached) {
        for (int j = lane; j < deg; j += 32) {
            float x0 = expf(sh_ex[w][j * 4 + 0] - m0); sh_ex[w][j * 4 + 0] = x0; t0 += x0;
            float x1 = expf(sh_ex[w][j * 4 + 1] - m1); sh_ex[w][j * 4 + 1] = x1; t1 += x1;
            float x2 = expf(sh_ex[w][j * 4 + 2] - m2); sh_ex[w][j * 4 + 2] = x2; t2 += x2;
            float x3 = expf(sh_ex[w][j * 4 + 3] - m3); sh_ex[w][j * 4 + 3] = x3; t3 += x3;
        }
    } else {
        for (int j = lane; j < deg; j += 32) {
            int s = __ldg(&g_epack[s0 + j]).x;
            float4 a = __ldg(&as4[s]);
            t0 += expf(lrelu(a.x + adv.x) - m0);
            t1 += expf(lrelu(a.y + adv.y) - m1);
            t2 += expf(lrelu(a.z + adv.z) - m2);
            t3 += expf(lrelu(a.w + adv.w) - m3);
        }
    }
#pragma unroll
    for (int off = 16; off; off >>= 1) {
        t0 += __shfl_xor_sync(0xffffffffu, t0, off);
        t1 += __shfl_xor_sync(0xffffffffu, t1, off);
        t2 += __shfl_xor_sync(0xffffffffu, t2, off);
        t3 += __shfl_xor_sync(0xffffffffu, t3, off);
    }
    __syncwarp();

    float xs0 = expf(es0 - m0), xs1 = expf(es1 - m1);
    float xs2 = expf(es2 - m2), xs3 = expf(es3 - m3);
    t0 += xs0; t1 += xs1; t2 += xs2; t3 += xs3;
    float i0 = 1.f / t0, i1 = 1.f / t1, i2 = 1.f / t2, i3 = 1.f / t3;

    const int h = lane >> 3;
    float mh    = h < 2 ? (h == 0 ? m0 : m1) : (h == 2 ? m2 : m3);
    float invh  = h < 2 ? (h == 0 ? i0 : i1) : (h == 2 ? i2 : i3);
    float aself = h < 2 ? (h == 0 ? xs0 * i0 : xs1 * i1) : (h == 2 ? xs2 * i2 : xs3 * i3);
    float adh   = h < 2 ? (h == 0 ? adv.x : adv.y) : (h == 2 ? adv.z : adv.w);

    const float4* hg4 = (const float4*)hg;
    float4 self = __ldg(&hg4[n * 32 + lane]);
    float4 acc = make_float4(self.x * aself, self.y * aself, self.z * aself, self.w * aself);
    if (cached) {
        int j = 0;
        for (; j + 2 <= deg; j += 2) {
            int sA = __ldg(&g_epack[s0 + j]).x;
            int sB = __ldg(&g_epack[s0 + j + 1]).x;
            float aA = sh_ex[w][j * 4 + h] * invh;
            float aB = sh_ex[w][(j + 1) * 4 + h] * invh;
            float4 vA = __ldg(&hg4[sA * 32 + lane]);
            float4 vB = __ldg(&hg4[sB * 32 + lane]);
            acc.x += aA * vA.x + aB * vB.x;
            acc.y += aA * vA.y + aB * vB.y;
            acc.z += aA * vA.z + aB * vB.z;
            acc.w += aA * vA.w + aB * vB.w;
        }
        if (j < deg) {
            int s = __ldg(&g_epack[s0 + j]).x;
            float a = sh_ex[w][j * 4 + h] * invh;
            float4 v = __ldg(&hg4[s * 32 + lane]);
            acc.x += a * v.x; acc.y += a * v.y; acc.z += a * v.z; acc.w += a * v.w;
        }
    } else {
        for (int j = 0; j < deg; j++) {
            int s = __ldg(&g_epack[s0 + j]).x;
            float e = lrelu(__ldg(&g_as[s * 4 + h]) + adh);
            float a = expf(e - mh) * invh;
            float4 v = __ldg(&hg4[s * 32 + lane]);
            acc.x += a * v.x; acc.y += a * v.y; acc.z += a * v.z; acc.w += a * v.w;
        }
    }
    float4 bv = __ldg(&((const float4*)bg)[lane]);
    acc.x += bv.x; acc.y += bv.y; acc.z += bv.z; acc.w += bv.w;
    ((float4*)out)[n * 32 + lane] = acc;
}

// ----------------------------------------------------------------------------
// Gate + final epilogue
// ----------------------------------------------------------------------------
__global__ void __launch_bounds__(128) final_kernel(
        const float* __restrict__ t, const float* __restrict__ x,
        const float* __restrict__ Gw2, const float* __restrict__ Gb2,
        const float* __restrict__ Ws, const float* __restrict__ bs,
        float* __restrict__ out) {
    __shared__ float sG[64 * DOUT];
    __shared__ float sGb[DOUT], sWs[DOUT], sbs[DOUT];
    const int tid = threadIdx.x;
    for (int i = tid; i < 64 * DOUT; i += 128) sG[i] = Gw2[i];
    if (tid < DOUT) { sGb[tid] = Gb2[tid]; sWs[tid] = Ws[tid]; sbs[tid] = bs[tid]; }
    __syncthreads();
    if (tid < 120) {
        const int ni = tid / DOUT, c = tid % DOUT;
        const int n = blockIdx.x * 10 + ni;
        float z = sGb[c];
#pragma unroll 8
        for (int k = 0; k < 64; k++)
            z += __ldg(&t[n * 64 + k]) * sG[k * DOUT + c];
        float gate = 1.f / (1.f + expf(-z));
        float status = __ldg(&x[n * DIN + 12]);
        float flag = status < 0.5f ? 1.f : 0.f;
        float sig = (1.f - status) * sWs[c] + sbs[c];
        out[n * DOUT + c] += 2.5f * flag * gate * sig;
    }
}

// ----------------------------------------------------------------------------
// Launch
// ----------------------------------------------------------------------------
extern "C" void kernel_launch(void* const* d_in, const int* in_sizes, int n_in,
                              void* d_out, int out_size) {
    const float* x   = (const float*)d_in[0];
    const int*   ei  = (const int*)d_in[1];
    const float* ew  = (const float*)d_in[2];
    const float* W1  = (const float*)d_in[3];
    const float* b1  = (const float*)d_in[4];
    const float* g1  = (const float*)d_in[5];
    const float* be1 = (const float*)d_in[6];
    const float* Wg  = (const float*)d_in[7];
    const float* atts= (const float*)d_in[8];
    const float* attd= (const float*)d_in[9];
    const float* bg  = (const float*)d_in[10];
    const float* g2  = (const float*)d_in[11];
    const float* be2 = (const float*)d_in[12];
    const float* W3  = (const float*)d_in[13];
    const float* b3  = (const float*)d_in[14];
    const float* g3  = (const float*)d_in[15];
    const float* be3 = (const float*)d_in[16];
    const float* W4  = (const float*)d_in[17];
    const float* b4  = (const float*)d_in[18];
    const float* Wi  = (const float*)d_in[19];
    const float* bi  = (const float*)d_in[20];
    const float* Gw1 = (const float*)d_in[21];
    const float* Gb1 = (const float*)d_in[22];
    const float* Gw2 = (const float*)d_in[23];
    const float* Gb2 = (const float*)d_in[24];
    const float* Ws  = (const float*)d_in[25];
    const float* bs  = (const float*)d_in[26];
    float* out = (float*)d_out;
    const int* src = ei;
    const int* dst = ei + EE;

    float *p_h1, *p_agg, *p_x1, *p_xin, *p_hg, *p_xa, *p_h4, *p_t, *p_bnsum;
    float *p_wtg, *p_wt3;
    cudaGetSymbolAddress((void**)&p_h1, g_h1);
    cudaGetSymbolAddress((void**)&p_agg, g_agg);
    cudaGetSymbolAddress((void**)&p_x1, g_x1);
    cudaGetSymbolAddress((void**)&p_xin, g_xin);
    cudaGetSymbolAddress((void**)&p_hg, g_hg);
    cudaGetSymbolAddress((void**)&p_xa, g_xa);
    cudaGetSymbolAddress((void**)&p_h4, g_h4);
    cudaGetSymbolAddress((void**)&p_t, g_t);
    cudaGetSymbolAddress((void**)&p_bnsum, g_bnsum);
    cudaGetSymbolAddress((void**)&p_wtg, g_wtg);
    cudaGetSymbolAddress((void**)&p_wt3, g_wt3);
    float* p_wtcomb;
    cudaGetSymbolAddress((void**)&p_wtcomb, g_wtcomb);

    const int SMEM128 = 1024 + 128 * 132 * 4;   // 68608
    const int SMEM80  = 1024 + 80 * 132 * 4;    // 43264
    cudaFuncSetAttribute(mma_gemm<128, false, true, true, false>,
                         cudaFuncAttributeMaxDynamicSharedMemorySize, SMEM128);
    cudaFuncSetAttribute(mma_gemm<128, true, false, false, false>,
                         cudaFuncAttributeMaxDynamicSharedMemorySize, SMEM128);
    cudaFuncSetAttribute(mma_gemm<80, true, false, false, true>,
                         cudaFuncAttributeMaxDynamicSharedMemorySize, SMEM80);
    const int MGRID = (NN + 127) / 128;   // 782

    // graph preprocessing + weight prep
    init_kernel<<<(NN + 255) / 256, 256>>>();
    count_kernel<<<(EE + 255) / 256, 256>>>(dst, ew);
    dinv_kernel<<<(NN + 255) / 256, 256>>>();
    part_kernel<<<NB, 256>>>();
    scanpart_kernel<<<1, 512>>>();
    writerow_kernel<<<NB, 256>>>();
    fill_kernel<<<(EE + 255) / 256, 256>>>(src, dst, ew);
    transpose_kernel<<<64, 256>>>(Wg, p_wtg, 128, 128);
    transpose_kernel<<<64, 256>>>(W3, p_wt3, 128, 128);
    comb_transpose_kernel<<<40, 256>>>(Gw1, W4);

    // layer 1: aggregate x in 24-dim, fused GEMM -> agg1 (raw), xin
    agg24_kernel<<<NN / 4, 128>>>(x, p_xa);
    gemm_in_kernel<<<NN / 16, 128>>>(p_xa, x, W1, b1, Wi, bi, p_agg, p_xin);
    bn_stats<<<1024, 128>>>(p_agg, p_bnsum + 0 * 256);
    bn_final<<<1, 128>>>(p_bnsum + 0 * 256, g1, be1);

    // GAT: Wg GEMM with fused BN1+ReLU on A, side-write x1, fused att reduce
    mma_gemm<128, false, true, true, false><<<MGRID, 256, SMEM128>>>(
        p_agg, nullptr, p_x1, p_wtg, nullptr, p_hg, nullptr, atts, attd);
    gat_agg_kernel<<<NN / 8, 256>>>(p_hg, bg, p_agg);
    bn_stats<<<1024, 128>>>(p_agg, p_bnsum + 1 * 256);
    bn_final<<<1, 128>>>(p_bnsum + 1 * 256, g2, be2);

    // layer 3: W3 GEMM with fused BN2+ReLU + xin residual on A
    mma_gemm<128, true, false, false, false><<<MGRID, 256, SMEM128>>>(
        p_agg, p_xin, nullptr, p_wt3, nullptr, p_h1, nullptr, nullptr, nullptr);
    gcn_agg128<<<NN / 4, 128>>>(p_h1, b3, p_agg);
    bn_stats<<<1024, 128>>>(p_agg, p_bnsum + 2 * 256);
    bn_final<<<1, 128>>>(p_bnsum + 2 * 256, g3, be3);

    // output: combined (Gw1 gate + W4) GEMM with fused BN3+ReLU + x1 residual
    mma_gemm<80, true, false, false, true><<<MGRID, 256, SMEM80>>>(
        p_agg, p_x1, nullptr, p_wtcomb, Gb1, p_t, p_h4, nullptr, nullptr);
    gcn_agg12<<<NN / 4, 128>>>(p_h4, b4, out);
    final_kernel<<<NN / 10, 128>>>(p_t, x, Gw2, Gb2, Ws, bs, out);
}

// round 8
// speedup vs baseline: 2.2809x; 1.1776x over previous
#include <cuda_runtime.h>
#include <math.h>
#include <stdint.h>

#define NN 100000
#define EE 1600000
#define DIN 24
#define HH 128
#define DOUT 12
#define HEADS 4
#define GAT_CAP 128
#define NB 391   // ceil(NN/256)

// ----------------------------------------------------------------------------
// Scratch (device globals; no dynamic allocation allowed)
// ----------------------------------------------------------------------------
__device__ float g_h1[NN * HH];      // h3 = x2@W3
__device__ float g_agg[NN * HH];     // raw pre-BN activations per layer
__device__ float g_x1[NN * HH];      // x1 (side-written by Wg GEMM)
__device__ float g_xin[NN * HH];     // x_in_proj
__device__ float g_hg[NN * HH];      // hg
__device__ float g_xa[NN * DIN];     // 24-dim aggregated x
__device__ float g_h4[NN * DOUT];
__device__ float g_t[NN * 64];
__device__ float g_as[NN * HEADS];
__device__ float g_ad[NN * HEADS];
__device__ float g_deg[NN];
__device__ float g_dinv[NN];
__device__ int   g_cnt[NN];
__device__ int   g_cur[NN];
__device__ int   g_rowptr[NN + 1];
__device__ int2  g_epack[EE];
__device__ int   g_part[512];
__device__ int   g_poff[512];
__device__ float g_bnpart[64][256];  // bucketed BN partials: [b][c]=sum, [b][c+128]=sumsq
__device__ float g_bnscale[128];
__device__ float g_bnshift[128];
__device__ float g_wtg[HH * HH];     // Wg^T  [128,128] K-major
__device__ float g_wt3[HH * HH];     // W3^T
__device__ float g_wtcomb[80 * HH];  // [Gw1^T ; W4^T ; pad]

__device__ __forceinline__ float lrelu(float v) { return v > 0.f ? v : 0.2f * v; }
__device__ __forceinline__ uint32_t to_tf32(float f) {
    uint32_t t;
    asm("cvt.rna.tf32.f32 %0, %1;" : "=r"(t) : "f"(f));
    return t;
}

// ----------------------------------------------------------------------------
// Graph preprocessing
// ----------------------------------------------------------------------------
__global__ void __launch_bounds__(256) init_kernel() {
    int i = blockIdx.x * blockDim.x + threadIdx.x;
    if (i < NN) { g_deg[i] = 1.0f; g_cnt[i] = 0; g_cur[i] = 0; }
    if (i < 64 * 256) ((float*)g_bnpart)[i] = 0.f;
}

__global__ void __launch_bounds__(256) count_kernel(const int* __restrict__ dst,
                                                    const float* __restrict__ w) {
    int e = blockIdx.x * blockDim.x + threadIdx.x;
    if (e < EE) {
        int d = dst[e];
        atomicAdd(&g_deg[d], w[e]);
        atomicAdd(&g_cnt[d], 1);
    }
}

__global__ void __launch_bounds__(256) dinv_kernel() {
    int i = blockIdx.x * blockDim.x + threadIdx.x;
    if (i < NN) g_dinv[i] = rsqrtf(g_deg[i]);
}

__global__ void __launch_bounds__(256) part_kernel() {
    __shared__ int sw[8];
    int i = blockIdx.x * 256 + threadIdx.x;
    int v = (i < NN) ? g_cnt[i] : 0;
#pragma unroll
    for (int off = 16; off; off >>= 1) v += __shfl_down_sync(0xffffffffu, v, off);
    if ((threadIdx.x & 31) == 0) sw[threadIdx.x >> 5] = v;
    __syncthreads();
    if (threadIdx.x == 0) {
        int s = 0;
#pragma unroll
        for (int k = 0; k < 8; k++) s += sw[k];
        g_part[blockIdx.x] = s;
    }
}

__global__ void __launch_bounds__(512) scanpart_kernel() {
    __shared__ int sp[512];
    int t = threadIdx.x;
    sp[t] = (t < NB) ? g_part[t] : 0;
    __syncthreads();
    for (int off = 1; off < 512; off <<= 1) {
        int a = (t >= off) ? sp[t - off] : 0;
        __syncthreads();
        sp[t] += a;
        __syncthreads();
    }
    if (t < NB) g_poff[t] = (t == 0) ? 0 : sp[t - 1];
}

__global__ void __launch_bounds__(256) writerow_kernel() {
    __shared__ int sp[256];
    int t = threadIdx.x;
    int i = blockIdx.x * 256 + t;
    int v = (i < NN) ? g_cnt[i] : 0;
    sp[t] = v;
    __syncthreads();
    for (int off = 1; off < 256; off <<= 1) {
        int a = (t >= off) ? sp[t - off] : 0;
        __syncthreads();
        sp[t] += a;
        __syncthreads();
    }
    if (i < NN) g_rowptr[i] = sp[t] - v + g_poff[blockIdx.x];
    if (i == 0) g_rowptr[NN] = EE;
}

__global__ void __launch_bounds__(256) fill_kernel(const int* __restrict__ src,
                                                   const int* __restrict__ dst,
                                                   const float* __restrict__ w) {
    int e = blockIdx.x * blockDim.x + threadIdx.x;
    if (e < EE) {
        int d = dst[e];
        int s = src[e];
        int pos = g_rowptr[d] + atomicAdd(&g_cur[d], 1);
        float coef = w[e] * __ldg(&g_dinv[s]) * __ldg(&g_dinv[d]);
        g_epack[pos] = make_int2(s, __float_as_int(coef));
    }
}

// W[k*C+c] -> Wt[c*K+k]
__global__ void __launch_bounds__(256) transpose_kernel(const float* __restrict__ W,
                                                        float* __restrict__ Wt,
                                                        int K, int C) {
    int idx = blockIdx.x * 256 + threadIdx.x;
    if (idx < K * C) {
        int k = idx / C, c = idx % C;
        Wt[c * K + k] = W[idx];
    }
}

__global__ void __launch_bounds__(256) comb_transpose_kernel(const float* __restrict__ Gw1,
                                                             const float* __restrict__ W4) {
    int idx = blockIdx.x * 256 + threadIdx.x;
    if (idx < 80 * 128) {
        int r = idx >> 7, k = idx & 127;
        float v = 0.f;
        if (r < 64) v = __ldg(&Gw1[k * 64 + r]);
        else if (r < 76) v = __ldg(&W4[k * DOUT + (r - 64)]);
        g_wtcomb[idx] = v;
    }
}

// ----------------------------------------------------------------------------
// BN finalize: reduce 64 buckets, compute scale/shift, re-zero buckets
// ----------------------------------------------------------------------------
__global__ void __launch_bounds__(128) bn_final2(const float* __restrict__ g,
                                                 const float* __restrict__ be) {
    const int c = threadIdx.x;
    float s = 0.f, s2 = 0.f;
#pragma unroll 8
    for (int b = 0; b < 64; b++) {
        s += g_bnpart[b][c];
        s2 += g_bnpart[b][c + 128];
        g_bnpart[b][c] = 0.f;
        g_bnpart[b][c + 128] = 0.f;
    }
    float mean = s * (1.0f / NN);
    float var = s2 * (1.0f / NN) - mean * mean;
    var = fmaxf(var, 0.f);
    float rstd = rsqrtf(var + 1e-5f);
    float sc = rstd * g[c];
    g_bnscale[c] = sc;
    g_bnshift[c] = be[c] - mean * sc;
}

// ----------------------------------------------------------------------------
// 24-channel GCN aggregation of raw x (layer-1 reassociation)
// ----------------------------------------------------------------------------
__global__ void __launch_bounds__(128) agg24_kernel(const float* __restrict__ x,
                                                    float* __restrict__ xa) {
    const int warp = threadIdx.x >> 5;
    const int lane = threadIdx.x & 31;
    const int n = blockIdx.x * 4 + warp;
    const float dn = g_dinv[n];
    const int s0 = g_rowptr[n], s1 = g_rowptr[n + 1];
    float acc = (lane < DIN) ? x[n * DIN + lane] * dn * dn : 0.f;
    int j = s0;
    for (; j + 4 <= s1; j += 4) {
        int2 eA = __ldg(&g_epack[j]);
        int2 eB = __ldg(&g_epack[j + 1]);
        int2 eC = __ldg(&g_epack[j + 2]);
        int2 eD = __ldg(&g_epack[j + 3]);
        float vA = (lane < DIN) ? __ldg(&x[eA.x * DIN + lane]) : 0.f;
        float vB = (lane < DIN) ? __ldg(&x[eB.x * DIN + lane]) : 0.f;
        float vC = (lane < DIN) ? __ldg(&x[eC.x * DIN + lane]) : 0.f;
        float vD = (lane < DIN) ? __ldg(&x[eD.x * DIN + lane]) : 0.f;
        acc += __int_as_float(eA.y) * vA + __int_as_float(eB.y) * vB
             + __int_as_float(eC.y) * vC + __int_as_float(eD.y) * vD;
    }
    for (; j < s1; j++) {
        int2 e = __ldg(&g_epack[j]);
        if (lane < DIN) acc += __int_as_float(e.y) * __ldg(&x[e.x * DIN + lane]);
    }
    if (lane < DIN) xa[n * DIN + lane] = acc;
}

// ----------------------------------------------------------------------------
// TF32 mma.sync GEMM with fused BN+ReLU on A, optional residual add,
// optional side-write of the activated A, optional att epilogue, combo epilogue
// ----------------------------------------------------------------------------
template<int NC, bool ADD, bool WRITEX, bool ATT, bool COMBO>
__global__ void __launch_bounds__(256) mma_gemm(const float* __restrict__ Araw,
                                                const float* __restrict__ addp,
                                                float* __restrict__ xout,
                                                const float* __restrict__ Bt,
                                                const float* __restrict__ bias,
                                                float* __restrict__ out,
                                                float* __restrict__ out2,
                                                const float* __restrict__ att_s,
                                                const float* __restrict__ att_d) {
    extern __shared__ float smf[];
    float* sSC = smf;               // [128]
    float* sSH = smf + 128;         // [128]
    uint32_t* sW = (uint32_t*)(smf + 256);   // [NC][132] tf32 bits
    const int tid = threadIdx.x, wid = tid >> 5, lane = tid & 31;
    const int n0 = blockIdx.x * 128;

    for (int i = tid; i < 128; i += 256) { sSC[i] = g_bnscale[i]; sSH[i] = g_bnshift[i]; }
    for (int i = tid; i < NC * 128; i += 256) {
        int c = i >> 7, k = i & 127;
        sW[c * 132 + k] = to_tf32(__ldg(&Bt[i]));
    }
    __syncthreads();

    constexpr int NCH = NC / 8;
    float acc[NCH][4];
#pragma unroll
    for (int i = 0; i < NCH; i++) {
        acc[i][0] = 0.f; acc[i][1] = 0.f; acc[i][2] = 0.f; acc[i][3] = 0.f;
    }

    const int r0 = n0 + wid * 16 + (lane >> 2);
    const int r1 = r0 + 8;
    const bool v0 = r0 < NN, v1 = r1 < NN;
    const int kq = lane & 3;
    const int nq = lane >> 2;

#pragma unroll 4
    for (int k8 = 0; k8 < 128; k8 += 8) {
        int ka = k8 + kq, kb = k8 + kq + 4;
        float f0 = 0.f, f1 = 0.f, f2 = 0.f, f3 = 0.f;
        if (v0) {
            f0 = fmaxf(__ldg(&Araw[(size_t)r0 * 128 + ka]) * sSC[ka] + sSH[ka], 0.f);
            f2 = fmaxf(__ldg(&Araw[(size_t)r0 * 128 + kb]) * sSC[kb] + sSH[kb], 0.f);
            if (ADD) {
                f0 += __ldg(&addp[(size_t)r0 * 128 + ka]);
                f2 += __ldg(&addp[(size_t)r0 * 128 + kb]);
            }
            if (WRITEX) {
                xout[(size_t)r0 * 128 + ka] = f0;
                xout[(size_t)r0 * 128 + kb] = f2;
            }
        }
        if (v1) {
            f1 = fmaxf(__ldg(&Araw[(size_t)r1 * 128 + ka]) * sSC[ka] + sSH[ka], 0.f);
            f3 = fmaxf(__ldg(&Araw[(size_t)r1 * 128 + kb]) * sSC[kb] + sSH[kb], 0.f);
            if (ADD) {
                f1 += __ldg(&addp[(size_t)r1 * 128 + ka]);
                f3 += __ldg(&addp[(size_t)r1 * 128 + kb]);
            }
            if (WRITEX) {
                xout[(size_t)r1 * 128 + ka] = f1;
                xout[(size_t)r1 * 128 + kb] = f3;
            }
        }
        uint32_t a0 = to_tf32(f0), a1 = to_tf32(f1), a2 = to_tf32(f2), a3 = to_tf32(f3);
#pragma unroll
        for (int nc = 0; nc < NCH; nc++) {
            uint32_t b0 = sW[(nc * 8 + nq) * 132 + ka];
            uint32_t b1 = sW[(nc * 8 + nq) * 132 + kb];
            asm volatile(
                "mma.sync.aligned.m16n8k8.row.col.f32.tf32.tf32.f32 "
                "{%0,%1,%2,%3}, {%4,%5,%6,%7}, {%8,%9}, {%0,%1,%2,%3};"
                : "+f"(acc[nc][0]), "+f"(acc[nc][1]), "+f"(acc[nc][2]), "+f"(acc[nc][3])
                : "r"(a0), "r"(a1), "r"(a2), "r"(a3), "r"(b0), "r"(b1));
        }
    }

    const int colb = 2 * kq;
#pragma unroll
    for (int nc = 0; nc < NCH; nc++) {
        int col = nc * 8 + colb;
        float2 vlo = make_float2(acc[nc][0], acc[nc][1]);
        float2 vhi = make_float2(acc[nc][2], acc[nc][3]);
        if (COMBO) {
            if (col < 64) {
                float bx = __ldg(&bias[col]), by = __ldg(&bias[col + 1]);
                vlo.x = fmaxf(vlo.x + bx, 0.f); vlo.y = fmaxf(vlo.y + by, 0.f);
                vhi.x = fmaxf(vhi.x + bx, 0.f); vhi.y = fmaxf(vhi.y + by, 0.f);
                if (v0) *(float2*)&out[(size_t)r0 * 64 + col] = vlo;
                if (v1) *(float2*)&out[(size_t)r1 * 64 + col] = vhi;
            } else if (col < 76) {
                int c2 = col - 64;
                if (v0) *(float2*)&out2[(size_t)r0 * DOUT + c2] = vlo;
                if (v1) *(float2*)&out2[(size_t)r1 * DOUT + c2] = vhi;
            }
        } else {
            if (v0) *(float2*)&out[(size_t)r0 * NC + col] = vlo;
            if (v1) *(float2*)&out[(size_t)r1 * NC + col] = vhi;
        }
    }

    if (ATT) {
        float as0[4] = {}, ad0[4] = {}, as1[4] = {}, ad1[4] = {};
#pragma unroll
        for (int nc = 0; nc < NCH; nc++) {
            int col = nc * 8 + colb;
            float sx = __ldg(&att_s[col]), sy = __ldg(&att_s[col + 1]);
            float dx = __ldg(&att_d[col]), dy = __ldg(&att_d[col + 1]);
            int h = nc >> 2;
            as0[h] += acc[nc][0] * sx + acc[nc][1] * sy;
            ad0[h] += acc[nc][0] * dx + acc[nc][1] * dy;
            as1[h] += acc[nc][2] * sx + acc[nc][3] * sy;
            ad1[h] += acc[nc][2] * dx + acc[nc][3] * dy;
        }
#pragma unroll
        for (int h = 0; h < 4; h++) {
#pragma unroll
            for (int off = 1; off <= 2; off <<= 1) {
                as0[h] += __shfl_xor_sync(0xffffffffu, as0[h], off);
                ad0[h] += __shfl_xor_sync(0xffffffffu, ad0[h], off);
                as1[h] += __shfl_xor_sync(0xffffffffu, as1[h], off);
                ad1[h] += __shfl_xor_sync(0xffffffffu, ad1[h], off);
            }
        }
        if (kq == 0) {
#pragma unroll
            for (int h = 0; h < 4; h++) {
                if (v0) { g_as[r0 * 4 + h] = as0[h]; g_ad[r0 * 4 + h] = ad0[h]; }
                if (v1) { g_as[r1 * 4 + h] = as1[h]; g_ad[r1 * 4 + h] = ad1[h]; }
            }
        }
    }
}

// ----------------------------------------------------------------------------
// Fused input GEMM: agg1 = xa@W1 + b1, xin = x@Wi + bi, + fused BN1 partials
// ----------------------------------------------------------------------------
__global__ void __launch_bounds__(128) gemm_in_kernel(
        const float* __restrict__ XA, const float* __restrict__ X,
        const float* __restrict__ W1, const float* __restrict__ b1,
        const float* __restrict__ Wi, const float* __restrict__ bi,
        float* __restrict__ h1, float* __restrict__ xin) {
    __shared__ float sS[4][128], sQ[4][128];
    const int tid = threadIdx.x;
    const int cg = tid & 31;
    const int rg = tid >> 5;
    const int n0 = blockIdx.x * 16 + rg * 4;
    float a1[4][4] = {}; float ai[4][4] = {};
    const float4* W1v = (const float4*)W1;
    const float4* Wiv = (const float4*)Wi;
#pragma unroll
    for (int k = 0; k < DIN; k++) {
        float4 w1 = __ldg(&W1v[k * 32 + cg]);
        float4 wi = __ldg(&Wiv[k * 32 + cg]);
#pragma unroll
        for (int r = 0; r < 4; r++) {
            float xav = __ldg(&XA[(n0 + r) * DIN + k]);
            float xv  = __ldg(&X[(n0 + r) * DIN + k]);
            a1[r][0] += xav * w1.x; a1[r][1] += xav * w1.y; a1[r][2] += xav * w1.z; a1[r][3] += xav * w1.w;
            ai[r][0] += xv * wi.x;  ai[r][1] += xv * wi.y;  ai[r][2] += xv * wi.z;  ai[r][3] += xv * wi.w;
        }
    }
    const int c0 = cg * 4;
    float4 b1v = __ldg(&((const float4*)b1)[cg]);
    float4 biv = __ldg(&((const float4*)bi)[cg]);
    float s4[4] = {}, q4[4] = {};
#pragma unroll
    for (int r = 0; r < 4; r++) {
        float4 v1, vi;
        v1.x = a1[r][0] + b1v.x; v1.y = a1[r][1] + b1v.y;
        v1.z = a1[r][2] + b1v.z; v1.w = a1[r][3] + b1v.w;
        vi.x = ai[r][0] + biv.x; vi.y = ai[r][1] + biv.y;
        vi.z = ai[r][2] + biv.z; vi.w = ai[r][3] + biv.w;
        s4[0] += v1.x; q4[0] += v1.x * v1.x;
        s4[1] += v1.y; q4[1] += v1.y * v1.y;
        s4[2] += v1.z; q4[2] += v1.z * v1.z;
        s4[3] += v1.w; q4[3] += v1.w * v1.w;
        *(float4*)&h1[(n0 + r) * HH + c0] = v1;
        *(float4*)&xin[(n0 + r) * HH + c0] = vi;
    }
#pragma unroll
    for (int i = 0; i < 4; i++) { sS[rg][c0 + i] = s4[i]; sQ[rg][c0 + i] = q4[i]; }
    __syncthreads();
    const int b = blockIdx.x & 63;
    float ts = sS[0][tid] + sS[1][tid] + sS[2][tid] + sS[3][tid];
    float tq = sQ[0][tid] + sQ[1][tid] + sQ[2][tid] + sQ[3][tid];
    atomicAdd(&g_bnpart[b][tid], ts);
    atomicAdd(&g_bnpart[b][tid + 128], tq);
}

// ----------------------------------------------------------------------------
// GCN aggregation (128 channels, warp per node, 8-wide) + fused BN3 partials
// ----------------------------------------------------------------------------
__global__ void __launch_bounds__(128) gcn_agg128(const float* __restrict__ in,
                                                  const float* __restrict__ bias,
                                                  float* __restrict__ out) {
    __shared__ float sS[4][128], sQ[4][128];
    const int warp = threadIdx.x >> 5;
    const int lane = threadIdx.x & 31;
    const int n = blockIdx.x * 4 + warp;
    const float dn = g_dinv[n];
    const int s0 = g_rowptr[n], s1 = g_rowptr[n + 1];
    const float4* in4 = (const float4*)in;
    float4 acc = __ldg(&in4[n * 32 + lane]);
    float dn2 = dn * dn;
    acc.x *= dn2; acc.y *= dn2; acc.z *= dn2; acc.w *= dn2;
    int j = s0;
    for (; j + 8 <= s1; j += 8) {
        int2 e[8];
        float4 v[8];
#pragma unroll
        for (int q = 0; q < 8; q++) e[q] = __ldg(&g_epack[j + q]);
#pragma unroll
        for (int q = 0; q < 8; q++) v[q] = __ldg(&in4[e[q].x * 32 + lane]);
#pragma unroll
        for (int q = 0; q < 8; q++) {
            float c = __int_as_float(e[q].y);
            acc.x += c * v[q].x; acc.y += c * v[q].y;
            acc.z += c * v[q].z; acc.w += c * v[q].w;
        }
    }
    for (; j < s1; j++) {
        int2 e = __ldg(&g_epack[j]);
        float4 v = __ldg(&in4[e.x * 32 + lane]);
        float c = __int_as_float(e.y);
        acc.x += c * v.x; acc.y += c * v.y; acc.z += c * v.z; acc.w += c * v.w;
    }
    float4 bv = __ldg(&((const float4*)bias)[lane]);
    acc.x += bv.x; acc.y += bv.y; acc.z += bv.z; acc.w += bv.w;
    ((float4*)out)[n * 32 + lane] = acc;
    sS[warp][lane * 4 + 0] = acc.x; sQ[warp][lane * 4 + 0] = acc.x * acc.x;
    sS[warp][lane * 4 + 1] = acc.y; sQ[warp][lane * 4 + 1] = acc.y * acc.y;
    sS[warp][lane * 4 + 2] = acc.z; sQ[warp][lane * 4 + 2] = acc.z * acc.z;
    sS[warp][lane * 4 + 3] = acc.w; sQ[warp][lane * 4 + 3] = acc.w * acc.w;
    __syncthreads();
    const int tid = threadIdx.x;
    const int b = blockIdx.x & 63;
    float ts = sS[0][tid] + sS[1][tid] + sS[2][tid] + sS[3][tid];
    float tq = sQ[0][tid] + sQ[1][tid] + sQ[2][tid] + sQ[3][tid];
    atomicAdd(&g_bnpart[b][tid], ts);
    atomicAdd(&g_bnpart[b][tid + 128], tq);
}

__global__ void __launch_bounds__(128) gcn_agg12(const float* __restrict__ in,
                                                 const float* __restrict__ bias,
                                                 float* __restrict__ out) {
    const int warp = threadIdx.x >> 5;
    const int lane = threadIdx.x & 31;
    const int n = blockIdx.x * 4 + warp;
    const float dn = g_dinv[n];
    const int s0 = g_rowptr[n], s1 = g_rowptr[n + 1];
    float acc = (lane < DOUT) ? in[n * DOUT + lane] * dn * dn : 0.f;
    int j = s0;
    for (; j + 2 <= s1; j += 2) {
        int2 eA = __ldg(&g_epack[j]);
        int2 eB = __ldg(&g_epack[j + 1]);
        float vA = (lane < DOUT) ? __ldg(&in[eA.x * DOUT + lane]) : 0.f;
        float vB = (lane < DOUT) ? __ldg(&in[eB.x * DOUT + lane]) : 0.f;
        acc += __int_as_float(eA.y) * vA + __int_as_float(eB.y) * vB;
    }
    if (j < s1) {
        int2 e = __ldg(&g_epack[j]);
        if (lane < DOUT) acc += __int_as_float(e.y) * __ldg(&in[e.x * DOUT + lane]);
    }
    if (lane < DOUT) out[n * DOUT + lane] = acc + bias[lane];
}

// ----------------------------------------------------------------------------
// GAT aggregation: warp per node (8/block) + fused BN2 partials
// ----------------------------------------------------------------------------
__global__ void __launch_bounds__(256) gat_agg_kernel(const float* __restrict__ hg,
                                                      const float* __restrict__ bg,
                                                      float* __restrict__ out) {
    __shared__ float sh_ex[8][GAT_CAP * 4];
    __shared__ float sS[8][128], sQ[8][128];
    const int w = threadIdx.x >> 5;
    const int lane = threadIdx.x & 31;
    const int n = blockIdx.x * 8 + w;
    const int s0 = g_rowptr[n], s1 = g_rowptr[n + 1];
    const int deg = s1 - s0;
    const bool cached = (deg <= GAT_CAP);
    const float4* as4 = (const float4*)g_as;
    const float4* ad4 = (const float4*)g_ad;

    float4 adv = __ldg(&ad4[n]);
    float4 asv = __ldg(&as4[n]);
    float es0 = lrelu(asv.x + adv.x), es1 = lrelu(asv.y + adv.y);
    float es2 = lrelu(asv.z + adv.z), es3 = lrelu(asv.w + adv.w);
    float m0 = es0, m1 = es1, m2 = es2, m3 = es3;

    for (int j = lane; j < deg; j += 32) {
        int s = __ldg(&g_epack[s0 + j]).x;
        float4 a = __ldg(&as4[s]);
        float e0 = lrelu(a.x + adv.x), e1 = lrelu(a.y + adv.y);
        float e2 = lrelu(a.z + adv.z), e3 = lrelu(a.w + adv.w);
        if (cached) {
            sh_ex[w][j * 4 + 0] = e0; sh_ex[w][j * 4 + 1] = e1;
            sh_ex[w][j * 4 + 2] = e2; sh_ex[w][j * 4 + 3] = e3;
        }
        m0 = fmaxf(m0, e0); m1 = fmaxf(m1, e1);
        m2 = fmaxf(m2, e2); m3 = fmaxf(m3, e3);
    }
#pragma unroll
    for (int off = 16; off; off >>= 1) {
        m0 = fmaxf(m0, __shfl_xor_sync(0xffffffffu, m0, off));
        m1 = fmaxf(m1, __shfl_xor_sync(0xffffffffu, m1, off));
        m2 = fmaxf(m2, __shfl_xor_sync(0xffffffffu, m2, off));
        m3 = fmaxf(m3, __shfl_xor_sync(0xffffffffu, m3, off));
    }
    __syncwarp();

    float t0 = 0.f, t1 = 0.f, t2 = 0.f, t3 = 0.f;
    if (cached) {
        for (int j = lane; j < deg; j += 32) {
            float x0 = expf(sh_ex[w][j * 4 + 0] - m0); sh_ex[w][j * 4 + 0] = x0; t0 += x0;
            float x1 = expf(sh_ex[w][j * 4 + 1] - m1); sh_ex[w][j * 4 + 1] = x1; t1 += x1;
            float x2 = expf(sh_ex[w][j * 4 + 2] - m2); sh_ex[w][j * 4 + 2] = x2; t2 += x2;
            float x3 = expf(sh_ex[w][j * 4 + 3] - m3); sh_ex[w][j * 4 + 3] = x3; t3 += x3;
        }
    } else {
        for (int j = lane; j < deg; j += 32) {
            int s = __ldg(&g_epack[s0 + j]).x;
            float4 a = __ldg(&as4[s]);
            t0 += expf(lrelu(a.x + adv.x) - m0);
            t1 += expf(lrelu(a.y + adv.y) - m1);
            t2 += expf(lrelu(a.z + adv.z) - m2);
            t3 += expf(lrelu(a.w + adv.w) - m3);
        }
    }
#pragma unroll
    for (int off = 16; off; off >>= 1) {
        t0 += __shfl_xor_sync(0xffffffffu, t0, off);
        t1 += __shfl_xor_sync(0xffffffffu, t1, off);
        t2 += __shfl_xor_sync(0xffffffffu, t2, off);
        t3 += __shfl_xor_sync(0xffffffffu, t3, off);
    }
    __syncwarp();

    float xs0 = expf(es0 - m0), xs1 = expf(es1 - m1);
    float xs2 = expf(es2 - m2), xs3 = expf(es3 - m3);
    t0 += xs0; t1 += xs1; t2 += xs2; t3 += xs3;
    float i0 = 1.f / t0, i1 = 1.f / t1, i2 = 1.f / t2, i3 = 1.f / t3;

    const int h = lane >> 3;
    float mh    = h < 2 ? (h == 0 ? m0 : m1) : (h == 2 ? m2 : m3);
    float invh  = h < 2 ? (h == 0 ? i0 : i1) : (h == 2 ? i2 : i3);
    float aself = h < 2 ? (h == 0 ? xs0 * i0 : xs1 * i1) : (h == 2 ? xs2 * i2 : xs3 * i3);
    float adh   = h < 2 ? (h == 0 ? adv.x : adv.y) : (h == 2 ? adv.z : adv.w);

    const float4* hg4 = (const float4*)hg;
    float4 self = __ldg(&hg4[n * 32 + lane]);
    float4 acc = make_float4(self.x * aself, self.y * aself, self.z * aself, self.w * aself);
    if (cached) {
        int j = 0;
        for (; j + 4 <= deg; j += 4) {
            int sA = __ldg(&g_epack[s0 + j]).x;
            int sB = __ldg(&g_epack[s0 + j + 1]).x;
            int sC = __ldg(&g_epack[s0 + j + 2]).x;
            int sD = __ldg(&g_epack[s0 + j + 3]).x;
            float aA = sh_ex[w][j * 4 + h] * invh;
            float aB = sh_ex[w][(j + 1) * 4 + h] * invh;
            float aC = sh_ex[w][(j + 2) * 4 + h] * invh;
            float aD = sh_ex[w][(j + 3) * 4 + h] * invh;
            float4 vA = __ldg(&hg4[sA * 32 + lane]);
            float4 vB = __ldg(&hg4[sB * 32 + lane]);
            float4 vC = __ldg(&hg4[sC * 32 + lane]);
            float4 vD = __ldg(&hg4[sD * 32 + lane]);
            acc.x += aA * vA.x + aB * vB.x + aC * vC.x + aD * vD.x;
            acc.y += aA * vA.y + aB * vB.y + aC * vC.y + aD * vD.y;
            acc.z += aA * vA.z + aB * vB.z + aC * vC.z + aD * vD.z;
            acc.w += aA * vA.w + aB * vB.w + aC * vC.w + aD * vD.w;
        }
        for (; j < deg; j++) {
            int s = __ldg(&g_epack[s0 + j]).x;
            float a = sh_ex[w][j * 4 + h] * invh;
            float4 v = __ldg(&hg4[s * 32 + lane]);
            acc.x += a * v.x; acc.y += a * v.y; acc.z += a * v.z; acc.w += a * v.w;
        }
    } else {
        for (int j = 0; j < deg; j++) {
            int s = __ldg(&g_epack[s0 + j]).x;
            float e = lrelu(__ldg(&g_as[s * 4 + h]) + adh);
            float a = expf(e - mh) * invh;
            float4 v = __ldg(&hg4[s * 32 + lane]);
            acc.x += a * v.x; acc.y += a * v.y; acc.z += a * v.z; acc.w += a * v.w;
        }
    }
    float4 bv = __ldg(&((const float4*)bg)[lane]);
    acc.x += bv.x; acc.y += bv.y; acc.z += bv.z; acc.w += bv.w;
    ((float4*)out)[n * 32 + lane] = acc;
    sS[w][lane * 4 + 0] = acc.x; sQ[w][lane * 4 + 0] = acc.x * acc.x;
    sS[w][lane * 4 + 1] = acc.y; sQ[w][lane * 4 + 1] = acc.y * acc.y;
    sS[w][lane * 4 + 2] = acc.z; sQ[w][lane * 4 + 2] = acc.z * acc.z;
    sS[w][lane * 4 + 3] = acc.w; sQ[w][lane * 4 + 3] = acc.w * acc.w;
    __syncthreads();
    const int tid = threadIdx.x;
    if (tid < 128) {
        const int b = blockIdx.x & 63;
        float ts = 0.f, tq = 0.f;
#pragma unroll
        for (int ww = 0; ww < 8; ww++) { ts += sS[ww][tid]; tq += sQ[ww][tid]; }
        atomicAdd(&g_bnpart[b][tid], ts);
        atomicAdd(&g_bnpart[b][tid + 128], tq);
    }
}

// ----------------------------------------------------------------------------
// Gate + final epilogue
// ----------------------------------------------------------------------------
__global__ void __launch_bounds__(128) final_kernel(
        const float* __restrict__ t, const float* __restrict__ x,
        const float* __restrict__ Gw2, const float* __restrict__ Gb2,
        const float* __restrict__ Ws, const float* __restrict__ bs,
        float* __restrict__ out) {
    __shared__ float sG[64 * DOUT];
    __shared__ float sGb[DOUT], sWs[DOUT], sbs[DOUT];
    const int tid = threadIdx.x;
    for (int i = tid; i < 64 * DOUT; i += 128) sG[i] = Gw2[i];
    if (tid < DOUT) { sGb[tid] = Gb2[tid]; sWs[tid] = Ws[tid]; sbs[tid] = bs[tid]; }
    __syncthreads();
    if (tid < 120) {
        const int ni = tid / DOUT, c = tid % DOUT;
        const int n = blockIdx.x * 10 + ni;
        float z = sGb[c];
#pragma unroll 8
        for (int k = 0; k < 64; k++)
            z += __ldg(&t[n * 64 + k]) * sG[k * DOUT + c];
        float gate = 1.f / (1.f + expf(-z));
        float status = __ldg(&x[n * DIN + 12]);
        float flag = status < 0.5f ? 1.f : 0.f;
        float sig = (1.f - status) * sWs[c] + sbs[c];
        out[n * DOUT + c] += 2.5f * flag * gate * sig;
    }
}

// ----------------------------------------------------------------------------
// Launch
// ----------------------------------------------------------------------------
extern "C" void kernel_launch(void* const* d_in, const int* in_sizes, int n_in,
                              void* d_out, int out_size) {
    const float* x   = (const float*)d_in[0];
    const int*   ei  = (const int*)d_in[1];
    const float* ew  = (const float*)d_in[2];
    const float* W1  = (const float*)d_in[3];
    const float* b1  = (const float*)d_in[4];
    const float* g1  = (const float*)d_in[5];
    const float* be1 = (const float*)d_in[6];
    const float* Wg  = (const float*)d_in[7];
    const float* atts= (const float*)d_in[8];
    const float* attd= (const float*)d_in[9];
    const float* bg  = (const float*)d_in[10];
    const float* g2  = (const float*)d_in[11];
    const float* be2 = (const float*)d_in[12];
    const float* W3  = (const float*)d_in[13];
    const float* b3  = (const float*)d_in[14];
    const float* g3  = (const float*)d_in[15];
    const float* be3 = (const float*)d_in[16];
    const float* W4  = (const float*)d_in[17];
    const float* b4  = (const float*)d_in[18];
    const float* Wi  = (const float*)d_in[19];
    const float* bi  = (const float*)d_in[20];
    const float* Gw1 = (const float*)d_in[21];
    const float* Gb1 = (const float*)d_in[22];
    const float* Gw2 = (const float*)d_in[23];
    const float* Gb2 = (const float*)d_in[24];
    const float* Ws  = (const float*)d_in[25];
    const float* bs  = (const float*)d_in[26];
    float* out = (float*)d_out;
    const int* src = ei;
    const int* dst = ei + EE;

    float *p_h1, *p_agg, *p_x1, *p_xin, *p_hg, *p_xa, *p_h4, *p_t;
    float *p_wtg, *p_wt3, *p_wtcomb;
    cudaGetSymbolAddress((void**)&p_h1, g_h1);
    cudaGetSymbolAddress((void**)&p_agg, g_agg);
    cudaGetSymbolAddress((void**)&p_x1, g_x1);
    cudaGetSymbolAddress((void**)&p_xin, g_xin);
    cudaGetSymbolAddress((void**)&p_hg, g_hg);
    cudaGetSymbolAddress((void**)&p_xa, g_xa);
    cudaGetSymbolAddress((void**)&p_h4, g_h4);
    cudaGetSymbolAddress((void**)&p_t, g_t);
    cudaGetSymbolAddress((void**)&p_wtg, g_wtg);
    cudaGetSymbolAddress((void**)&p_wt3, g_wt3);
    cudaGetSymbolAddress((void**)&p_wtcomb, g_wtcomb);

    const int SMEM128 = 1024 + 128 * 132 * 4;   // 68608
    const int SMEM80  = 1024 + 80 * 132 * 4;    // 43264
    cudaFuncSetAttribute(mma_gemm<128, false, true, true, false>,
                         cudaFuncAttributeMaxDynamicSharedMemorySize, SMEM128);
    cudaFuncSetAttribute(mma_gemm<128, true, false, false, false>,
                         cudaFuncAttributeMaxDynamicSharedMemorySize, SMEM128);
    cudaFuncSetAttribute(mma_gemm<80, true, false, false, true>,
                         cudaFuncAttributeMaxDynamicSharedMemorySize, SMEM80);
    const int MGRID = (NN + 127) / 128;   // 782

    // graph preprocessing + weight prep
    init_kernel<<<(NN + 255) / 256, 256>>>();
    count_kernel<<<(EE + 255) / 256, 256>>>(dst, ew);
    dinv_kernel<<<(NN + 255) / 256, 256>>>();
    part_kernel<<<NB, 256>>>();
    scanpart_kernel<<<1, 512>>>();
    writerow_kernel<<<NB, 256>>>();
    fill_kernel<<<(EE + 255) / 256, 256>>>(src, dst, ew);
    transpose_kernel<<<64, 256>>>(Wg, p_wtg, 128, 128);
    transpose_kernel<<<64, 256>>>(W3, p_wt3, 128, 128);
    comb_transpose_kernel<<<40, 256>>>(Gw1, W4);

    // layer 1: aggregate x in 24-dim, fused GEMM -> agg1 (raw) + BN1 partials
    agg24_kernel<<<NN / 4, 128>>>(x, p_xa);
    gemm_in_kernel<<<NN / 16, 128>>>(p_xa, x, W1, b1, Wi, bi, p_agg, p_xin);
    bn_final2<<<1, 128>>>(g1, be1);

    // GAT: Wg GEMM with fused BN1+ReLU on A, side-write x1, fused att reduce
    mma_gemm<128, false, true, true, false><<<MGRID, 256, SMEM128>>>(
        p_agg, nullptr, p_x1, p_wtg, nullptr, p_hg, nullptr, atts, attd);
    gat_agg_kernel<<<NN / 8, 256>>>(p_hg, bg, p_agg);
    bn_final2<<<1, 128>>>(g2, be2);

    // layer 3: W3 GEMM with fused BN2+ReLU + xin residual on A
    mma_gemm<128, true, false, false, false><<<MGRID, 256, SMEM128>>>(
        p_agg, p_xin, nullptr, p_wt3, nullptr, p_h1, nullptr, nullptr, nullptr);
    gcn_agg128<<<NN / 4, 128>>>(p_h1, b3, p_agg);
    bn_final2<<<1, 128>>>(g3, be3);

    // output: combined (Gw1 gate + W4) GEMM with fused BN3+ReLU + x1 residual
    mma_gemm<80, true, false, false, true><<<MGRID, 256, SMEM80>>>(
        p_agg, p_x1, nullptr, p_wtcomb, Gb1, p_t, p_h4, nullptr, nullptr);
    gcn_agg12<<<NN / 4, 128>>>(p_h4, b4, out);
    final_kernel<<<NN / 10, 128>>>(p_t, x, Gw2, Gb2, Ws, bs, out);
}

// round 9
// speedup vs baseline: 2.3254x; 1.0195x over previous
#include <cuda_runtime.h>
#include <math.h>
#include <stdint.h>

#define NN 100000
#define EE 1600000
#define DIN 24
#define HH 128
#define DOUT 12
#define HEADS 4
#define GAT_CAP 128
#define NB 391   // ceil(NN/256)

// ----------------------------------------------------------------------------
// Scratch (device globals; no dynamic allocation allowed)
// ----------------------------------------------------------------------------
__device__ float g_h1[NN * HH];      // h3 = x2@W3
__device__ float g_agg[NN * HH];     // raw pre-BN activations per layer
__device__ float g_x1[NN * HH];      // x1 (side-written by Wg GEMM)
__device__ float g_xin[NN * HH];     // x_in_proj
__device__ float g_hg[NN * HH];      // hg
__device__ float g_xa[NN * DIN];     // 24-dim aggregated x
__device__ float g_h4[NN * DOUT];
__device__ float g_t[NN * 64];
__device__ float g_as[NN * HEADS];
__device__ float g_ad[NN * HEADS];
__device__ float g_deg[NN];
__device__ float g_dinv[NN];
__device__ int   g_cnt[NN];
__device__ int   g_cur[NN];
__device__ int   g_rowptr[NN + 1];
__device__ int2  g_epack[EE];
__device__ int   g_part[512];
__device__ int   g_poff[512];
__device__ float g_bnpart[64][256];  // bucketed BN partials
__device__ float g_bnscale[128];
__device__ float g_bnshift[128];
__device__ float g_wtg[HH * HH];     // Wg^T  [128,128] K-major
__device__ float g_wt3[HH * HH];     // W3^T
__device__ float g_wtcomb[80 * HH];  // [Gw1^T ; W4^T ; pad]

__device__ __forceinline__ float lrelu(float v) { return v > 0.f ? v : 0.2f * v; }
__device__ __forceinline__ uint32_t to_tf32(float f) {
    uint32_t t;
    asm("cvt.rna.tf32.f32 %0, %1;" : "=r"(t) : "f"(f));
    return t;
}

// ----------------------------------------------------------------------------
// Graph preprocessing
// ----------------------------------------------------------------------------
__global__ void __launch_bounds__(256) init_kernel() {
    int i = blockIdx.x * blockDim.x + threadIdx.x;
    if (i < NN) { g_deg[i] = 1.0f; g_cnt[i] = 0; g_cur[i] = 0; }
    if (i < 64 * 256) ((float*)g_bnpart)[i] = 0.f;
}

__global__ void __launch_bounds__(256) count_kernel(const int* __restrict__ dst,
                                                    const float* __restrict__ w) {
    int e = blockIdx.x * blockDim.x + threadIdx.x;
    if (e < EE) {
        int d = dst[e];
        atomicAdd(&g_deg[d], w[e]);
        atomicAdd(&g_cnt[d], 1);
    }
}

// block partials for the scan + dinv (both depend only on count_kernel)
__global__ void __launch_bounds__(256) part_kernel() {
    __shared__ int sw[8];
    int i = blockIdx.x * 256 + threadIdx.x;
    if (i < NN) g_dinv[i] = rsqrtf(g_deg[i]);
    int v = (i < NN) ? g_cnt[i] : 0;
#pragma unroll
    for (int off = 16; off; off >>= 1) v += __shfl_down_sync(0xffffffffu, v, off);
    if ((threadIdx.x & 31) == 0) sw[threadIdx.x >> 5] = v;
    __syncthreads();
    if (threadIdx.x == 0) {
        int s = 0;
#pragma unroll
        for (int k = 0; k < 8; k++) s += sw[k];
        g_part[blockIdx.x] = s;
    }
}

__global__ void __launch_bounds__(512) scanpart_kernel() {
    __shared__ int sp[512];
    int t = threadIdx.x;
    sp[t] = (t < NB) ? g_part[t] : 0;
    __syncthreads();
    for (int off = 1; off < 512; off <<= 1) {
        int a = (t >= off) ? sp[t - off] : 0;
        __syncthreads();
        sp[t] += a;
        __syncthreads();
    }
    if (t < NB) g_poff[t] = (t == 0) ? 0 : sp[t - 1];
}

__global__ void __launch_bounds__(256) writerow_kernel() {
    __shared__ int sp[256];
    int t = threadIdx.x;
    int i = blockIdx.x * 256 + t;
    int v = (i < NN) ? g_cnt[i] : 0;
    sp[t] = v;
    __syncthreads();
    for (int off = 1; off < 256; off <<= 1) {
        int a = (t >= off) ? sp[t - off] : 0;
        __syncthreads();
        sp[t] += a;
        __syncthreads();
    }
    if (i < NN) g_rowptr[i] = sp[t] - v + g_poff[blockIdx.x];
    if (i == 0) g_rowptr[NN] = EE;
}

__global__ void __launch_bounds__(256) fill_kernel(const int* __restrict__ src,
                                                   const int* __restrict__ dst,
                                                   const float* __restrict__ w) {
    int e = blockIdx.x * blockDim.x + threadIdx.x;
    if (e < EE) {
        int d = dst[e];
        int s = src[e];
        int pos = g_rowptr[d] + atomicAdd(&g_cur[d], 1);
        float coef = w[e] * __ldg(&g_dinv[s]) * __ldg(&g_dinv[d]);
        g_epack[pos] = make_int2(s, __float_as_int(coef));
    }
}

// All weight prep in one kernel: Wg^T, W3^T, [Gw1^T;W4^T]
__global__ void __launch_bounds__(256) prep_weights_kernel(const float* __restrict__ Wg,
                                                           const float* __restrict__ W3,
                                                           const float* __restrict__ Gw1,
                                                           const float* __restrict__ W4) {
    int idx = blockIdx.x * 256 + threadIdx.x;
    if (idx < 16384) {
        int k = idx >> 7, c = idx & 127;
        g_wtg[c * 128 + k] = __ldg(&Wg[idx]);
    } else if (idx < 32768) {
        int j = idx - 16384;
        int k = j >> 7, c = j & 127;
        g_wt3[c * 128 + k] = __ldg(&W3[j]);
    } else if (idx < 43008) {
        int j = idx - 32768;
        int r = j >> 7, k = j & 127;
        float v = 0.f;
        if (r < 64) v = __ldg(&Gw1[k * 64 + r]);
        else if (r < 76) v = __ldg(&W4[k * DOUT + (r - 64)]);
        g_wtcomb[j] = v;
    }
}

// ----------------------------------------------------------------------------
// BN finalize: reduce 64 buckets, compute scale/shift, re-zero buckets
// ----------------------------------------------------------------------------
__global__ void __launch_bounds__(128) bn_final2(const float* __restrict__ g,
                                                 const float* __restrict__ be) {
    const int c = threadIdx.x;
    float s = 0.f, s2 = 0.f;
#pragma unroll 8
    for (int b = 0; b < 64; b++) {
        s += g_bnpart[b][c];
        s2 += g_bnpart[b][c + 128];
        g_bnpart[b][c] = 0.f;
        g_bnpart[b][c + 128] = 0.f;
    }
    float mean = s * (1.0f / NN);
    float var = s2 * (1.0f / NN) - mean * mean;
    var = fmaxf(var, 0.f);
    float rstd = rsqrtf(var + 1e-5f);
    float sc = rstd * g[c];
    g_bnscale[c] = sc;
    g_bnshift[c] = be[c] - mean * sc;
}

// ----------------------------------------------------------------------------
// 24-channel GCN aggregation of raw x (layer-1 reassociation)
// ----------------------------------------------------------------------------
__global__ void __launch_bounds__(128) agg24_kernel(const float* __restrict__ x,
                                                    float* __restrict__ xa) {
    const int warp = threadIdx.x >> 5;
    const int lane = threadIdx.x & 31;
    const int n = blockIdx.x * 4 + warp;
    const float dn = g_dinv[n];
    const int s0 = g_rowptr[n], s1 = g_rowptr[n + 1];
    float acc = (lane < DIN) ? x[n * DIN + lane] * dn * dn : 0.f;
    int j = s0;
    for (; j + 4 <= s1; j += 4) {
        int2 eA = __ldg(&g_epack[j]);
        int2 eB = __ldg(&g_epack[j + 1]);
        int2 eC = __ldg(&g_epack[j + 2]);
        int2 eD = __ldg(&g_epack[j + 3]);
        float vA = (lane < DIN) ? __ldg(&x[eA.x * DIN + lane]) : 0.f;
        float vB = (lane < DIN) ? __ldg(&x[eB.x * DIN + lane]) : 0.f;
        float vC = (lane < DIN) ? __ldg(&x[eC.x * DIN + lane]) : 0.f;
        float vD = (lane < DIN) ? __ldg(&x[eD.x * DIN + lane]) : 0.f;
        acc += __int_as_float(eA.y) * vA + __int_as_float(eB.y) * vB
             + __int_as_float(eC.y) * vC + __int_as_float(eD.y) * vD;
    }
    for (; j < s1; j++) {
        int2 e = __ldg(&g_epack[j]);
        if (lane < DIN) acc += __int_as_float(e.y) * __ldg(&x[e.x * DIN + lane]);
    }
    if (lane < DIN) xa[n * DIN + lane] = acc;
}

// ----------------------------------------------------------------------------
// TF32 mma.sync GEMM with fused BN+ReLU on A, optional residual add,
// optional side-write of the activated A, optional att epilogue, combo epilogue
// ----------------------------------------------------------------------------
template<int NC, bool ADD, bool WRITEX, bool ATT, bool COMBO>
__global__ void __launch_bounds__(256) mma_gemm(const float* __restrict__ Araw,
                                                const float* __restrict__ addp,
                                                float* __restrict__ xout,
                                                const float* __restrict__ Bt,
                                                const float* __restrict__ bias,
                                                float* __restrict__ out,
                                                float* __restrict__ out2,
                                                const float* __restrict__ att_s,
                                                const float* __restrict__ att_d) {
    extern __shared__ float smf[];
    float* sSC = smf;               // [128]
    float* sSH = smf + 128;         // [128]
    uint32_t* sW = (uint32_t*)(smf + 256);   // [NC][132] tf32 bits
    const int tid = threadIdx.x, wid = tid >> 5, lane = tid & 31;
    const int n0 = blockIdx.x * 128;

    for (int i = tid; i < 128; i += 256) { sSC[i] = g_bnscale[i]; sSH[i] = g_bnshift[i]; }
    for (int i = tid; i < NC * 128; i += 256) {
        int c = i >> 7, k = i & 127;
        sW[c * 132 + k] = to_tf32(__ldg(&Bt[i]));
    }
    __syncthreads();

    constexpr int NCH = NC / 8;
    float acc[NCH][4];
#pragma unroll
    for (int i = 0; i < NCH; i++) {
        acc[i][0] = 0.f; acc[i][1] = 0.f; acc[i][2] = 0.f; acc[i][3] = 0.f;
    }

    const int r0 = n0 + wid * 16 + (lane >> 2);
    const int r1 = r0 + 8;
    const bool v0 = r0 < NN, v1 = r1 < NN;
    const int kq = lane & 3;
    const int nq = lane >> 2;

#pragma unroll 4
    for (int k8 = 0; k8 < 128; k8 += 8) {
        int ka = k8 + kq, kb = k8 + kq + 4;
        float f0 = 0.f, f1 = 0.f, f2 = 0.f, f3 = 0.f;
        if (v0) {
            f0 = fmaxf(__ldg(&Araw[(size_t)r0 * 128 + ka]) * sSC[ka] + sSH[ka], 0.f);
            f2 = fmaxf(__ldg(&Araw[(size_t)r0 * 128 + kb]) * sSC[kb] + sSH[kb], 0.f);
            if (ADD) {
                f0 += __ldg(&addp[(size_t)r0 * 128 + ka]);
                f2 += __ldg(&addp[(size_t)r0 * 128 + kb]);
            }
            if (WRITEX) {
                xout[(size_t)r0 * 128 + ka] = f0;
                xout[(size_t)r0 * 128 + kb] = f2;
            }
        }
        if (v1) {
            f1 = fmaxf(__ldg(&Araw[(size_t)r1 * 128 + ka]) * sSC[ka] + sSH[ka], 0.f);
            f3 = fmaxf(__ldg(&Araw[(size_t)r1 * 128 + kb]) * sSC[kb] + sSH[kb], 0.f);
            if (ADD) {
                f1 += __ldg(&addp[(size_t)r1 * 128 + ka]);
                f3 += __ldg(&addp[(size_t)r1 * 128 + kb]);
            }
            if (WRITEX) {
                xout[(size_t)r1 * 128 + ka] = f1;
                xout[(size_t)r1 * 128 + kb] = f3;
            }
        }
        uint32_t a0 = to_tf32(f0), a1 = to_tf32(f1), a2 = to_tf32(f2), a3 = to_tf32(f3);
#pragma unroll
        for (int nc = 0; nc < NCH; nc++) {
            uint32_t b0 = sW[(nc * 8 + nq) * 132 + ka];
            uint32_t b1 = sW[(nc * 8 + nq) * 132 + kb];
            asm volatile(
                "mma.sync.aligned.m16n8k8.row.col.f32.tf32.tf32.f32 "
                "{%0,%1,%2,%3}, {%4,%5,%6,%7}, {%8,%9}, {%0,%1,%2,%3};"
                : "+f"(acc[nc][0]), "+f"(acc[nc][1]), "+f"(acc[nc][2]), "+f"(acc[nc][3])
                : "r"(a0), "r"(a1), "r"(a2), "r"(a3), "r"(b0), "r"(b1));
        }
    }

    const int colb = 2 * kq;
#pragma unroll
    for (int nc = 0; nc < NCH; nc++) {
        int col = nc * 8 + colb;
        float2 vlo = make_float2(acc[nc][0], acc[nc][1]);
        float2 vhi = make_float2(acc[nc][2], acc[nc][3]);
        if (COMBO) {
            if (col < 64) {
                float bx = __ldg(&bias[col]), by = __ldg(&bias[col + 1]);
                vlo.x = fmaxf(vlo.x + bx, 0.f); vlo.y = fmaxf(vlo.y + by, 0.f);
                vhi.x = fmaxf(vhi.x + bx, 0.f); vhi.y = fmaxf(vhi.y + by, 0.f);
                if (v0) *(float2*)&out[(size_t)r0 * 64 + col] = vlo;
                if (v1) *(float2*)&out[(size_t)r1 * 64 + col] = vhi;
            } else if (col < 76) {
                int c2 = col - 64;
                if (v0) *(float2*)&out2[(size_t)r0 * DOUT + c2] = vlo;
                if (v1) *(float2*)&out2[(size_t)r1 * DOUT + c2] = vhi;
            }
        } else {
            if (v0) *(float2*)&out[(size_t)r0 * NC + col] = vlo;
            if (v1) *(float2*)&out[(size_t)r1 * NC + col] = vhi;
        }
    }

    if (ATT) {
        float as0[4] = {}, ad0[4] = {}, as1[4] = {}, ad1[4] = {};
#pragma unroll
        for (int nc = 0; nc < NCH; nc++) {
            int col = nc * 8 + colb;
            float sx = __ldg(&att_s[col]), sy = __ldg(&att_s[col + 1]);
            float dx = __ldg(&att_d[col]), dy = __ldg(&att_d[col + 1]);
            int h = nc >> 2;
            as0[h] += acc[nc][0] * sx + acc[nc][1] * sy;
            ad0[h] += acc[nc][0] * dx + acc[nc][1] * dy;
            as1[h] += acc[nc][2] * sx + acc[nc][3] * sy;
            ad1[h] += acc[nc][2] * dx + acc[nc][3] * dy;
        }
#pragma unroll
        for (int h = 0; h < 4; h++) {
#pragma unroll
            for (int off = 1; off <= 2; off <<= 1) {
                as0[h] += __shfl_xor_sync(0xffffffffu, as0[h], off);
                ad0[h] += __shfl_xor_sync(0xffffffffu, ad0[h], off);
                as1[h] += __shfl_xor_sync(0xffffffffu, as1[h], off);
                ad1[h] += __shfl_xor_sync(0xffffffffu, ad1[h], off);
            }
        }
        if (kq == 0) {
#pragma unroll
            for (int h = 0; h < 4; h++) {
                if (v0) { g_as[r0 * 4 + h] = as0[h]; g_ad[r0 * 4 + h] = ad0[h]; }
                if (v1) { g_as[r1 * 4 + h] = as1[h]; g_ad[r1 * 4 + h] = ad1[h]; }
            }
        }
    }
}

// ----------------------------------------------------------------------------
// Fused input GEMM: agg1 = xa@W1 + b1, xin = x@Wi + bi, + fused BN1 partials
// ----------------------------------------------------------------------------
__global__ void __launch_bounds__(128) gemm_in_kernel(
        const float* __restrict__ XA, const float* __restrict__ X,
        const float* __restrict__ W1, const float* __restrict__ b1,
        const float* __restrict__ Wi, const float* __restrict__ bi,
        float* __restrict__ h1, float* __restrict__ xin) {
    __shared__ float sS[4][128], sQ[4][128];
    const int tid = threadIdx.x;
    const int cg = tid & 31;
    const int rg = tid >> 5;
    const int n0 = blockIdx.x * 16 + rg * 4;
    float a1[4][4] = {}; float ai[4][4] = {};
    const float4* W1v = (const float4*)W1;
    const float4* Wiv = (const float4*)Wi;
#pragma unroll
    for (int k = 0; k < DIN; k++) {
        float4 w1 = __ldg(&W1v[k * 32 + cg]);
        float4 wi = __ldg(&Wiv[k * 32 + cg]);
#pragma unroll
        for (int r = 0; r < 4; r++) {
            float xav = __ldg(&XA[(n0 + r) * DIN + k]);
            float xv  = __ldg(&X[(n0 + r) * DIN + k]);
            a1[r][0] += xav * w1.x; a1[r][1] += xav * w1.y; a1[r][2] += xav * w1.z; a1[r][3] += xav * w1.w;
            ai[r][0] += xv * wi.x;  ai[r][1] += xv * wi.y;  ai[r][2] += xv * wi.z;  ai[r][3] += xv * wi.w;
        }
    }
    const int c0 = cg * 4;
    float4 b1v = __ldg(&((const float4*)b1)[cg]);
    float4 biv = __ldg(&((const float4*)bi)[cg]);
    float s4[4] = {}, q4[4] = {};
#pragma unroll
    for (int r = 0; r < 4; r++) {
        float4 v1, vi;
        v1.x = a1[r][0] + b1v.x; v1.y = a1[r][1] + b1v.y;
        v1.z = a1[r][2] + b1v.z; v1.w = a1[r][3] + b1v.w;
        vi.x = ai[r][0] + biv.x; vi.y = ai[r][1] + biv.y;
        vi.z = ai[r][2] + biv.z; vi.w = ai[r][3] + biv.w;
        s4[0] += v1.x; q4[0] += v1.x * v1.x;
        s4[1] += v1.y; q4[1] += v1.y * v1.y;
        s4[2] += v1.z; q4[2] += v1.z * v1.z;
        s4[3] += v1.w; q4[3] += v1.w * v1.w;
        *(float4*)&h1[(n0 + r) * HH + c0] = v1;
        *(float4*)&xin[(n0 + r) * HH + c0] = vi;
    }
#pragma unroll
    for (int i = 0; i < 4; i++) { sS[rg][c0 + i] = s4[i]; sQ[rg][c0 + i] = q4[i]; }
    __syncthreads();
    const int b = blockIdx.x & 63;
    float ts = sS[0][tid] + sS[1][tid] + sS[2][tid] + sS[3][tid];
    float tq = sQ[0][tid] + sQ[1][tid] + sQ[2][tid] + sQ[3][tid];
    atomicAdd(&g_bnpart[b][tid], ts);
    atomicAdd(&g_bnpart[b][tid + 128], tq);
}

// ----------------------------------------------------------------------------
// GCN aggregation (128 channels, warp per node, 8-wide) + fused BN3 partials
// ----------------------------------------------------------------------------
__global__ void __launch_bounds__(128) gcn_agg128(const float* __restrict__ in,
                                                  const float* __restrict__ bias,
                                                  float* __restrict__ out) {
    __shared__ float sS[4][128], sQ[4][128];
    const int warp = threadIdx.x >> 5;
    const int lane = threadIdx.x & 31;
    const int n = blockIdx.x * 4 + warp;
    const float dn = g_dinv[n];
    const int s0 = g_rowptr[n], s1 = g_rowptr[n + 1];
    const float4* in4 = (const float4*)in;
    float4 acc = __ldg(&in4[n * 32 + lane]);
    float dn2 = dn * dn;
    acc.x *= dn2; acc.y *= dn2; acc.z *= dn2; acc.w *= dn2;
    int j = s0;
    for (; j + 8 <= s1; j += 8) {
        int2 e[8];
        float4 v[8];
#pragma unroll
        for (int q = 0; q < 8; q++) e[q] = __ldg(&g_epack[j + q]);
#pragma unroll
        for (int q = 0; q < 8; q++) v[q] = __ldg(&in4[e[q].x * 32 + lane]);
#pragma unroll
        for (int q = 0; q < 8; q++) {
            float c = __int_as_float(e[q].y);
            acc.x += c * v[q].x; acc.y += c * v[q].y;
            acc.z += c * v[q].z; acc.w += c * v[q].w;
        }
    }
    for (; j < s1; j++) {
        int2 e = __ldg(&g_epack[j]);
        float4 v = __ldg(&in4[e.x * 32 + lane]);
        float c = __int_as_float(e.y);
        acc.x += c * v.x; acc.y += c * v.y; acc.z += c * v.z; acc.w += c * v.w;
    }
    float4 bv = __ldg(&((const float4*)bias)[lane]);
    acc.x += bv.x; acc.y += bv.y; acc.z += bv.z; acc.w += bv.w;
    ((float4*)out)[n * 32 + lane] = acc;
    sS[warp][lane * 4 + 0] = acc.x; sQ[warp][lane * 4 + 0] = acc.x * acc.x;
    sS[warp][lane * 4 + 1] = acc.y; sQ[warp][lane * 4 + 1] = acc.y * acc.y;
    sS[warp][lane * 4 + 2] = acc.z; sQ[warp][lane * 4 + 2] = acc.z * acc.z;
    sS[warp][lane * 4 + 3] = acc.w; sQ[warp][lane * 4 + 3] = acc.w * acc.w;
    __syncthreads();
    const int tid = threadIdx.x;
    const int b = blockIdx.x & 63;
    float ts = sS[0][tid] + sS[1][tid] + sS[2][tid] + sS[3][tid];
    float tq = sQ[0][tid] + sQ[1][tid] + sQ[2][tid] + sQ[3][tid];
    atomicAdd(&g_bnpart[b][tid], ts);
    atomicAdd(&g_bnpart[b][tid + 128], tq);
}

// ----------------------------------------------------------------------------
// GAT aggregation: warp per node, single-pass softmax (no max subtraction —
// logits bounded, exp(e)/Σexp(e) ≡ reference), 8-wide gather + BN2 partials
// ----------------------------------------------------------------------------
__global__ void __launch_bounds__(256) gat_agg_kernel(const float* __restrict__ hg,
                                                      const float* __restrict__ bg,
                                                      float* __restrict__ out) {
    __shared__ float sh_ex[8][GAT_CAP * 4];
    __shared__ float sS[8][128], sQ[8][128];
    const int w = threadIdx.x >> 5;
    const int lane = threadIdx.x & 31;
    const int n = blockIdx.x * 8 + w;
    const int s0 = g_rowptr[n], s1 = g_rowptr[n + 1];
    const int deg = s1 - s0;
    const bool cached = (deg <= GAT_CAP);
    const float4* as4 = (const float4*)g_as;
    const float4* ad4 = (const float4*)g_ad;

    float4 adv = __ldg(&ad4[n]);
    float4 asv = __ldg(&as4[n]);
    float xs0 = expf(lrelu(asv.x + adv.x)), xs1 = expf(lrelu(asv.y + adv.y));
    float xs2 = expf(lrelu(asv.z + adv.z)), xs3 = expf(lrelu(asv.w + adv.w));

    float t0 = 0.f, t1 = 0.f, t2 = 0.f, t3 = 0.f;
    for (int j = lane; j < deg; j += 32) {
        int s = __ldg(&g_epack[s0 + j]).x;
        float4 a = __ldg(&as4[s]);
        float x0 = expf(lrelu(a.x + adv.x));
        float x1 = expf(lrelu(a.y + adv.y));
        float x2 = expf(lrelu(a.z + adv.z));
        float x3 = expf(lrelu(a.w + adv.w));
        if (cached) {
            sh_ex[w][j * 4 + 0] = x0; sh_ex[w][j * 4 + 1] = x1;
            sh_ex[w][j * 4 + 2] = x2; sh_ex[w][j * 4 + 3] = x3;
        }
        t0 += x0; t1 += x1; t2 += x2; t3 += x3;
    }
#pragma unroll
    for (int off = 16; off; off >>= 1) {
        t0 += __shfl_xor_sync(0xffffffffu, t0, off);
        t1 += __shfl_xor_sync(0xffffffffu, t1, off);
        t2 += __shfl_xor_sync(0xffffffffu, t2, off);
        t3 += __shfl_xor_sync(0xffffffffu, t3, off);
    }
    __syncwarp();

    t0 += xs0; t1 += xs1; t2 += xs2; t3 += xs3;
    float i0 = 1.f / t0, i1 = 1.f / t1, i2 = 1.f / t2, i3 = 1.f / t3;

    const int h = lane >> 3;
    float invh  = h < 2 ? (h == 0 ? i0 : i1) : (h == 2 ? i2 : i3);
    float aself = h < 2 ? (h == 0 ? xs0 * i0 : xs1 * i1) : (h == 2 ? xs2 * i2 : xs3 * i3);
    float adh   = h < 2 ? (h == 0 ? adv.x : adv.y) : (h == 2 ? adv.z : adv.w);

    const float4* hg4 = (const float4*)hg;
    float4 self = __ldg(&hg4[n * 32 + lane]);
    float4 acc = make_float4(self.x * aself, self.y * aself, self.z * aself, self.w * aself);
    if (cached) {
        int j = 0;
        for (; j + 8 <= deg; j += 8) {
            int s[8];
            float a[8];
            float4 v[8];
#pragma unroll
            for (int q = 0; q < 8; q++) s[q] = __ldg(&g_epack[s0 + j + q]).x;
#pragma unroll
            for (int q = 0; q < 8; q++) a[q] = sh_ex[w][(j + q) * 4 + h] * invh;
#pragma unroll
            for (int q = 0; q < 8; q++) v[q] = __ldg(&hg4[s[q] * 32 + lane]);
#pragma unroll
            for (int q = 0; q < 8; q++) {
                acc.x += a[q] * v[q].x; acc.y += a[q] * v[q].y;
                acc.z += a[q] * v[q].z; acc.w += a[q] * v[q].w;
            }
        }
        for (; j < deg; j++) {
            int s = __ldg(&g_epack[s0 + j]).x;
            float a = sh_ex[w][j * 4 + h] * invh;
            float4 v = __ldg(&hg4[s * 32 + lane]);
            acc.x += a * v.x; acc.y += a * v.y; acc.z += a * v.z; acc.w += a * v.w;
        }
    } else {
        for (int j = 0; j < deg; j++) {
            int s = __ldg(&g_epack[s0 + j]).x;
            float a = expf(lrelu(__ldg(&g_as[s * 4 + h]) + adh)) * invh;
            float4 v = __ldg(&hg4[s * 32 + lane]);
            acc.x += a * v.x; acc.y += a * v.y; acc.z += a * v.z; acc.w += a * v.w;
        }
    }
    float4 bv = __ldg(&((const float4*)bg)[lane]);
    acc.x += bv.x; acc.y += bv.y; acc.z += bv.z; acc.w += bv.w;
    ((float4*)out)[n * 32 + lane] = acc;
    sS[w][lane * 4 + 0] = acc.x; sQ[w][lane * 4 + 0] = acc.x * acc.x;
    sS[w][lane * 4 + 1] = acc.y; sQ[w][lane * 4 + 1] = acc.y * acc.y;
    sS[w][lane * 4 + 2] = acc.z; sQ[w][lane * 4 + 2] = acc.z * acc.z;
    sS[w][lane * 4 + 3] = acc.w; sQ[w][lane * 4 + 3] = acc.w * acc.w;
    __syncthreads();
    const int tid = threadIdx.x;
    if (tid < 128) {
        const int b = blockIdx.x & 63;
        float ts = 0.f, tq = 0.f;
#pragma unroll
        for (int ww = 0; ww < 8; ww++) { ts += sS[ww][tid]; tq += sQ[ww][tid]; }
        atomicAdd(&g_bnpart[b][tid], ts);
        atomicAdd(&g_bnpart[b][tid + 128], tq);
    }
}

// ----------------------------------------------------------------------------
// Output: GCN aggregation of h4 (12 channels) + gate epilogue, fused.
// warp per node, lanes 0..11 active for output channels
// ----------------------------------------------------------------------------
__global__ void __launch_bounds__(128) out_kernel(
        const float* __restrict__ h4, const float* __restrict__ b4,
        const float* __restrict__ t, const float* __restrict__ x,
        const float* __restrict__ Gw2, const float* __restrict__ Gb2,
        const float* __restrict__ Ws, const float* __restrict__ bs,
        float* __restrict__ out) {
    __shared__ float sG[64 * DOUT];
    __shared__ float sGb[DOUT], sWs[DOUT], sbs[DOUT], sb4[DOUT];
    const int tid = threadIdx.x;
    for (int i = tid; i < 64 * DOUT; i += 128) sG[i] = __ldg(&Gw2[i]);
    if (tid < DOUT) {
        sGb[tid] = __ldg(&Gb2[tid]); sWs[tid] = __ldg(&Ws[tid]);
        sbs[tid] = __ldg(&bs[tid]);  sb4[tid] = __ldg(&b4[tid]);
    }
    __syncthreads();
    const int warp = tid >> 5;
    const int lane = tid & 31;
    const int n = blockIdx.x * 4 + warp;
    const float dn = g_dinv[n];
    const int s0 = g_rowptr[n], s1 = g_rowptr[n + 1];
    float acc = (lane < DOUT) ? h4[n * DOUT + lane] * dn * dn : 0.f;
    int j = s0;
    for (; j + 4 <= s1; j += 4) {
        int2 eA = __ldg(&g_epack[j]);
        int2 eB = __ldg(&g_epack[j + 1]);
        int2 eC = __ldg(&g_epack[j + 2]);
        int2 eD = __ldg(&g_epack[j + 3]);
        float vA = (lane < DOUT) ? __ldg(&h4[eA.x * DOUT + lane]) : 0.f;
        float vB = (lane < DOUT) ? __ldg(&h4[eB.x * DOUT + lane]) : 0.f;
        float vC = (lane < DOUT) ? __ldg(&h4[eC.x * DOUT + lane]) : 0.f;
        float vD = (lane < DOUT) ? __ldg(&h4[eD.x * DOUT + lane]) : 0.f;
        acc += __int_as_float(eA.y) * vA + __int_as_float(eB.y) * vB
             + __int_as_float(eC.y) * vC + __int_as_float(eD.y) * vD;
    }
    for (; j < s1; j++) {
        int2 e = __ldg(&g_epack[j]);
        if (lane < DOUT) acc += __int_as_float(e.y) * __ldg(&h4[e.x * DOUT + lane]);
    }
    if (lane < DOUT) {
        float z = sGb[lane];
        const float* tr = t + (size_t)n * 64;
#pragma unroll 8
        for (int k = 0; k < 64; k++)
            z += __ldg(&tr[k]) * sG[k * DOUT + lane];
        float gate = 1.f / (1.f + expf(-z));
        float status = __ldg(&x[n * DIN + 12]);
        float flag = status < 0.5f ? 1.f : 0.f;
        float sig = (1.f - status) * sWs[lane] + sbs[lane];
        out[n * DOUT + lane] = acc + sb4[lane] + 2.5f * flag * gate * sig;
    }
}

// ----------------------------------------------------------------------------
// Launch
// ----------------------------------------------------------------------------
extern "C" void kernel_launch(void* const* d_in, const int* in_sizes, int n_in,
                              void* d_out, int out_size) {
    const float* x   = (const float*)d_in[0];
    const int*   ei  = (const int*)d_in[1];
    const float* ew  = (const float*)d_in[2];
    const float* W1  = (const float*)d_in[3];
    const float* b1  = (const float*)d_in[4];
    const float* g1  = (const float*)d_in[5];
    const float* be1 = (const float*)d_in[6];
    const float* Wg  = (const float*)d_in[7];
    const float* atts= (const float*)d_in[8];
    const float* attd= (const float*)d_in[9];
    const float* bg  = (const float*)d_in[10];
    const float* g2  = (const float*)d_in[11];
    const float* be2 = (const float*)d_in[12];
    const float* W3  = (const float*)d_in[13];
    const float* b3  = (const float*)d_in[14];
    const float* g3  = (const float*)d_in[15];
    const float* be3 = (const float*)d_in[16];
    const float* W4  = (const float*)d_in[17];
    const float* b4  = (const float*)d_in[18];
    const float* Wi  = (const float*)d_in[19];
    const float* bi  = (const float*)d_in[20];
    const float* Gw1 = (const float*)d_in[21];
    const float* Gb1 = (const float*)d_in[22];
    const float* Gw2 = (const float*)d_in[23];
    const float* Gb2 = (const float*)d_in[24];
    const float* Ws  = (const float*)d_in[25];
    const float* bs  = (const float*)d_in[26];
    float* out = (float*)d_out;
    const int* src = ei;
    const int* dst = ei + EE;

    float *p_h1, *p_agg, *p_x1, *p_xin, *p_hg, *p_xa, *p_h4, *p_t;
    float *p_wtg, *p_wt3, *p_wtcomb;
    cudaGetSymbolAddress((void**)&p_h1, g_h1);
    cudaGetSymbolAddress((void**)&p_agg, g_agg);
    cudaGetSymbolAddress((void**)&p_x1, g_x1);
    cudaGetSymbolAddress((void**)&p_xin, g_xin);
    cudaGetSymbolAddress((void**)&p_hg, g_hg);
    cudaGetSymbolAddress((void**)&p_xa, g_xa);
    cudaGetSymbolAddress((void**)&p_h4, g_h4);
    cudaGetSymbolAddress((void**)&p_t, g_t);
    cudaGetSymbolAddress((void**)&p_wtg, g_wtg);
    cudaGetSymbolAddress((void**)&p_wt3, g_wt3);
    cudaGetSymbolAddress((void**)&p_wtcomb, g_wtcomb);

    const int SMEM128 = 1024 + 128 * 132 * 4;   // 68608
    const int SMEM80  = 1024 + 80 * 132 * 4;    // 43264
    cudaFuncSetAttribute(mma_gemm<128, false, true, true, false>,
                         cudaFuncAttributeMaxDynamicSharedMemorySize, SMEM128);
    cudaFuncSetAttribute(mma_gemm<128, true, false, false, false>,
                         cudaFuncAttributeMaxDynamicSharedMemorySize, SMEM128);
    cudaFuncSetAttribute(mma_gemm<80, true, false, false, true>,
                         cudaFuncAttributeMaxDynamicSharedMemorySize, SMEM80);
    const int MGRID = (NN + 127) / 128;   // 782

    // graph preprocessing + weight prep
    init_kernel<<<(NN + 255) / 256, 256>>>();
    count_kernel<<<(EE + 255) / 256, 256>>>(dst, ew);
    part_kernel<<<NB, 256>>>();
    scanpart_kernel<<<1, 512>>>();
    writerow_kernel<<<NB, 256>>>();
    fill_kernel<<<(EE + 255) / 256, 256>>>(src, dst, ew);
    prep_weights_kernel<<<168, 256>>>(Wg, W3, Gw1, W4);

    // layer 1: aggregate x in 24-dim, fused GEMM -> agg1 (raw) + BN1 partials
    agg24_kernel<<<NN / 4, 128>>>(x, p_xa);
    gemm_in_kernel<<<NN / 16, 128>>>(p_xa, x, W1, b1, Wi, bi, p_agg, p_xin);
    bn_final2<<<1, 128>>>(g1, be1);

    // GAT: Wg GEMM with fused BN1+ReLU on A, side-write x1, fused att reduce
    mma_gemm<128, false, true, true, false><<<MGRID, 256, SMEM128>>>(
        p_agg, nullptr, p_x1, p_wtg, nullptr, p_hg, nullptr, atts, attd);
    gat_agg_kernel<<<NN / 8, 256>>>(p_hg, bg, p_agg);
    bn_final2<<<1, 128>>>(g2, be2);

    // layer 3: W3 GEMM with fused BN2+ReLU + xin residual on A
    mma_gemm<128, true, false, false, false><<<MGRID, 256, SMEM128>>>(
        p_agg, p_xin, nullptr, p_wt3, nullptr, p_h1, nullptr, nullptr, nullptr);
    gcn_agg128<<<NN / 4, 128>>>(p_h1, b3, p_agg);
    bn_final2<<<1, 128>>>(g3, be3);

    // output: combined (Gw1 gate + W4) GEMM with fused BN3+ReLU + x1 residual
    mma_gemm<80, true, false, false, true><<<MGRID, 256, SMEM80>>>(
        p_agg, p_x1, nullptr, p_wtcomb, Gb1, p_t, p_h4, nullptr, nullptr);
    out_kernel<<<NN / 4, 128>>>(p_h4, b4, p_t, x, Gw2, Gb2, Ws, bs, out);
}

// round 10
// speedup vs baseline: 2.3258x; 1.0002x over previous
#include <cuda_runtime.h>
#include <math.h>
#include <stdint.h>

#define NN 100000
#define EE 1600000
#define DIN 24
#define HH 128
#define DOUT 12
#define HEADS 4
#define NB 391   // ceil(NN/256)

// ----------------------------------------------------------------------------
// Scratch (device globals; no dynamic allocation allowed)
// ----------------------------------------------------------------------------
__device__ float g_h1[NN * HH];      // h3 = x2@W3
__device__ float g_agg[NN * HH];     // raw pre-BN activations per layer
__device__ float g_x1[NN * HH];      // x1 (side-written by Wg GEMM)
__device__ float g_xin[NN * HH];     // x_in_proj
__device__ float g_hg[NN * HH];      // hg
__device__ float g_xa[NN * DIN];     // 24-dim aggregated x
__device__ float g_h4[NN * DOUT];
__device__ float g_t[NN * 64];
__device__ float g_as[NN * HEADS];
__device__ float g_ad[NN * HEADS];
__device__ float g_deg[NN];
__device__ float g_dinv[NN];
__device__ int   g_cnt[NN];
__device__ int   g_cur[NN];
__device__ int   g_rowptr[NN + 1];
__device__ int2  g_epack[EE];
__device__ int   g_part[512];
__device__ int   g_poff[512];
__device__ float g_bnpart[64][256];  // bucketed BN partials
__device__ float g_bnscale[128];
__device__ float g_bnshift[128];
__device__ float g_wtg[HH * HH];     // Wg^T  [128,128] K-major
__device__ float g_wt3[HH * HH];     // W3^T
__device__ float g_wtcomb[80 * HH];  // [Gw1^T ; W4^T ; pad]

__device__ __forceinline__ float lrelu(float v) { return v > 0.f ? v : 0.2f * v; }
__device__ __forceinline__ uint32_t to_tf32(float f) {
    uint32_t t;
    asm("cvt.rna.tf32.f32 %0, %1;" : "=r"(t) : "f"(f));
    return t;
}

// ----------------------------------------------------------------------------
// Graph preprocessing
// ----------------------------------------------------------------------------
__global__ void __launch_bounds__(256) init_kernel() {
    int i = blockIdx.x * blockDim.x + threadIdx.x;
    if (i < NN) { g_deg[i] = 1.0f; g_cnt[i] = 0; g_cur[i] = 0; }
    if (i < 64 * 256) ((float*)g_bnpart)[i] = 0.f;
}

__global__ void __launch_bounds__(256) count_kernel(const int* __restrict__ dst,
                                                    const float* __restrict__ w) {
    int e = blockIdx.x * blockDim.x + threadIdx.x;
    if (e < EE) {
        int d = dst[e];
        atomicAdd(&g_deg[d], w[e]);
        atomicAdd(&g_cnt[d], 1);
    }
}

__global__ void __launch_bounds__(256) part_kernel() {
    __shared__ int sw[8];
    int i = blockIdx.x * 256 + threadIdx.x;
    if (i < NN) g_dinv[i] = rsqrtf(g_deg[i]);
    int v = (i < NN) ? g_cnt[i] : 0;
#pragma unroll
    for (int off = 16; off; off >>= 1) v += __shfl_down_sync(0xffffffffu, v, off);
    if ((threadIdx.x & 31) == 0) sw[threadIdx.x >> 5] = v;
    __syncthreads();
    if (threadIdx.x == 0) {
        int s = 0;
#pragma unroll
        for (int k = 0; k < 8; k++) s += sw[k];
        g_part[blockIdx.x] = s;
    }
}

__global__ void __launch_bounds__(512) scanpart_kernel() {
    __shared__ int sp[512];
    int t = threadIdx.x;
    sp[t] = (t < NB) ? g_part[t] : 0;
    __syncthreads();
    for (int off = 1; off < 512; off <<= 1) {
        int a = (t >= off) ? sp[t - off] : 0;
        __syncthreads();
        sp[t] += a;
        __syncthreads();
    }
    if (t < NB) g_poff[t] = (t == 0) ? 0 : sp[t - 1];
}

__global__ void __launch_bounds__(256) writerow_kernel() {
    __shared__ int sp[256];
    int t = threadIdx.x;
    int i = blockIdx.x * 256 + t;
    int v = (i < NN) ? g_cnt[i] : 0;
    sp[t] = v;
    __syncthreads();
    for (int off = 1; off < 256; off <<= 1) {
        int a = (t >= off) ? sp[t - off] : 0;
        __syncthreads();
        sp[t] += a;
        __syncthreads();
    }
    if (i < NN) g_rowptr[i] = sp[t] - v + g_poff[blockIdx.x];
    if (i == 0) g_rowptr[NN] = EE;
}

__global__ void __launch_bounds__(256) fill_kernel(const int* __restrict__ src,
                                                   const int* __restrict__ dst,
                                                   const float* __restrict__ w) {
    int e = blockIdx.x * blockDim.x + threadIdx.x;
    if (e < EE) {
        int d = dst[e];
        int s = src[e];
        int pos = g_rowptr[d] + atomicAdd(&g_cur[d], 1);
        float coef = w[e] * __ldg(&g_dinv[s]) * __ldg(&g_dinv[d]);
        g_epack[pos] = make_int2(s, __float_as_int(coef));
    }
}

__global__ void __launch_bounds__(256) prep_weights_kernel(const float* __restrict__ Wg,
                                                           const float* __restrict__ W3,
                                                           const float* __restrict__ Gw1,
                                                           const float* __restrict__ W4) {
    int idx = blockIdx.x * 256 + threadIdx.x;
    if (idx < 16384) {
        int k = idx >> 7, c = idx & 127;
        g_wtg[c * 128 + k] = __ldg(&Wg[idx]);
    } else if (idx < 32768) {
        int j = idx - 16384;
        int k = j >> 7, c = j & 127;
        g_wt3[c * 128 + k] = __ldg(&W3[j]);
    } else if (idx < 43008) {
        int j = idx - 32768;
        int r = j >> 7, k = j & 127;
        float v = 0.f;
        if (r < 64) v = __ldg(&Gw1[k * 64 + r]);
        else if (r < 76) v = __ldg(&W4[k * DOUT + (r - 64)]);
        g_wtcomb[j] = v;
    }
}

// ----------------------------------------------------------------------------
// BN finalize: reduce 64 buckets, compute scale/shift, re-zero buckets
// ----------------------------------------------------------------------------
__global__ void __launch_bounds__(128) bn_final2(const float* __restrict__ g,
                                                 const float* __restrict__ be) {
    const int c = threadIdx.x;
    float s = 0.f, s2 = 0.f;
#pragma unroll 8
    for (int b = 0; b < 64; b++) {
        s += g_bnpart[b][c];
        s2 += g_bnpart[b][c + 128];
        g_bnpart[b][c] = 0.f;
        g_bnpart[b][c + 128] = 0.f;
    }
    float mean = s * (1.0f / NN);
    float var = s2 * (1.0f / NN) - mean * mean;
    var = fmaxf(var, 0.f);
    float rstd = rsqrtf(var + 1e-5f);
    float sc = rstd * g[c];
    g_bnscale[c] = sc;
    g_bnshift[c] = be[c] - mean * sc;
}

// ----------------------------------------------------------------------------
// 24-channel GCN aggregation of raw x (layer-1 reassociation)
// ----------------------------------------------------------------------------
__global__ void __launch_bounds__(128) agg24_kernel(const float* __restrict__ x,
                                                    float* __restrict__ xa) {
    const int warp = threadIdx.x >> 5;
    const int lane = threadIdx.x & 31;
    const int n = blockIdx.x * 4 + warp;
    const float dn = g_dinv[n];
    const int s0 = g_rowptr[n], s1 = g_rowptr[n + 1];
    float acc = (lane < DIN) ? x[n * DIN + lane] * dn * dn : 0.f;
    int j = s0;
    for (; j + 8 <= s1; j += 8) {
        int2 e[8];
        float v[8];
#pragma unroll
        for (int q = 0; q < 8; q++) e[q] = __ldg(&g_epack[j + q]);
#pragma unroll
        for (int q = 0; q < 8; q++)
            v[q] = (lane < DIN) ? __ldg(&x[e[q].x * DIN + lane]) : 0.f;
#pragma unroll
        for (int q = 0; q < 8; q++) acc += __int_as_float(e[q].y) * v[q];
    }
    for (; j < s1; j++) {
        int2 e = __ldg(&g_epack[j]);
        if (lane < DIN) acc += __int_as_float(e.y) * __ldg(&x[e.x * DIN + lane]);
    }
    if (lane < DIN) xa[n * DIN + lane] = acc;
}

// ----------------------------------------------------------------------------
// TF32 mma.sync GEMM with fused BN+ReLU on A, optional residual add,
// optional side-write of the activated A, optional att epilogue, combo epilogue
// ----------------------------------------------------------------------------
template<int NC, bool ADD, bool WRITEX, bool ATT, bool COMBO>
__global__ void __launch_bounds__(256) mma_gemm(const float* __restrict__ Araw,
                                                const float* __restrict__ addp,
                                                float* __restrict__ xout,
                                                const float* __restrict__ Bt,
                                                const float* __restrict__ bias,
                                                float* __restrict__ out,
                                                float* __restrict__ out2,
                                                const float* __restrict__ att_s,
                                                const float* __restrict__ att_d) {
    extern __shared__ float smf[];
    float* sSC = smf;
    float* sSH = smf + 128;
    uint32_t* sW = (uint32_t*)(smf + 256);   // [NC][132] tf32 bits
    const int tid = threadIdx.x, wid = tid >> 5, lane = tid & 31;
    const int n0 = blockIdx.x * 128;

    for (int i = tid; i < 128; i += 256) { sSC[i] = g_bnscale[i]; sSH[i] = g_bnshift[i]; }
    for (int i = tid; i < NC * 128; i += 256) {
        int c = i >> 7, k = i & 127;
        sW[c * 132 + k] = to_tf32(__ldg(&Bt[i]));
    }
    __syncthreads();

    constexpr int NCH = NC / 8;
    float acc[NCH][4];
#pragma unroll
    for (int i = 0; i < NCH; i++) {
        acc[i][0] = 0.f; acc[i][1] = 0.f; acc[i][2] = 0.f; acc[i][3] = 0.f;
    }

    const int r0 = n0 + wid * 16 + (lane >> 2);
    const int r1 = r0 + 8;
    const bool v0 = r0 < NN, v1 = r1 < NN;
    const int kq = lane & 3;
    const int nq = lane >> 2;

#pragma unroll 4
    for (int k8 = 0; k8 < 128; k8 += 8) {
        int ka = k8 + kq, kb = k8 + kq + 4;
        float f0 = 0.f, f1 = 0.f, f2 = 0.f, f3 = 0.f;
        if (v0) {
            f0 = fmaxf(__ldg(&Araw[(size_t)r0 * 128 + ka]) * sSC[ka] + sSH[ka], 0.f);
            f2 = fmaxf(__ldg(&Araw[(size_t)r0 * 128 + kb]) * sSC[kb] + sSH[kb], 0.f);
            if (ADD) {
                f0 += __ldg(&addp[(size_t)r0 * 128 + ka]);
                f2 += __ldg(&addp[(size_t)r0 * 128 + kb]);
            }
            if (WRITEX) {
                xout[(size_t)r0 * 128 + ka] = f0;
                xout[(size_t)r0 * 128 + kb] = f2;
            }
        }
        if (v1) {
            f1 = fmaxf(__ldg(&Araw[(size_t)r1 * 128 + ka]) * sSC[ka] + sSH[ka], 0.f);
            f3 = fmaxf(__ldg(&Araw[(size_t)r1 * 128 + kb]) * sSC[kb] + sSH[kb], 0.f);
            if (ADD) {
                f1 += __ldg(&addp[(size_t)r1 * 128 + ka]);
                f3 += __ldg(&addp[(size_t)r1 * 128 + kb]);
            }
            if (WRITEX) {
                xout[(size_t)r1 * 128 + ka] = f1;
                xout[(size_t)r1 * 128 + kb] = f3;
            }
        }
        uint32_t a0 = to_tf32(f0), a1 = to_tf32(f1), a2 = to_tf32(f2), a3 = to_tf32(f3);
#pragma unroll
        for (int nc = 0; nc < NCH; nc++) {
            uint32_t b0 = sW[(nc * 8 + nq) * 132 + ka];
            uint32_t b1 = sW[(nc * 8 + nq) * 132 + kb];
            asm volatile(
                "mma.sync.aligned.m16n8k8.row.col.f32.tf32.tf32.f32 "
                "{%0,%1,%2,%3}, {%4,%5,%6,%7}, {%8,%9}, {%0,%1,%2,%3};"
                : "+f"(acc[nc][0]), "+f"(acc[nc][1]), "+f"(acc[nc][2]), "+f"(acc[nc][3])
                : "r"(a0), "r"(a1), "r"(a2), "r"(a3), "r"(b0), "r"(b1));
        }
    }

    const int colb = 2 * kq;
#pragma unroll
    for (int nc = 0; nc < NCH; nc++) {
        int col = nc * 8 + colb;
        float2 vlo = make_float2(acc[nc][0], acc[nc][1]);
        float2 vhi = make_float2(acc[nc][2], acc[nc][3]);
        if (COMBO) {
            if (col < 64) {
                float bx = __ldg(&bias[col]), by = __ldg(&bias[col + 1]);
                vlo.x = fmaxf(vlo.x + bx, 0.f); vlo.y = fmaxf(vlo.y + by, 0.f);
                vhi.x = fmaxf(vhi.x + bx, 0.f); vhi.y = fmaxf(vhi.y + by, 0.f);
                if (v0) *(float2*)&out[(size_t)r0 * 64 + col] = vlo;
                if (v1) *(float2*)&out[(size_t)r1 * 64 + col] = vhi;
            } else if (col < 76) {
                int c2 = col - 64;
                if (v0) *(float2*)&out2[(size_t)r0 * DOUT + c2] = vlo;
                if (v1) *(float2*)&out2[(size_t)r1 * DOUT + c2] = vhi;
            }
        } else {
            if (v0) *(float2*)&out[(size_t)r0 * NC + col] = vlo;
            if (v1) *(float2*)&out[(size_t)r1 * NC + col] = vhi;
        }
    }

    if (ATT) {
        float as0[4] = {}, ad0[4] = {}, as1[4] = {}, ad1[4] = {};
#pragma unroll
        for (int nc = 0; nc < NCH; nc++) {
            int col = nc * 8 + colb;
            float sx = __ldg(&att_s[col]), sy = __ldg(&att_s[col + 1]);
            float dx = __ldg(&att_d[col]), dy = __ldg(&att_d[col + 1]);
            int h = nc >> 2;
            as0[h] += acc[nc][0] * sx + acc[nc][1] * sy;
            ad0[h] += acc[nc][0] * dx + acc[nc][1] * dy;
            as1[h] += acc[nc][2] * sx + acc[nc][3] * sy;
            ad1[h] += acc[nc][2] * dx + acc[nc][3] * dy;
        }
#pragma unroll
        for (int h = 0; h < 4; h++) {
#pragma unroll
            for (int off = 1; off <= 2; off <<= 1) {
                as0[h] += __shfl_xor_sync(0xffffffffu, as0[h], off);
                ad0[h] += __shfl_xor_sync(0xffffffffu, ad0[h], off);
                as1[h] += __shfl_xor_sync(0xffffffffu, as1[h], off);
                ad1[h] += __shfl_xor_sync(0xffffffffu, ad1[h], off);
            }
        }
        if (kq == 0) {
#pragma unroll
            for (int h = 0; h < 4; h++) {
                if (v0) { g_as[r0 * 4 + h] = as0[h]; g_ad[r0 * 4 + h] = ad0[h]; }
                if (v1) { g_as[r1 * 4 + h] = as1[h]; g_ad[r1 * 4 + h] = ad1[h]; }
            }
        }
    }
}

// ----------------------------------------------------------------------------
// Fused input GEMM: agg1 = xa@W1 + b1, xin = x@Wi + bi, + fused BN1 partials
// ----------------------------------------------------------------------------
__global__ void __launch_bounds__(128) gemm_in_kernel(
        const float* __restrict__ XA, const float* __restrict__ X,
        const float* __restrict__ W1, const float* __restrict__ b1,
        const float* __restrict__ Wi, const float* __restrict__ bi,
        float* __restrict__ h1, float* __restrict__ xin) {
    __shared__ float sS[4][128], sQ[4][128];
    const int tid = threadIdx.x;
    const int cg = tid & 31;
    const int rg = tid >> 5;
    const int n0 = blockIdx.x * 16 + rg * 4;
    float a1[4][4] = {}; float ai[4][4] = {};
    const float4* W1v = (const float4*)W1;
    const float4* Wiv = (const float4*)Wi;
#pragma unroll
    for (int k = 0; k < DIN; k++) {
        float4 w1 = __ldg(&W1v[k * 32 + cg]);
        float4 wi = __ldg(&Wiv[k * 32 + cg]);
#pragma unroll
        for (int r = 0; r < 4; r++) {
            float xav = __ldg(&XA[(n0 + r) * DIN + k]);
            float xv  = __ldg(&X[(n0 + r) * DIN + k]);
            a1[r][0] += xav * w1.x; a1[r][1] += xav * w1.y; a1[r][2] += xav * w1.z; a1[r][3] += xav * w1.w;
            ai[r][0] += xv * wi.x;  ai[r][1] += xv * wi.y;  ai[r][2] += xv * wi.z;  ai[r][3] += xv * wi.w;
        }
    }
    const int c0 = cg * 4;
    float4 b1v = __ldg(&((const float4*)b1)[cg]);
    float4 biv = __ldg(&((const float4*)bi)[cg]);
    float s4[4] = {}, q4[4] = {};
#pragma unroll
    for (int r = 0; r < 4; r++) {
        float4 v1, vi;
        v1.x = a1[r][0] + b1v.x; v1.y = a1[r][1] + b1v.y;
        v1.z = a1[r][2] + b1v.z; v1.w = a1[r][3] + b1v.w;
        vi.x = ai[r][0] + biv.x; vi.y = ai[r][1] + biv.y;
        vi.z = ai[r][2] + biv.z; vi.w = ai[r][3] + biv.w;
        s4[0] += v1.x; q4[0] += v1.x * v1.x;
        s4[1] += v1.y; q4[1] += v1.y * v1.y;
        s4[2] += v1.z; q4[2] += v1.z * v1.z;
        s4[3] += v1.w; q4[3] += v1.w * v1.w;
        *(float4*)&h1[(n0 + r) * HH + c0] = v1;
        *(float4*)&xin[(n0 + r) * HH + c0] = vi;
    }
#pragma unroll
    for (int i = 0; i < 4; i++) { sS[rg][c0 + i] = s4[i]; sQ[rg][c0 + i] = q4[i]; }
    __syncthreads();
    const int b = blockIdx.x & 63;
    float ts = sS[0][tid] + sS[1][tid] + sS[2][tid] + sS[3][tid];
    float tq = sQ[0][tid] + sQ[1][tid] + sQ[2][tid] + sQ[3][tid];
    atomicAdd(&g_bnpart[b][tid], ts);
    atomicAdd(&g_bnpart[b][tid + 128], tq);
}

// ----------------------------------------------------------------------------
// GCN aggregation (128 channels, warp per node, 8-wide) + fused BN3 partials
// ----------------------------------------------------------------------------
__global__ void __launch_bounds__(128) gcn_agg128(const float* __restrict__ in,
                                                  const float* __restrict__ bias,
                                                  float* __restrict__ out) {
    __shared__ float sS[4][128], sQ[4][128];
    const int warp = threadIdx.x >> 5;
    const int lane = threadIdx.x & 31;
    const int n = blockIdx.x * 4 + warp;
    const float dn = g_dinv[n];
    const int s0 = g_rowptr[n], s1 = g_rowptr[n + 1];
    const float4* in4 = (const float4*)in;
    float4 acc = __ldg(&in4[n * 32 + lane]);
    float dn2 = dn * dn;
    acc.x *= dn2; acc.y *= dn2; acc.z *= dn2; acc.w *= dn2;
    int j = s0;
    for (; j + 8 <= s1; j += 8) {
        int2 e[8];
        float4 v[8];
#pragma unroll
        for (int q = 0; q < 8; q++) e[q] = __ldg(&g_epack[j + q]);
#pragma unroll
        for (int q = 0; q < 8; q++) v[q] = __ldg(&in4[e[q].x * 32 + lane]);
#pragma unroll
        for (int q = 0; q < 8; q++) {
            float c = __int_as_float(e[q].y);
            acc.x += c * v[q].x; acc.y += c * v[q].y;
            acc.z += c * v[q].z; acc.w += c * v[q].w;
        }
    }
    for (; j < s1; j++) {
        int2 e = __ldg(&g_epack[j]);
        float4 v = __ldg(&in4[e.x * 32 + lane]);
        float c = __int_as_float(e.y);
        acc.x += c * v.x; acc.y += c * v.y; acc.z += c * v.z; acc.w += c * v.w;
    }
    float4 bv = __ldg(&((const float4*)bias)[lane]);
    acc.x += bv.x; acc.y += bv.y; acc.z += bv.z; acc.w += bv.w;
    ((float4*)out)[n * 32 + lane] = acc;
    sS[warp][lane * 4 + 0] = acc.x; sQ[warp][lane * 4 + 0] = acc.x * acc.x;
    sS[warp][lane * 4 + 1] = acc.y; sQ[warp][lane * 4 + 1] = acc.y * acc.y;
    sS[warp][lane * 4 + 2] = acc.z; sQ[warp][lane * 4 + 2] = acc.z * acc.z;
    sS[warp][lane * 4 + 3] = acc.w; sQ[warp][lane * 4 + 3] = acc.w * acc.w;
    __syncthreads();
    const int tid = threadIdx.x;
    const int b = blockIdx.x & 63;
    float ts = sS[0][tid] + sS[1][tid] + sS[2][tid] + sS[3][tid];
    float tq = sQ[0][tid] + sQ[1][tid] + sQ[2][tid] + sQ[3][tid];
    atomicAdd(&g_bnpart[b][tid], ts);
    atomicAdd(&g_bnpart[b][tid + 128], tq);
}

// ----------------------------------------------------------------------------
// GAT aggregation: SINGLE PASS. Unnormalized weighted sum + exp-sum in one
// edge loop; normalize at the end. Lane (h*8+q) computes the exp for edge-slot
// q, head h; an 8-lane shfl broadcasts it to the gather lanes. + BN2 partials.
// ----------------------------------------------------------------------------
__global__ void __launch_bounds__(256) gat_agg_kernel(const float* __restrict__ hg,
                                                      const float* __restrict__ bg,
                                                      float* __restrict__ out) {
    __shared__ float sS[8][128], sQ[8][128];
    const int w = threadIdx.x >> 5;
    const int lane = threadIdx.x & 31;
    const int n = blockIdx.x * 8 + w;
    const int s0 = g_rowptr[n], s1 = g_rowptr[n + 1];
    const int h = lane >> 3;       // this lane's head
    const int eq = lane & 7;       // this lane's edge slot for exp computation
    const float4* ad4 = (const float4*)g_ad;
    const float4* as4 = (const float4*)g_as;

    float4 adv = __ldg(&ad4[n]);
    float4 asv = __ldg(&as4[n]);
    float adh = h < 2 ? (h == 0 ? adv.x : adv.y) : (h == 2 ? adv.z : adv.w);
    float ash = h < 2 ? (h == 0 ? asv.x : asv.y) : (h == 2 ? asv.z : asv.w);
    float xs = expf(lrelu(ash + adh));   // self exp for this head (dup x8)

    const float4* hg4 = (const float4*)hg;
    float4 acc = make_float4(0.f, 0.f, 0.f, 0.f);
    float tsum = 0.f;

    int j = s0;
    for (; j + 8 <= s1; j += 8) {
        int2 e[8];
#pragma unroll
        for (int q = 0; q < 8; q++) e[q] = __ldg(&g_epack[j + q]);
        // my exp: edge slot eq, head h
        float myx = expf(lrelu(__ldg(&g_as[e[eq].x * 4 + h]) + adh));
        tsum += myx;
        float4 v[8];
#pragma unroll
        for (int q = 0; q < 8; q++) v[q] = __ldg(&hg4[e[q].x * 32 + lane]);
#pragma unroll
        for (int q = 0; q < 8; q++) {
            float a = __shfl_sync(0xffffffffu, myx, h * 8 + q);
            acc.x += a * v[q].x; acc.y += a * v[q].y;
            acc.z += a * v[q].z; acc.w += a * v[q].w;
        }
    }
    for (; j < s1; j++) {
        int2 e = __ldg(&g_epack[j]);
        float a = expf(lrelu(__ldg(&g_as[e.x * 4 + h]) + adh));
        if (eq == 0) tsum += a;   // count each tail edge once per head group
        float4 v = __ldg(&hg4[e.x * 32 + lane]);
        acc.x += a * v.x; acc.y += a * v.y; acc.z += a * v.z; acc.w += a * v.w;
    }
    // reduce tsum within the 8-lane head group
#pragma unroll
    for (int off = 1; off <= 4; off <<= 1)
        tsum += __shfl_xor_sync(0xffffffffu, tsum, off);
    float inv = 1.f / (tsum + xs);

    float4 self = __ldg(&hg4[n * 32 + lane]);
    float4 bv = __ldg(&((const float4*)bg)[lane]);
    float4 o;
    o.x = (acc.x + xs * self.x) * inv + bv.x;
    o.y = (acc.y + xs * self.y) * inv + bv.y;
    o.z = (acc.z + xs * self.z) * inv + bv.z;
    o.w = (acc.w + xs * self.w) * inv + bv.w;
    ((float4*)out)[n * 32 + lane] = o;
    sS[w][lane * 4 + 0] = o.x; sQ[w][lane * 4 + 0] = o.x * o.x;
    sS[w][lane * 4 + 1] = o.y; sQ[w][lane * 4 + 1] = o.y * o.y;
    sS[w][lane * 4 + 2] = o.z; sQ[w][lane * 4 + 2] = o.z * o.z;
    sS[w][lane * 4 + 3] = o.w; sQ[w][lane * 4 + 3] = o.w * o.w;
    __syncthreads();
    const int tid = threadIdx.x;
    if (tid < 128) {
        const int b = blockIdx.x & 63;
        float ts = 0.f, tq = 0.f;
#pragma unroll
        for (int ww = 0; ww < 8; ww++) { ts += sS[ww][tid]; tq += sQ[ww][tid]; }
        atomicAdd(&g_bnpart[b][tid], ts);
        atomicAdd(&g_bnpart[b][tid + 128], tq);
    }
}

// ----------------------------------------------------------------------------
// Output: GCN aggregation of h4 (12 channels, 8-wide) + gate epilogue, fused.
// ----------------------------------------------------------------------------
__global__ void __launch_bounds__(128) out_kernel(
        const float* __restrict__ h4, const float* __restrict__ b4,
        const float* __restrict__ t, const float* __restrict__ x,
        const float* __restrict__ Gw2, const float* __restrict__ Gb2,
        const float* __restrict__ Ws, const float* __restrict__ bs,
        float* __restrict__ out) {
    __shared__ float sG[64 * DOUT];
    __shared__ float sGb[DOUT], sWs[DOUT], sbs[DOUT], sb4[DOUT];
    const int tid = threadIdx.x;
    for (int i = tid; i < 64 * DOUT; i += 128) sG[i] = __ldg(&Gw2[i]);
    if (tid < DOUT) {
        sGb[tid] = __ldg(&Gb2[tid]); sWs[tid] = __ldg(&Ws[tid]);
        sbs[tid] = __ldg(&bs[tid]);  sb4[tid] = __ldg(&b4[tid]);
    }
    __syncthreads();
    const int warp = tid >> 5;
    const int lane = tid & 31;
    const int n = blockIdx.x * 4 + warp;
    const float dn = g_dinv[n];
    const int s0 = g_rowptr[n], s1 = g_rowptr[n + 1];
    float acc = (lane < DOUT) ? h4[n * DOUT + lane] * dn * dn : 0.f;
    int j = s0;
    for (; j + 8 <= s1; j += 8) {
        int2 e[8];
        float v[8];
#pragma unroll
        for (int q = 0; q < 8; q++) e[q] = __ldg(&g_epack[j + q]);
#pragma unroll
        for (int q = 0; q < 8; q++)
            v[q] = (lane < DOUT) ? __ldg(&h4[e[q].x * DOUT + lane]) : 0.f;
#pragma unroll
        for (int q = 0; q < 8; q++) acc += __int_as_float(e[q].y) * v[q];
    }
    for (; j < s1; j++) {
        int2 e = __ldg(&g_epack[j]);
        if (lane < DOUT) acc += __int_as_float(e.y) * __ldg(&h4[e.x * DOUT + lane]);
    }
    if (lane < DOUT) {
        float z = sGb[lane];
        const float* tr = t + (size_t)n * 64;
#pragma unroll 8
        for (int k = 0; k < 64; k++)
            z += __ldg(&tr[k]) * sG[k * DOUT + lane];
        float gate = 1.f / (1.f + expf(-z));
        float status = __ldg(&x[n * DIN + 12]);
        float flag = status < 0.5f ? 1.f : 0.f;
        float sig = (1.f - status) * sWs[lane] + sbs[lane];
        out[n * DOUT + lane] = acc + sb4[lane] + 2.5f * flag * gate * sig;
    }
}

// ----------------------------------------------------------------------------
// Launch
// ----------------------------------------------------------------------------
extern "C" void kernel_launch(void* const* d_in, const int* in_sizes, int n_in,
                              void* d_out, int out_size) {
    const float* x   = (const float*)d_in[0];
    const int*   ei  = (const int*)d_in[1];
    const float* ew  = (const float*)d_in[2];
    const float* W1  = (const float*)d_in[3];
    const float* b1  = (const float*)d_in[4];
    const float* g1  = (const float*)d_in[5];
    const float* be1 = (const float*)d_in[6];
    const float* Wg  = (const float*)d_in[7];
    const float* atts= (const float*)d_in[8];
    const float* attd= (const float*)d_in[9];
    const float* bg  = (const float*)d_in[10];
    const float* g2  = (const float*)d_in[11];
    const float* be2 = (const float*)d_in[12];
    const float* W3  = (const float*)d_in[13];
    const float* b3  = (const float*)d_in[14];
    const float* g3  = (const float*)d_in[15];
    const float* be3 = (const float*)d_in[16];
    const float* W4  = (const float*)d_in[17];
    const float* b4  = (const float*)d_in[18];
    const float* Wi  = (const float*)d_in[19];
    const float* bi  = (const float*)d_in[20];
    const float* Gw1 = (const float*)d_in[21];
    const float* Gb1 = (const float*)d_in[22];
    const float* Gw2 = (const float*)d_in[23];
    const float* Gb2 = (const float*)d_in[24];
    const float* Ws  = (const float*)d_in[25];
    const float* bs  = (const float*)d_in[26];
    float* out = (float*)d_out;
    const int* src = ei;
    const int* dst = ei + EE;

    float *p_h1, *p_agg, *p_x1, *p_xin, *p_hg, *p_xa, *p_h4, *p_t;
    float *p_wtg, *p_wt3, *p_wtcomb;
    cudaGetSymbolAddress((void**)&p_h1, g_h1);
    cudaGetSymbolAddress((void**)&p_agg, g_agg);
    cudaGetSymbolAddress((void**)&p_x1, g_x1);
    cudaGetSymbolAddress((void**)&p_xin, g_xin);
    cudaGetSymbolAddress((void**)&p_hg, g_hg);
    cudaGetSymbolAddress((void**)&p_xa, g_xa);
    cudaGetSymbolAddress((void**)&p_h4, g_h4);
    cudaGetSymbolAddress((void**)&p_t, g_t);
    cudaGetSymbolAddress((void**)&p_wtg, g_wtg);
    cudaGetSymbolAddress((void**)&p_wt3, g_wt3);
    cudaGetSymbolAddress((void**)&p_wtcomb, g_wtcomb);

    const int SMEM128 = 1024 + 128 * 132 * 4;   // 68608
    const int SMEM80  = 1024 + 80 * 132 * 4;    // 43264
    cudaFuncSetAttribute(mma_gemm<128, false, true, true, false>,
                         cudaFuncAttributeMaxDynamicSharedMemorySize, SMEM128);
    cudaFuncSetAttribute(mma_gemm<128, true, false, false, false>,
                         cudaFuncAttributeMaxDynamicSharedMemorySize, SMEM128);
    cudaFuncSetAttribute(mma_gemm<80, true, false, false, true>,
                         cudaFuncAttributeMaxDynamicSharedMemorySize, SMEM80);
    const int MGRID = (NN + 127) / 128;   // 782

    // graph preprocessing + weight prep
    init_kernel<<<(NN + 255) / 256, 256>>>();
    count_kernel<<<(EE + 255) / 256, 256>>>(dst, ew);
    part_kernel<<<NB, 256>>>();
    scanpart_kernel<<<1, 512>>>();
    writerow_kernel<<<NB, 256>>>();
    fill_kernel<<<(EE + 255) / 256, 256>>>(src, dst, ew);
    prep_weights_kernel<<<168, 256>>>(Wg, W3, Gw1, W4);

    // layer 1: aggregate x in 24-dim, fused GEMM -> agg1 (raw) + BN1 partials
    agg24_kernel<<<NN / 4, 128>>>(x, p_xa);
    gemm_in_kernel<<<NN / 16, 128>>>(p_xa, x, W1, b1, Wi, bi, p_agg, p_xin);
    bn_final2<<<1, 128>>>(g1, be1);

    // GAT: Wg GEMM with fused BN1+ReLU on A, side-write x1, fused att reduce
    mma_gemm<128, false, true, true, false><<<MGRID, 256, SMEM128>>>(
        p_agg, nullptr, p_x1, p_wtg, nullptr, p_hg, nullptr, atts, attd);
    gat_agg_kernel<<<NN / 8, 256>>>(p_hg, bg, p_agg);
    bn_final2<<<1, 128>>>(g2, be2);

    // layer 3: W3 GEMM with fused BN2+ReLU + xin residual on A
    mma_gemm<128, true, false, false, false><<<MGRID, 256, SMEM128>>>(
        p_agg, p_xin, nullptr, p_wt3, nullptr, p_h1, nullptr, nullptr, nullptr);
    gcn_agg128<<<NN / 4, 128>>>(p_h1, b3, p_agg);
    bn_final2<<<1, 128>>>(g3, be3);

    // output: combined (Gw1 gate + W4) GEMM with fused BN3+ReLU + x1 residual
    mma_gemm<80, true, false, false, true><<<MGRID, 256, SMEM80>>>(
        p_agg, p_x1, nullptr, p_wtcomb, Gb1, p_t, p_h4, nullptr, nullptr);
    out_kernel<<<NN / 4, 128>>>(p_h4, b4, p_t, x, Gw2, Gb2, Ws, bs, out);
}

// round 11
// speedup vs baseline: 2.4458x; 1.0516x over previous
#include <cuda_runtime.h>
#include <math.h>
#include <stdint.h>

#define NN 100000
#define EE 1600000
#define DIN 24
#define HH 128
#define DOUT 12
#define HEADS 4
#define NB 391   // ceil(NN/256)

// ----------------------------------------------------------------------------
// Scratch (device globals; no dynamic allocation allowed)
// ----------------------------------------------------------------------------
__device__ float g_h1[NN * HH];      // h3 = x2@W3
__device__ float g_agg[NN * HH];     // raw pre-BN activations per layer
__device__ float g_x1[NN * HH];      // x1 (side-written by Wg GEMM)
__device__ float g_xin[NN * HH];     // x_in_proj
__device__ float g_hg[NN * HH];      // hg
__device__ float g_xa[NN * DIN];     // 24-dim aggregated x
__device__ float g_h4[NN * DOUT];
__device__ float g_gc[NN * DOUT];    // gate contribution per node
__device__ float g_as[NN * HEADS];
__device__ float g_ad[NN * HEADS];
__device__ float g_deg[NN];
__device__ float g_dinv[NN];
__device__ int   g_cnt[NN];
__device__ int   g_cur[NN];
__device__ int   g_rowptr[NN + 1];
__device__ int2  g_epack[EE];
__device__ int   g_part[512];
__device__ float g_bnpart[3][64][256];  // per-layer bucketed BN partials
__device__ float g_wtg[HH * HH];     // Wg^T  [128,128] K-major
__device__ float g_wt3[HH * HH];     // W3^T
__device__ float g_wtcomb[80 * HH];  // [Gw1^T ; W4^T ; pad]

__device__ __forceinline__ float lrelu(float v) { return v > 0.f ? v : 0.2f * v; }
__device__ __forceinline__ uint32_t to_tf32(float f) {
    uint32_t t;
    asm("cvt.rna.tf32.f32 %0, %1;" : "=r"(t) : "f"(f));
    return t;
}

// ----------------------------------------------------------------------------
// Graph preprocessing
// ----------------------------------------------------------------------------
__global__ void __launch_bounds__(256) init_kernel() {
    int i = blockIdx.x * blockDim.x + threadIdx.x;
    if (i < NN) { g_deg[i] = 1.0f; g_cnt[i] = 0; g_cur[i] = 0; }
    if (i < 3 * 64 * 256) ((float*)g_bnpart)[i] = 0.f;
}

__global__ void __launch_bounds__(256) count_kernel(const int* __restrict__ dst,
                                                    const float* __restrict__ w) {
    int e = blockIdx.x * blockDim.x + threadIdx.x;
    if (e < EE) {
        int d = dst[e];
        atomicAdd(&g_deg[d], w[e]);
        atomicAdd(&g_cnt[d], 1);
    }
}

__global__ void __launch_bounds__(256) part_kernel() {
    __shared__ int sw[8];
    int i = blockIdx.x * 256 + threadIdx.x;
    if (i < NN) g_dinv[i] = rsqrtf(g_deg[i]);
    int v = (i < NN) ? g_cnt[i] : 0;
#pragma unroll
    for (int off = 16; off; off >>= 1) v += __shfl_down_sync(0xffffffffu, v, off);
    if ((threadIdx.x & 31) == 0) sw[threadIdx.x >> 5] = v;
    __syncthreads();
    if (threadIdx.x == 0) {
        int s = 0;
#pragma unroll
        for (int k = 0; k < 8; k++) s += sw[k];
        g_part[blockIdx.x] = s;
    }
}

// rowptr write: each block computes its own prefix over g_part
__global__ void __launch_bounds__(256) writerow_kernel() {
    __shared__ int sp[256];
    __shared__ int swr[8];
    __shared__ int soff;
    const int t = threadIdx.x;
    const int i = blockIdx.x * 256 + t;
    int pre = 0;
    for (int b = t; b < blockIdx.x; b += 256) pre += g_part[b];
#pragma unroll
    for (int off = 16; off; off >>= 1) pre += __shfl_down_sync(0xffffffffu, pre, off);
    if ((t & 31) == 0) swr[t >> 5] = pre;
    __syncthreads();
    if (t == 0) {
        int s = 0;
#pragma unroll
        for (int k = 0; k < 8; k++) s += swr[k];
        soff = s;
    }
    int v = (i < NN) ? g_cnt[i] : 0;
    sp[t] = v;
    __syncthreads();
    for (int off = 1; off < 256; off <<= 1) {
        int a = (t >= off) ? sp[t - off] : 0;
        __syncthreads();
        sp[t] += a;
        __syncthreads();
    }
    if (i < NN) g_rowptr[i] = sp[t] - v + soff;
    if (i == 0) g_rowptr[NN] = EE;
}

__global__ void __launch_bounds__(256) fill_kernel(const int* __restrict__ src,
                                                   const int* __restrict__ dst,
                                                   const float* __restrict__ w) {
    int e = blockIdx.x * blockDim.x + threadIdx.x;
    if (e < EE) {
        int d = dst[e];
        int s = src[e];
        int pos = g_rowptr[d] + atomicAdd(&g_cur[d], 1);
        float coef = w[e] * __ldg(&g_dinv[s]) * __ldg(&g_dinv[d]);
        g_epack[pos] = make_int2(s, __float_as_int(coef));
    }
}

__global__ void __launch_bounds__(256) prep_weights_kernel(const float* __restrict__ Wg,
                                                           const float* __restrict__ W3,
                                                           const float* __restrict__ Gw1,
                                                           const float* __restrict__ W4) {
    int idx = blockIdx.x * 256 + threadIdx.x;
    if (idx < 16384) {
        int k = idx >> 7, c = idx & 127;
        g_wtg[c * 128 + k] = __ldg(&Wg[idx]);
    } else if (idx < 32768) {
        int j = idx - 16384;
        int k = j >> 7, c = j & 127;
        g_wt3[c * 128 + k] = __ldg(&W3[j]);
    } else if (idx < 43008) {
        int j = idx - 32768;
        int r = j >> 7, k = j & 127;
        float v = 0.f;
        if (r < 64) v = __ldg(&Gw1[k * 64 + r]);
        else if (r < 76) v = __ldg(&W4[k * DOUT + (r - 64)]);
        g_wtcomb[j] = v;
    }
}

// ----------------------------------------------------------------------------
// 24-channel GCN aggregation of raw x (layer-1 reassociation)
// ----------------------------------------------------------------------------
__global__ void __launch_bounds__(128) agg24_kernel(const float* __restrict__ x,
                                                    float* __restrict__ xa) {
    const int warp = threadIdx.x >> 5;
    const int lane = threadIdx.x & 31;
    const int n = blockIdx.x * 4 + warp;
    const float dn = g_dinv[n];
    const int s0 = g_rowptr[n], s1 = g_rowptr[n + 1];
    float acc = (lane < DIN) ? x[n * DIN + lane] * dn * dn : 0.f;
    int j = s0;
    for (; j + 8 <= s1; j += 8) {
        int2 e[8];
        float v[8];
#pragma unroll
        for (int q = 0; q < 8; q++) e[q] = __ldg(&g_epack[j + q]);
#pragma unroll
        for (int q = 0; q < 8; q++)
            v[q] = (lane < DIN) ? __ldg(&x[e[q].x * DIN + lane]) : 0.f;
#pragma unroll
        for (int q = 0; q < 8; q++) acc += __int_as_float(e[q].y) * v[q];
    }
    for (; j < s1; j++) {
        int2 e = __ldg(&g_epack[j]);
        if (lane < DIN) acc += __int_as_float(e.y) * __ldg(&x[e.x * DIN + lane]);
    }
    if (lane < DIN) xa[n * DIN + lane] = acc;
}

// ----------------------------------------------------------------------------
// TF32 mma.sync GEMM. BN scale/shift computed IN-KERNEL from bucketed partials
// (bnp points at this layer's [64][256] buckets). Optional residual add,
// side-write of activated A, att epilogue, or COMBO epilogue with fused gate.
// ----------------------------------------------------------------------------
template<int NC, bool ADD, bool WRITEX, bool ATT, bool COMBO>
__global__ void __launch_bounds__(256) mma_gemm(const float* __restrict__ Araw,
                                                const float* __restrict__ addp,
                                                float* __restrict__ xout,
                                                const float* __restrict__ Bt,
                                                const float* __restrict__ bias,
                                                float* __restrict__ out,
                                                float* __restrict__ out2,
                                                const float* __restrict__ att_s,
                                                const float* __restrict__ att_d,
                                                const float* __restrict__ bnp,
                                                const float* __restrict__ bng,
                                                const float* __restrict__ bnbe,
                                                const float* __restrict__ Gw2,
                                                const float* __restrict__ Gb2,
                                                const float* __restrict__ Ws,
                                                const float* __restrict__ bs,
                                                const float* __restrict__ xfull) {
    extern __shared__ float smf[];
    float* sSC = smf;
    float* sSH = smf + 128;
    uint32_t* sW = (uint32_t*)(smf + 256);   // [NC][132]
    float* sG = smf + 256 + NC * 132;        // [64*12] (COMBO only)
    const int tid = threadIdx.x, wid = tid >> 5, lane = tid & 31;
    const int n0 = blockIdx.x * 128;

    // in-CTA BN finalize
    if (tid < 128) {
        float s = 0.f, s2 = 0.f;
#pragma unroll 8
        for (int b = 0; b < 64; b++) {
            s += __ldg(&bnp[b * 256 + tid]);
            s2 += __ldg(&bnp[b * 256 + tid + 128]);
        }
        float mean = s * (1.0f / NN);
        float var = fmaxf(s2 * (1.0f / NN) - mean * mean, 0.f);
        float sc = rsqrtf(var + 1e-5f) * __ldg(&bng[tid]);
        sSC[tid] = sc;
        sSH[tid] = __ldg(&bnbe[tid]) - mean * sc;
    }
    for (int i = tid; i < NC * 128; i += 256) {
        int c = i >> 7, k = i & 127;
        sW[c * 132 + k] = to_tf32(__ldg(&Bt[i]));
    }
    if (COMBO) {
        for (int i = tid; i < 64 * DOUT; i += 256) sG[i] = __ldg(&Gw2[i]);
    }
    __syncthreads();

    constexpr int NCH = NC / 8;
    float acc[NCH][4];
#pragma unroll
    for (int i = 0; i < NCH; i++) {
        acc[i][0] = 0.f; acc[i][1] = 0.f; acc[i][2] = 0.f; acc[i][3] = 0.f;
    }

    const int r0 = n0 + wid * 16 + (lane >> 2);
    const int r1 = r0 + 8;
    const bool v0 = r0 < NN, v1 = r1 < NN;
    const int kq = lane & 3;
    const int nq = lane >> 2;

#pragma unroll 4
    for (int k8 = 0; k8 < 128; k8 += 8) {
        int ka = k8 + kq, kb = k8 + kq + 4;
        float f0 = 0.f, f1 = 0.f, f2 = 0.f, f3 = 0.f;
        if (v0) {
            f0 = fmaxf(__ldg(&Araw[(size_t)r0 * 128 + ka]) * sSC[ka] + sSH[ka], 0.f);
            f2 = fmaxf(__ldg(&Araw[(size_t)r0 * 128 + kb]) * sSC[kb] + sSH[kb], 0.f);
            if (ADD) {
                f0 += __ldg(&addp[(size_t)r0 * 128 + ka]);
                f2 += __ldg(&addp[(size_t)r0 * 128 + kb]);
            }
            if (WRITEX) {
                xout[(size_t)r0 * 128 + ka] = f0;
                xout[(size_t)r0 * 128 + kb] = f2;
            }
        }
        if (v1) {
            f1 = fmaxf(__ldg(&Araw[(size_t)r1 * 128 + ka]) * sSC[ka] + sSH[ka], 0.f);
            f3 = fmaxf(__ldg(&Araw[(size_t)r1 * 128 + kb]) * sSC[kb] + sSH[kb], 0.f);
            if (ADD) {
                f1 += __ldg(&addp[(size_t)r1 * 128 + ka]);
                f3 += __ldg(&addp[(size_t)r1 * 128 + kb]);
            }
            if (WRITEX) {
                xout[(size_t)r1 * 128 + ka] = f1;
                xout[(size_t)r1 * 128 + kb] = f3;
            }
        }
        uint32_t a0 = to_tf32(f0), a1 = to_tf32(f1), a2 = to_tf32(f2), a3 = to_tf32(f3);
#pragma unroll
        for (int nc = 0; nc < NCH; nc++) {
            uint32_t b0 = sW[(nc * 8 + nq) * 132 + ka];
            uint32_t b1 = sW[(nc * 8 + nq) * 132 + kb];
            asm volatile(
                "mma.sync.aligned.m16n8k8.row.col.f32.tf32.tf32.f32 "
                "{%0,%1,%2,%3}, {%4,%5,%6,%7}, {%8,%9}, {%0,%1,%2,%3};"
                : "+f"(acc[nc][0]), "+f"(acc[nc][1]), "+f"(acc[nc][2]), "+f"(acc[nc][3])
                : "r"(a0), "r"(a1), "r"(a2), "r"(a3), "r"(b0), "r"(b1));
        }
    }

    const int colb = 2 * kq;
    if (COMBO) {
        // cols 0..63: t = relu(acc + Gb1) -> fused gate GEMM (no store of t)
        // cols 64..75: h4 -> out2
        float z0[DOUT], z1[DOUT];
#pragma unroll
        for (int c = 0; c < DOUT; c++) { z0[c] = 0.f; z1[c] = 0.f; }
#pragma unroll
        for (int nc = 0; nc < NCH; nc++) {
            int col = nc * 8 + colb;
            if (col < 64) {
                float bx = __ldg(&bias[col]), by = __ldg(&bias[col + 1]);
                float t0a = fmaxf(acc[nc][0] + bx, 0.f), t0b = fmaxf(acc[nc][1] + by, 0.f);
                float t1a = fmaxf(acc[nc][2] + bx, 0.f), t1b = fmaxf(acc[nc][3] + by, 0.f);
#pragma unroll
                for (int c = 0; c < DOUT; c++) {
                    float w0 = sG[col * DOUT + c], w1 = sG[(col + 1) * DOUT + c];
                    z0[c] += t0a * w0 + t0b * w1;
                    z1[c] += t1a * w0 + t1b * w1;
                }
            } else if (col < 76) {
                int c2 = col - 64;
                if (v0) *(float2*)&out2[(size_t)r0 * DOUT + c2] =
                            make_float2(acc[nc][0], acc[nc][1]);
                if (v1) *(float2*)&out2[(size_t)r1 * DOUT + c2] =
                            make_float2(acc[nc][2], acc[nc][3]);
            }
        }
        // reduce z over the quad (lanes kq=0..3 own the same rows)
#pragma unroll
        for (int c = 0; c < DOUT; c++) {
            z0[c] += __shfl_xor_sync(0xffffffffu, z0[c], 1);
            z0[c] += __shfl_xor_sync(0xffffffffu, z0[c], 2);
            z1[c] += __shfl_xor_sync(0xffffffffu, z1[c], 1);
            z1[c] += __shfl_xor_sync(0xffffffffu, z1[c], 2);
        }
        if (kq == 0) {
            if (v0) {
                float status = __ldg(&xfull[(size_t)r0 * DIN + 12]);
                float flag = status < 0.5f ? 2.5f : 0.f;
#pragma unroll
                for (int c = 0; c < DOUT; c++) {
                    float gate = 1.f / (1.f + expf(-(z0[c] + __ldg(&Gb2[c]))));
                    float sig = (1.f - status) * __ldg(&Ws[c]) + __ldg(&bs[c]);
                    out[(size_t)r0 * DOUT + c] = flag * gate * sig;
                }
            }
            if (v1) {
                float status = __ldg(&xfull[(size_t)r1 * DIN + 12]);
                float flag = status < 0.5f ? 2.5f : 0.f;
#pragma unroll
                for (int c = 0; c < DOUT; c++) {
                    float gate = 1.f / (1.f + expf(-(z1[c] + __ldg(&Gb2[c]))));
                    float sig = (1.f - status) * __ldg(&Ws[c]) + __ldg(&bs[c]);
                    out[(size_t)r1 * DOUT + c] = flag * gate * sig;
                }
            }
        }
    } else {
#pragma unroll
        for (int nc = 0; nc < NCH; nc++) {
            int col = nc * 8 + colb;
            if (v0) *(float2*)&out[(size_t)r0 * NC + col] =
                        make_float2(acc[nc][0], acc[nc][1]);
            if (v1) *(float2*)&out[(size_t)r1 * NC + col] =
                        make_float2(acc[nc][2], acc[nc][3]);
        }
    }

    if (ATT) {
        float as0[4] = {}, ad0[4] = {}, as1[4] = {}, ad1[4] = {};
#pragma unroll
        for (int nc = 0; nc < NCH; nc++) {
            int col = nc * 8 + colb;
            float sx = __ldg(&att_s[col]), sy = __ldg(&att_s[col + 1]);
            float dx = __ldg(&att_d[col]), dy = __ldg(&att_d[col + 1]);
            int h = nc >> 2;
            as0[h] += acc[nc][0] * sx + acc[nc][1] * sy;
            ad0[h] += acc[nc][0] * dx + acc[nc][1] * dy;
            as1[h] += acc[nc][2] * sx + acc[nc][3] * sy;
            ad1[h] += acc[nc][2] * dx + acc[nc][3] * dy;
        }
#pragma unroll
        for (int h = 0; h < 4; h++) {
#pragma unroll
            for (int off = 1; off <= 2; off <<= 1) {
                as0[h] += __shfl_xor_sync(0xffffffffu, as0[h], off);
                ad0[h] += __shfl_xor_sync(0xffffffffu, ad0[h], off);
                as1[h] += __shfl_xor_sync(0xffffffffu, as1[h], off);
                ad1[h] += __shfl_xor_sync(0xffffffffu, ad1[h], off);
            }
        }
        if (kq == 0) {
#pragma unroll
            for (int h = 0; h < 4; h++) {
                if (v0) { g_as[r0 * 4 + h] = as0[h]; g_ad[r0 * 4 + h] = ad0[h]; }
                if (v1) { g_as[r1 * 4 + h] = as1[h]; g_ad[r1 * 4 + h] = ad1[h]; }
            }
        }
    }
}

// ----------------------------------------------------------------------------
// Fused input GEMM: agg1 = xa@W1 + b1, xin = x@Wi + bi, + fused BN1 partials
// ----------------------------------------------------------------------------
__global__ void __launch_bounds__(128) gemm_in_kernel(
        const float* __restrict__ XA, const float* __restrict__ X,
        const float* __restrict__ W1, const float* __restrict__ b1,
        const float* __restrict__ Wi, const float* __restrict__ bi,
        float* __restrict__ h1, float* __restrict__ xin) {
    __shared__ float sS[4][128], sQ[4][128];
    const int tid = threadIdx.x;
    const int cg = tid & 31;
    const int rg = tid >> 5;
    const int n0 = blockIdx.x * 16 + rg * 4;
    float a1[4][4] = {}; float ai[4][4] = {};
    const float4* W1v = (const float4*)W1;
    const float4* Wiv = (const float4*)Wi;
#pragma unroll
    for (int k = 0; k < DIN; k++) {
        float4 w1 = __ldg(&W1v[k * 32 + cg]);
        float4 wi = __ldg(&Wiv[k * 32 + cg]);
#pragma unroll
        for (int r = 0; r < 4; r++) {
            float xav = __ldg(&XA[(n0 + r) * DIN + k]);
            float xv  = __ldg(&X[(n0 + r) * DIN + k]);
            a1[r][0] += xav * w1.x; a1[r][1] += xav * w1.y; a1[r][2] += xav * w1.z; a1[r][3] += xav * w1.w;
            ai[r][0] += xv * wi.x;  ai[r][1] += xv * wi.y;  ai[r][2] += xv * wi.z;  ai[r][3] += xv * wi.w;
        }
    }
    const int c0 = cg * 4;
    float4 b1v = __ldg(&((const float4*)b1)[cg]);
    float4 biv = __ldg(&((const float4*)bi)[cg]);
    float s4[4] = {}, q4[4] = {};
#pragma unroll
    for (int r = 0; r < 4; r++) {
        float4 v1, vi;
        v1.x = a1[r][0] + b1v.x; v1.y = a1[r][1] + b1v.y;
        v1.z = a1[r][2] + b1v.z; v1.w = a1[r][3] + b1v.w;
        vi.x = ai[r][0] + biv.x; vi.y = ai[r][1] + biv.y;
        vi.z = ai[r][2] + biv.z; vi.w = ai[r][3] + biv.w;
        s4[0] += v1.x; q4[0] += v1.x * v1.x;
        s4[1] += v1.y; q4[1] += v1.y * v1.y;
        s4[2] += v1.z; q4[2] += v1.z * v1.z;
        s4[3] += v1.w; q4[3] += v1.w * v1.w;
        *(float4*)&h1[(n0 + r) * HH + c0] = v1;
        *(float4*)&xin[(n0 + r) * HH + c0] = vi;
    }
#pragma unroll
    for (int i = 0; i < 4; i++) { sS[rg][c0 + i] = s4[i]; sQ[rg][c0 + i] = q4[i]; }
    __syncthreads();
    const int b = blockIdx.x & 63;
    float ts = sS[0][tid] + sS[1][tid] + sS[2][tid] + sS[3][tid];
    float tq = sQ[0][tid] + sQ[1][tid] + sQ[2][tid] + sQ[3][tid];
    atomicAdd(&g_bnpart[0][b][tid], ts);
    atomicAdd(&g_bnpart[0][b][tid + 128], tq);
}

// ----------------------------------------------------------------------------
// GCN aggregation (128 channels, warp per node, 8-wide) + fused BN3 partials
// ----------------------------------------------------------------------------
__global__ void __launch_bounds__(128) gcn_agg128(const float* __restrict__ in,
                                                  const float* __restrict__ bias,
                                                  float* __restrict__ out) {
    __shared__ float sS[4][128], sQ[4][128];
    const int warp = threadIdx.x >> 5;
    const int lane = threadIdx.x & 31;
    const int n = blockIdx.x * 4 + warp;
    const float dn = g_dinv[n];
    const int s0 = g_rowptr[n], s1 = g_rowptr[n + 1];
    const float4* in4 = (const float4*)in;
    float4 acc = __ldg(&in4[n * 32 + lane]);
    float dn2 = dn * dn;
    acc.x *= dn2; acc.y *= dn2; acc.z *= dn2; acc.w *= dn2;
    int j = s0;
    for (; j + 8 <= s1; j += 8) {
        int2 e[8];
        float4 v[8];
#pragma unroll
        for (int q = 0; q < 8; q++) e[q] = __ldg(&g_epack[j + q]);
#pragma unroll
        for (int q = 0; q < 8; q++) v[q] = __ldg(&in4[e[q].x * 32 + lane]);
#pragma unroll
        for (int q = 0; q < 8; q++) {
            float c = __int_as_float(e[q].y);
            acc.x += c * v[q].x; acc.y += c * v[q].y;
            acc.z += c * v[q].z; acc.w += c * v[q].w;
        }
    }
    for (; j < s1; j++) {
        int2 e = __ldg(&g_epack[j]);
        float4 v = __ldg(&in4[e.x * 32 + lane]);
        float c = __int_as_float(e.y);
        acc.x += c * v.x; acc.y += c * v.y; acc.z += c * v.z; acc.w += c * v.w;
    }
    float4 bv = __ldg(&((const float4*)bias)[lane]);
    acc.x += bv.x; acc.y += bv.y; acc.z += bv.z; acc.w += bv.w;
    ((float4*)out)[n * 32 + lane] = acc;
    sS[warp][lane * 4 + 0] = acc.x; sQ[warp][lane * 4 + 0] = acc.x * acc.x;
    sS[warp][lane * 4 + 1] = acc.y; sQ[warp][lane * 4 + 1] = acc.y * acc.y;
    sS[warp][lane * 4 + 2] = acc.z; sQ[warp][lane * 4 + 2] = acc.z * acc.z;
    sS[warp][lane * 4 + 3] = acc.w; sQ[warp][lane * 4 + 3] = acc.w * acc.w;
    __syncthreads();
    const int tid = threadIdx.x;
    const int b = blockIdx.x & 63;
    float ts = sS[0][tid] + sS[1][tid] + sS[2][tid] + sS[3][tid];
    float tq = sQ[0][tid] + sQ[1][tid] + sQ[2][tid] + sQ[3][tid];
    atomicAdd(&g_bnpart[2][b][tid], ts);
    atomicAdd(&g_bnpart[2][b][tid + 128], tq);
}

// ----------------------------------------------------------------------------
// GAT aggregation: single pass, warp per node + fused BN2 partials
// ----------------------------------------------------------------------------
__global__ void __launch_bounds__(256) gat_agg_kernel(const float* __restrict__ hg,
                                                      const float* __restrict__ bg,
                                                      float* __restrict__ out) {
    __shared__ float sS[8][128], sQ[8][128];
    const int w = threadIdx.x >> 5;
    const int lane = threadIdx.x & 31;
    const int n = blockIdx.x * 8 + w;
    const int s0 = g_rowptr[n], s1 = g_rowptr[n + 1];
    const int h = lane >> 3;
    const int eq = lane & 7;
    const float4* ad4 = (const float4*)g_ad;
    const float4* as4 = (const float4*)g_as;

    float4 adv = __ldg(&ad4[n]);
    float4 asv = __ldg(&as4[n]);
    float adh = h < 2 ? (h == 0 ? adv.x : adv.y) : (h == 2 ? adv.z : adv.w);
    float ash = h < 2 ? (h == 0 ? asv.x : asv.y) : (h == 2 ? asv.z : asv.w);
    float xs = expf(lrelu(ash + adh));

    const float4* hg4 = (const float4*)hg;
    float4 acc = make_float4(0.f, 0.f, 0.f, 0.f);
    float tsum = 0.f;

    int j = s0;
    for (; j + 8 <= s1; j += 8) {
        int2 e[8];
#pragma unroll
        for (int q = 0; q < 8; q++) e[q] = __ldg(&g_epack[j + q]);
        float myx = expf(lrelu(__ldg(&g_as[e[eq].x * 4 + h]) + adh));
        tsum += myx;
        float4 v[8];
#pragma unroll
        for (int q = 0; q < 8; q++) v[q] = __ldg(&hg4[e[q].x * 32 + lane]);
#pragma unroll
        for (int q = 0; q < 8; q++) {
            float a = __shfl_sync(0xffffffffu, myx, h * 8 + q);
            acc.x += a * v[q].x; acc.y += a * v[q].y;
            acc.z += a * v[q].z; acc.w += a * v[q].w;
        }
    }
    for (; j < s1; j++) {
        int2 e = __ldg(&g_epack[j]);
        float a = expf(lrelu(__ldg(&g_as[e.x * 4 + h]) + adh));
        if (eq == 0) tsum += a;
        float4 v = __ldg(&hg4[e.x * 32 + lane]);
        acc.x += a * v.x; acc.y += a * v.y; acc.z += a * v.z; acc.w += a * v.w;
    }
#pragma unroll
    for (int off = 1; off <= 4; off <<= 1)
        tsum += __shfl_xor_sync(0xffffffffu, tsum, off);
    float inv = 1.f / (tsum + xs);

    float4 self = __ldg(&hg4[n * 32 + lane]);
    float4 bv = __ldg(&((const float4*)bg)[lane]);
    float4 o;
    o.x = (acc.x + xs * self.x) * inv + bv.x;
    o.y = (acc.y + xs * self.y) * inv + bv.y;
    o.z = (acc.z + xs * self.z) * inv + bv.z;
    o.w = (acc.w + xs * self.w) * inv + bv.w;
    ((float4*)out)[n * 32 + lane] = o;
    sS[w][lane * 4 + 0] = o.x; sQ[w][lane * 4 + 0] = o.x * o.x;
    sS[w][lane * 4 + 1] = o.y; sQ[w][lane * 4 + 1] = o.y * o.y;
    sS[w][lane * 4 + 2] = o.z; sQ[w][lane * 4 + 2] = o.z * o.z;
    sS[w][lane * 4 + 3] = o.w; sQ[w][lane * 4 + 3] = o.w * o.w;
    __syncthreads();
    const int tid = threadIdx.x;
    if (tid < 128) {
        const int b = blockIdx.x & 63;
        float ts = 0.f, tq = 0.f;
#pragma unroll
        for (int ww = 0; ww < 8; ww++) { ts += sS[ww][tid]; tq += sQ[ww][tid]; }
        atomicAdd(&g_bnpart[1][b][tid], ts);
        atomicAdd(&g_bnpart[1][b][tid + 128], tq);
    }
}

// ----------------------------------------------------------------------------
// Output: GCN aggregation of h4 (12 channels, 8-wide) + gate contribution add.
// ----------------------------------------------------------------------------
__global__ void __launch_bounds__(128) out_kernel(
        const float* __restrict__ h4, const float* __restrict__ b4,
        const float* __restrict__ gc, float* __restrict__ out) {
    const int warp = threadIdx.x >> 5;
    const int lane = threadIdx.x & 31;
    const int n = blockIdx.x * 4 + warp;
    const float dn = g_dinv[n];
    const int s0 = g_rowptr[n], s1 = g_rowptr[n + 1];
    float acc = (lane < DOUT) ? h4[n * DOUT + lane] * dn * dn : 0.f;
    int j = s0;
    for (; j + 8 <= s1; j += 8) {
        int2 e[8];
        float v[8];
#pragma unroll
        for (int q = 0; q < 8; q++) e[q] = __ldg(&g_epack[j + q]);
#pragma unroll
        for (int q = 0; q < 8; q++)
            v[q] = (lane < DOUT) ? __ldg(&h4[e[q].x * DOUT + lane]) : 0.f;
#pragma unroll
        for (int q = 0; q < 8; q++) acc += __int_as_float(e[q].y) * v[q];
    }
    for (; j < s1; j++) {
        int2 e = __ldg(&g_epack[j]);
        if (lane < DOUT) acc += __int_as_float(e.y) * __ldg(&h4[e.x * DOUT + lane]);
    }
    if (lane < DOUT)
        out[n * DOUT + lane] = acc + __ldg(&b4[lane]) + __ldg(&gc[n * DOUT + lane]);
}

// ----------------------------------------------------------------------------
// Launch
// ----------------------------------------------------------------------------
extern "C" void kernel_launch(void* const* d_in, const int* in_sizes, int n_in,
                              void* d_out, int out_size) {
    const float* x   = (const float*)d_in[0];
    const int*   ei  = (const int*)d_in[1];
    const float* ew  = (const float*)d_in[2];
    const float* W1  = (const float*)d_in[3];
    const float* b1  = (const float*)d_in[4];
    const float* g1  = (const float*)d_in[5];
    const float* be1 = (const float*)d_in[6];
    const float* Wg  = (const float*)d_in[7];
    const float* atts= (const float*)d_in[8];
    const float* attd= (const float*)d_in[9];
    const float* bg  = (const float*)d_in[10];
    const float* g2  = (const float*)d_in[11];
    const float* be2 = (const float*)d_in[12];
    const float* W3  = (const float*)d_in[13];
    const float* b3  = (const float*)d_in[14];
    const float* g3  = (const float*)d_in[15];
    const float* be3 = (const float*)d_in[16];
    const float* W4  = (const float*)d_in[17];
    const float* b4  = (const float*)d_in[18];
    const float* Wi  = (const float*)d_in[19];
    const float* bi  = (const float*)d_in[20];
    const float* Gw1 = (const float*)d_in[21];
    const float* Gb1 = (const float*)d_in[22];
    const float* Gw2 = (const float*)d_in[23];
    const float* Gb2 = (const float*)d_in[24];
    const float* Ws  = (const float*)d_in[25];
    const float* bs  = (const float*)d_in[26];
    float* out = (float*)d_out;
    const int* src = ei;
    const int* dst = ei + EE;

    float *p_h1, *p_agg, *p_x1, *p_xin, *p_hg, *p_xa, *p_h4, *p_gc;
    float *p_wtg, *p_wt3, *p_wtcomb, *p_bn;
    cudaGetSymbolAddress((void**)&p_h1, g_h1);
    cudaGetSymbolAddress((void**)&p_agg, g_agg);
    cudaGetSymbolAddress((void**)&p_x1, g_x1);
    cudaGetSymbolAddress((void**)&p_xin, g_xin);
    cudaGetSymbolAddress((void**)&p_hg, g_hg);
    cudaGetSymbolAddress((void**)&p_xa, g_xa);
    cudaGetSymbolAddress((void**)&p_h4, g_h4);
    cudaGetSymbolAddress((void**)&p_gc, g_gc);
    cudaGetSymbolAddress((void**)&p_wtg, g_wtg);
    cudaGetSymbolAddress((void**)&p_wt3, g_wt3);
    cudaGetSymbolAddress((void**)&p_wtcomb, g_wtcomb);
    cudaGetSymbolAddress((void**)&p_bn, g_bnpart);

    const int SMEM128 = 1024 + 128 * 132 * 4;                 // 68608
    const int SMEM80  = 1024 + 80 * 132 * 4 + 64 * DOUT * 4;  // 46336
    cudaFuncSetAttribute(mma_gemm<128, false, true, true, false>,
                         cudaFuncAttributeMaxDynamicSharedMemorySize, SMEM128);
    cudaFuncSetAttribute(mma_gemm<128, true, false, false, false>,
                         cudaFuncAttributeMaxDynamicSharedMemorySize, SMEM128);
    cudaFuncSetAttribute(mma_gemm<80, true, false, false, true>,
                         cudaFuncAttributeMaxDynamicSharedMemorySize, SMEM80);
    const int MGRID = (NN + 127) / 128;   // 782

    // graph preprocessing + weight prep
    init_kernel<<<(NN + 255) / 256, 256>>>();
    count_kernel<<<(EE + 255) / 256, 256>>>(dst, ew);
    part_kernel<<<NB, 256>>>();
    writerow_kernel<<<NB, 256>>>();
    fill_kernel<<<(EE + 255) / 256, 256>>>(src, dst, ew);
    prep_weights_kernel<<<168, 256>>>(Wg, W3, Gw1, W4);

    // layer 1
    agg24_kernel<<<NN / 4, 128>>>(x, p_xa);
    gemm_in_kernel<<<NN / 16, 128>>>(p_xa, x, W1, b1, Wi, bi, p_agg, p_xin);

    // GAT: Wg GEMM (in-kernel BN1 finalize) + side-write x1 + att reduce
    mma_gemm<128, false, true, true, false><<<MGRID, 256, SMEM128>>>(
        p_agg, nullptr, p_x1, p_wtg, nullptr, p_hg, nullptr, atts, attd,
        p_bn + 0 * 64 * 256, g1, be1, nullptr, nullptr, nullptr, nullptr, nullptr);
    gat_agg_kernel<<<NN / 8, 256>>>(p_hg, bg, p_agg);

    // layer 3: W3 GEMM (in-kernel BN2 finalize) + xin residual
    mma_gemm<128, true, false, false, false><<<MGRID, 256, SMEM128>>>(
        p_agg, p_xin, nullptr, p_wt3, nullptr, p_h1, nullptr, nullptr, nullptr,
        p_bn + 1 * 64 * 256, g2, be2, nullptr, nullptr, nullptr, nullptr, nullptr);
    gcn_agg128<<<NN / 4, 128>>>(p_h1, b3, p_agg);

    // output: combo GEMM (in-kernel BN3 finalize) + x1 residual + fused gate
    mma_gemm<80, true, false, false, true><<<MGRID, 256, SMEM80>>>(
        p_agg, p_x1, nullptr, p_wtcomb, Gb1, p_gc, p_h4, nullptr, nullptr,
        p_bn + 2 * 64 * 256, g3, be3, Gw2, Gb2, Ws, bs, x);
    out_kernel<<<NN / 4, 128>>>(p_h4, b4, p_gc, out);
}